// round 3
// baseline (speedup 1.0000x reference)
#include <cuda_runtime.h>
#include <math.h>

// Problem constants
#define Bsz 640
#define Dd 512
#define Ss 4
#define Tt 10
#define TBsz 64
#define Ll 30
#define KBsz 196
#define MKB (Bsz*KBsz)   // 125440
#define TS 40            // T*S

// ---------------- scratch (static device globals; no allocations) ----------
__device__ float g_q0[Bsz*Dd];
__device__ float g_qall[Ss*Bsz*Dd];          // (s, b, d)
__device__ float g_ch[Bsz*Ss*Dd];            // (b, s, d)
__device__ float g_chkey[Bsz*Ss*Dd];
__device__ float g_chval[Bsz*Ss*Dd];
__device__ float g_normed[Bsz*Ss*Dd];
__device__ float g_Amat[TBsz*TS*TS];
__device__ float g_att[Bsz*Ss*Dd];           // (b, s, d)
__device__ float g_kp [(size_t)MKB*Dd];      // know_proj
__device__ float g_kp2[(size_t)MKB*Dd];      // know_proj @ concat_w[D:] + concat_b
__device__ float g_e1 [(size_t)MKB*Dd];      // elu(inter @ W_top + kp2)
__device__ float g_mp[Bsz*Dd];
__device__ float g_s[MKB];
__device__ float g_read[Bsz*Dd];
__device__ float g_mem0[Bsz*Dd];
__device__ float g_mem1[Bsz*Dd];

__device__ __forceinline__ float eluf(float x){ return x > 0.f ? x : expm1f(x); }

__device__ __forceinline__ unsigned tf32r(float x){
    unsigned r; asm("cvt.rna.tf32.f32 %0, %1;" : "=r"(r) : "f"(x)); return r;
}

__device__ __forceinline__ void mma8(float* cc, const unsigned* a, const unsigned* b){
    asm("mma.sync.aligned.m16n8k8.row.col.f32.tf32.tf32.f32 "
        "{%0,%1,%2,%3}, {%4,%5,%6,%7}, {%8,%9}, {%0,%1,%2,%3};"
        : "+f"(cc[0]), "+f"(cc[1]), "+f"(cc[2]), "+f"(cc[3])
        : "r"(a[0]), "r"(a[1]), "r"(a[2]), "r"(a[3]), "r"(b[0]), "r"(b[1]));
}

// ---------------- generic tiled GEMM, split-tf32 tensor-core mainloop --------
// C[M,N] = epilogue( A'[M,K] @ W[K,N] )    W row-major with stride N.
// A'[m,k] = (k < splitK ? A[m*lda+k] : A2[m*lda2+k-splitK]),
//           optionally * rowscale[(m/KB)*512 + k]   (MODE 2)
// MODE 0: C = acc + bias
// MODE 1: C = tanh(acc + bias)
// MODE 2: C = elu(acc + addmat[m*N+n])              (bias folded into addmat)
// MODE 3: no C; svec[m] += sum_n elu((acc+bias[n])*colmul[(m/KB)*cmStride+n])*rvec[n]
// Requires: M % 128 == 0, N % 128 == 0, K % 16 == 0.
#define BM 128
#define BN 128
#define BKK 16
#define ASTR 136   // padded stride: (136 mod 32) == 8 -> conflict-free frag loads

template<int MODE>
__global__ __launch_bounds__(256)
void sgemm_k(const float* __restrict__ A, int lda,
             const float* __restrict__ A2, int lda2, int splitK,
             const float* __restrict__ W,
             const float* __restrict__ bias,
             float* __restrict__ C,
             int M, int K, int N,
             const float* __restrict__ rowscale,
             const float* __restrict__ addmat,
             const float* __restrict__ colmul, int cmStride,
             const float* __restrict__ rvec,
             float* __restrict__ svec)
{
    __shared__ float Ah[BKK][ASTR], Al[BKK][ASTR];
    __shared__ float Bh[BKK][ASTR], Bl[BKK][ASTR];

    const int bm = blockIdx.y * BM;
    const int bn = blockIdx.x * BN;
    const int tid = threadIdx.x;
    const int wid = tid >> 5, lane = tid & 31;
    const int warp_m = wid & 1;          // 2 warps over M (64 rows each)
    const int warp_n = wid >> 1;         // 4 warps over N (32 cols each)
    const int r = lane >> 2, c = lane & 3;

    float acc[4][4][4];                  // [mtile][ntile][reg]
    #pragma unroll
    for (int i = 0; i < 4; i++)
        #pragma unroll
        for (int j = 0; j < 4; j++)
            #pragma unroll
            for (int q = 0; q < 4; q++) acc[i][j][q] = 0.f;

    for (int k0 = 0; k0 < K; k0 += BKK) {
        // ---- fill A tile (128 x 16) split into tf32 hi/lo, transposed layout
        #pragma unroll
        for (int e2 = 0; e2 < 2; e2++) {
            int e   = tid * 2 + e2;          // 0..511
            int row = e >> 2;                // 0..127
            int kq  = (e & 3) * 4;           // 0,4,8,12
            int m   = bm + row;
            int k   = k0 + kq;
            const float* src = (k < splitK)
                ? (A  + (size_t)m * lda  + k)
                : (A2 + (size_t)m * lda2 + (k - splitK));
            float4 v = *(const float4*)src;
            if (MODE == 2) {
                int b = m / KBsz;
                float4 rs = *(const float4*)(rowscale + (size_t)b * Dd + k);
                v.x *= rs.x; v.y *= rs.y; v.z *= rs.z; v.w *= rs.w;
            }
            float xs[4] = {v.x, v.y, v.z, v.w};
            #pragma unroll
            for (int j = 0; j < 4; j++) {
                float hi = __uint_as_float(tf32r(xs[j]));
                float lo = __uint_as_float(tf32r(xs[j] - hi));
                Ah[kq + j][row] = hi;
                Al[kq + j][row] = lo;
            }
        }
        // ---- fill B tile (16 x 128) split into tf32 hi/lo
        #pragma unroll
        for (int e2 = 0; e2 < 2; e2++) {
            int e   = tid * 2 + e2;
            int row = e >> 5;                // 0..15
            int c4  = (e & 31) * 4;          // 0..124
            float4 v = *(const float4*)(W + (size_t)(k0 + row) * N + bn + c4);
            float xs[4] = {v.x, v.y, v.z, v.w};
            #pragma unroll
            for (int j = 0; j < 4; j++) {
                float hi = __uint_as_float(tf32r(xs[j]));
                float lo = __uint_as_float(tf32r(xs[j] - hi));
                Bh[row][c4 + j] = hi;
                Bl[row][c4 + j] = lo;
            }
        }
        __syncthreads();

        #pragma unroll
        for (int kk = 0; kk < BKK; kk += 8) {
            unsigned ah[4][4], al[4][4], bh[4][2], bl[4][2];
            // hi fragments
            #pragma unroll
            for (int mt = 0; mt < 4; mt++) {
                int m0 = warp_m * 64 + mt * 16 + r;
                ah[mt][0] = __float_as_uint(Ah[kk + c    ][m0]);
                ah[mt][1] = __float_as_uint(Ah[kk + c    ][m0 + 8]);
                ah[mt][2] = __float_as_uint(Ah[kk + c + 4][m0]);
                ah[mt][3] = __float_as_uint(Ah[kk + c + 4][m0 + 8]);
            }
            #pragma unroll
            for (int nt = 0; nt < 4; nt++) {
                int n0 = warp_n * 32 + nt * 8 + r;
                bh[nt][0] = __float_as_uint(Bh[kk + c    ][n0]);
                bh[nt][1] = __float_as_uint(Bh[kk + c + 4][n0]);
            }
            #pragma unroll
            for (int mt = 0; mt < 4; mt++)
                #pragma unroll
                for (int nt = 0; nt < 4; nt++)
                    mma8(acc[mt][nt], ah[mt], bh[nt]);     // hi * hi
            // lo(A) * hi(B)
            #pragma unroll
            for (int mt = 0; mt < 4; mt++) {
                int m0 = warp_m * 64 + mt * 16 + r;
                al[mt][0] = __float_as_uint(Al[kk + c    ][m0]);
                al[mt][1] = __float_as_uint(Al[kk + c    ][m0 + 8]);
                al[mt][2] = __float_as_uint(Al[kk + c + 4][m0]);
                al[mt][3] = __float_as_uint(Al[kk + c + 4][m0 + 8]);
            }
            #pragma unroll
            for (int mt = 0; mt < 4; mt++)
                #pragma unroll
                for (int nt = 0; nt < 4; nt++)
                    mma8(acc[mt][nt], al[mt], bh[nt]);
            // hi(A) * lo(B)
            #pragma unroll
            for (int nt = 0; nt < 4; nt++) {
                int n0 = warp_n * 32 + nt * 8 + r;
                bl[nt][0] = __float_as_uint(Bl[kk + c    ][n0]);
                bl[nt][1] = __float_as_uint(Bl[kk + c + 4][n0]);
            }
            #pragma unroll
            for (int mt = 0; mt < 4; mt++)
                #pragma unroll
                for (int nt = 0; nt < 4; nt++)
                    mma8(acc[mt][nt], ah[mt], bl[nt]);
        }
        __syncthreads();
    }

    if (MODE == 3) {
        __shared__ float sred[BM];
        if (tid < BM) sred[tid] = 0.f;
        __syncthreads();
        #pragma unroll
        for (int mt = 0; mt < 4; mt++) {
            int mloc = warp_m * 64 + mt * 16 + r;
            int m0 = bm + mloc;
            int b0 = m0 / KBsz;
            int b1 = (m0 + 8) / KBsz;
            float p0 = 0.f, p1 = 0.f;
            #pragma unroll
            for (int nt = 0; nt < 4; nt++) {
                int n0 = bn + warp_n * 32 + nt * 8 + 2 * c;
                float v;
                v = eluf((acc[mt][nt][0] + bias[n0  ]) * colmul[(size_t)b0 * cmStride + n0  ]); p0 += v * rvec[n0];
                v = eluf((acc[mt][nt][1] + bias[n0+1]) * colmul[(size_t)b0 * cmStride + n0+1]); p0 += v * rvec[n0+1];
                v = eluf((acc[mt][nt][2] + bias[n0  ]) * colmul[(size_t)b1 * cmStride + n0  ]); p1 += v * rvec[n0];
                v = eluf((acc[mt][nt][3] + bias[n0+1]) * colmul[(size_t)b1 * cmStride + n0+1]); p1 += v * rvec[n0+1];
            }
            p0 += __shfl_xor_sync(0xffffffffu, p0, 1);
            p0 += __shfl_xor_sync(0xffffffffu, p0, 2);
            p1 += __shfl_xor_sync(0xffffffffu, p1, 1);
            p1 += __shfl_xor_sync(0xffffffffu, p1, 2);
            if (c == 0) {
                atomicAdd(&sred[mloc], p0);
                atomicAdd(&sred[mloc + 8], p1);
            }
        }
        __syncthreads();
        if (tid < BM) atomicAdd(&svec[bm + tid], sred[tid]);
        return;
    }

    #pragma unroll
    for (int mt = 0; mt < 4; mt++) {
        int m0 = bm + warp_m * 64 + mt * 16 + r;
        #pragma unroll
        for (int nt = 0; nt < 4; nt++) {
            int n0 = bn + warp_n * 32 + nt * 8 + 2 * c;
            float2 v0, v1;
            v0.x = acc[mt][nt][0]; v0.y = acc[mt][nt][1];
            v1.x = acc[mt][nt][2]; v1.y = acc[mt][nt][3];
            if (MODE == 2) {
                float2 a0 = *(const float2*)(addmat + (size_t)m0 * N + n0);
                float2 a1 = *(const float2*)(addmat + (size_t)(m0 + 8) * N + n0);
                v0.x = eluf(v0.x + a0.x); v0.y = eluf(v0.y + a0.y);
                v1.x = eluf(v1.x + a1.x); v1.y = eluf(v1.y + a1.y);
            } else {
                float bx = bias[n0], by = bias[n0 + 1];
                v0.x += bx; v0.y += by; v1.x += bx; v1.y += by;
                if (MODE == 1) {
                    v0.x = tanhf(v0.x); v0.y = tanhf(v0.y);
                    v1.x = tanhf(v1.x); v1.y = tanhf(v1.y);
                }
            }
            *(float2*)(C + (size_t)m0 * N + n0) = v0;
            *(float2*)(C + (size_t)(m0 + 8) * N + n0) = v1;
        }
    }
}

// ---------------- step C: per-(b,s) word attention ---------------------------
__global__ void word_attn_k(const float* __restrict__ qall,
                            const float* __restrict__ qword,
                            const float* __restrict__ caw,
                            float* __restrict__ ch)
{
    int b = blockIdx.x, s = blockIdx.y;
    __shared__ float qs[Dd];
    __shared__ float lg[Ll];
    int tid = threadIdx.x;
    for (int d = tid; d < Dd; d += 256)
        qs[d] = qall[((size_t)s * Bsz + b) * Dd + d] * caw[d];
    __syncthreads();
    int wid = tid >> 5, lane = tid & 31;
    for (int l = wid; l < Ll; l += 8) {
        const float* qw = qword + ((size_t)b * Ll + l) * Dd;
        float a = 0.f;
        for (int d = lane; d < Dd; d += 32) a += qs[d] * qw[d];
        #pragma unroll
        for (int o = 16; o; o >>= 1) a += __shfl_xor_sync(0xffffffffu, a, o);
        if (lane == 0) lg[l] = a;
    }
    __syncthreads();
    if (tid == 0) {
        float mx = -INFINITY;
        for (int l = 0; l < Ll; l++) mx = fmaxf(mx, lg[l]);
        float sm = 0.f;
        for (int l = 0; l < Ll; l++) { float e = expf(lg[l] - mx); lg[l] = e; sm += e; }
        float inv = 1.f / sm;
        for (int l = 0; l < Ll; l++) lg[l] *= inv;
    }
    __syncthreads();
    for (int d = tid; d < Dd; d += 256) {
        float a = 0.f;
        for (int l = 0; l < Ll; l++) a += lg[l] * qword[((size_t)b * Ll + l) * Dd + d];
        ch[((size_t)b * Ss + s) * Dd + d] = a;
    }
}

// ---------------- norm over S axis -------------------------------------------
__global__ void norm_k(const float* __restrict__ chkey, float* __restrict__ normed)
{
    int i = blockIdx.x * blockDim.x + threadIdx.x;
    if (i >= Bsz * Dd) return;
    int b = i >> 9, d = i & 511;
    size_t base = (size_t)b * Ss * Dd + d;
    float ss = 0.f;
    #pragma unroll
    for (int s = 0; s < Ss; s++) { float v = chkey[base + s * Dd]; ss += v * v; }
    float inv = 1.f / sqrtf(ss);
    #pragma unroll
    for (int s = 0; s < Ss; s++) normed[base + s * Dd] = chkey[base + s * Dd] * inv;
}

// ---------------- causal self-attn over the 40-step sequence -----------------
__global__ void gram_k(const float* __restrict__ normed, float* __restrict__ Amat)
{
    int tb = blockIdx.x, i = blockIdx.y;
    __shared__ float Ki[Dd];
    __shared__ float lg[TS];
    int tid = threadIdx.x;
    int ti = i / Ss, si = i % Ss;
    size_t rowi = ((size_t)(ti * TBsz + tb) * Ss + si) * Dd;
    for (int d = tid; d < Dd; d += 256) Ki[d] = normed[rowi + d];
    __syncthreads();
    int wid = tid >> 5, lane = tid & 31;
    for (int j = wid; j < TS; j += 8) {
        float a;
        if (j > i) a = -1e30f;
        else {
            int tj = j / Ss, sj = j % Ss;
            size_t rowj = ((size_t)(tj * TBsz + tb) * Ss + sj) * Dd;
            a = 0.f;
            for (int d = lane; d < Dd; d += 32) a += Ki[d] * normed[rowj + d];
            #pragma unroll
            for (int o = 16; o; o >>= 1) a += __shfl_xor_sync(0xffffffffu, a, o);
        }
        if (lane == 0) lg[j] = a;
    }
    __syncthreads();
    if (tid == 0) {
        float mx = -INFINITY;
        for (int j = 0; j < TS; j++) mx = fmaxf(mx, lg[j]);
        float sm = 0.f;
        for (int j = 0; j < TS; j++) { float e = expf(lg[j] - mx); lg[j] = e; sm += e; }
        float inv = 1.f / sm;
        for (int j = 0; j < TS; j++) lg[j] *= inv;
    }
    __syncthreads();
    if (tid < TS) Amat[((size_t)tb * TS + i) * TS + tid] = lg[tid];
}

__global__ void attv_k(const float* __restrict__ Amat,
                       const float* __restrict__ chval,
                       float* __restrict__ att)
{
    int tb = blockIdx.x, i = blockIdx.y;
    __shared__ float aw[TS];
    int tid = threadIdx.x;
    if (tid < TS) aw[tid] = Amat[((size_t)tb * TS + i) * TS + tid];
    __syncthreads();
    int ti = i / Ss, si = i % Ss;
    for (int d = tid; d < Dd; d += 256) {
        float a = 0.f;
        for (int j = 0; j <= i; j++) {   // strictly causal: rest are exactly 0
            int tj = j / Ss, sj = j % Ss;
            a += aw[j] * chval[((size_t)(tj * TBsz + tb) * Ss + sj) * Dd + d];
        }
        att[((size_t)(ti * TBsz + tb) * Ss + si) * Dd + d] = a;
    }
}

// ---------------- misc small kernels -----------------------------------------
__global__ void bcast_k(const float* __restrict__ src, float* __restrict__ dst)
{
    int i = blockIdx.x * blockDim.x + threadIdx.x;
    if (i < Bsz * Dd) dst[i] = src[i & 511];
}

__global__ void zero_k(float* __restrict__ p, int n)
{
    int i = blockIdx.x * blockDim.x + threadIdx.x;
    if (i < n) p[i] = 0.f;
}

// per-b softmax over KB scores + weighted read of knowledge
__global__ void read_k(const float* __restrict__ s,
                       const float* __restrict__ knowledge,
                       float* __restrict__ readv)
{
    int b = blockIdx.x;
    __shared__ float sv[KBsz];
    int tid = threadIdx.x;
    if (tid < KBsz) sv[tid] = s[(size_t)b * KBsz + tid];
    __syncthreads();
    if (tid == 0) {
        float mx = -INFINITY;
        for (int k = 0; k < KBsz; k++) mx = fmaxf(mx, sv[k]);
        float sm = 0.f;
        for (int k = 0; k < KBsz; k++) { float e = expf(sv[k] - mx); sv[k] = e; sm += e; }
        float inv = 1.f / sm;
        for (int k = 0; k < KBsz; k++) sv[k] *= inv;
    }
    __syncthreads();
    for (int d = tid; d < Dd; d += 256) {
        float a = 0.f;
        for (int k = 0; k < KBsz; k++)
            a += sv[k] * knowledge[((size_t)b * KBsz + k) * Dd + d];
        readv[(size_t)b * Dd + d] = a;
    }
}

__global__ void out_k(const float* __restrict__ mem,
                      const float* __restrict__ att,
                      float* __restrict__ out, int out_size)
{
    int i = blockIdx.x * blockDim.x + threadIdx.x;
    const int BD = Bsz * Dd;
    if (i >= BD) return;
    if (i < out_size) out[i] = mem[i];
    if (out_size >= 2 * BD) {
        int b = i >> 9, d = i & 511;
        out[BD + i] = att[((size_t)b * Ss + (Ss - 1)) * Dd + d];
    }
}

// ---------------- launch -----------------------------------------------------
static float* sym(const void* s) { void* p = nullptr; cudaGetSymbolAddress(&p, s); return (float*)p; }

extern "C" void kernel_launch(void* const* d_in, const int* in_sizes, int n_in,
                              void* d_out, int out_size)
{
    const float* qword     = (const float*)d_in[0];
    const float* qemb      = (const float*)d_in[1];
    const float* knowledge = (const float*)d_in[2];
    // d_in[3] = question_lengths (unused by the reference)
    const float* ci_w     = (const float*)d_in[4];
    const float* ci_b     = (const float*)d_in[5];
    const float* ciu_w    = (const float*)d_in[6];
    const float* ciu_b    = (const float*)d_in[7];
    const float* ca_w     = (const float*)d_in[8];
    const float* kproj_w  = (const float*)d_in[10];
    const float* kproj_b  = (const float*)d_in[11];
    const float* mproj_w  = (const float*)d_in[12];
    const float* mproj_b  = (const float*)d_in[13];
    const float* concat_w = (const float*)d_in[14];
    const float* concat_b = (const float*)d_in[15];
    const float* concat2_w= (const float*)d_in[16];
    const float* concat2_b= (const float*)d_in[17];
    const float* rattn_w  = (const float*)d_in[18];
    const float* write_w  = (const float*)d_in[20];
    const float* write_b  = (const float*)d_in[21];
    const float* init_mem = (const float*)d_in[22];
    const float* kq_w     = (const float*)d_in[23];
    const float* kq_b     = (const float*)d_in[24];
    const float* val_w    = (const float*)d_in[25];
    const float* val_b    = (const float*)d_in[26];
    float* out = (float*)d_out;

    float* q0    = sym(g_q0);
    float* qall  = sym(g_qall);
    float* ch    = sym(g_ch);
    float* chkey = sym(g_chkey);
    float* chval = sym(g_chval);
    float* normed= sym(g_normed);
    float* Amat  = sym(g_Amat);
    float* att   = sym(g_att);
    float* kp    = sym(g_kp);
    float* kp2   = sym(g_kp2);
    float* e1    = sym(g_e1);
    float* mp    = sym(g_mp);
    float* sbuf  = sym(g_s);
    float* readv = sym(g_read);
    float* mem0  = sym(g_mem0);
    float* mem1  = sym(g_mem1);

    auto G = [](int M, int N) { return dim3(N / BN, M / BM); };
    const float* NPF = nullptr;

    // q0 = tanh(qemb @ ci_w + ci_b)
    sgemm_k<1><<<G(Bsz, Dd), 256>>>(qemb, Dd, qemb, Dd, Dd, ci_w, ci_b, q0,
                                    Bsz, Dd, Dd, NPF, NPF, NPF, 0, NPF, nullptr);
    // qall[s] = q0 @ ciu_w[s] + ciu_b[s]
    for (int s = 0; s < Ss; s++)
        sgemm_k<0><<<G(Bsz, Dd), 256>>>(q0, Dd, q0, Dd, Dd,
                                        ciu_w + (size_t)s * Dd * Dd, ciu_b + s * Dd,
                                        qall + (size_t)s * Bsz * Dd,
                                        Bsz, Dd, Dd, NPF, NPF, NPF, 0, NPF, nullptr);
    // word attention -> ch
    word_attn_k<<<dim3(Bsz, Ss), 256>>>(qall, qword, ca_w, ch);
    // ch_key / ch_val
    sgemm_k<0><<<G(Bsz * Ss, Dd), 256>>>(ch, Dd, ch, Dd, Dd, kq_w, kq_b, chkey,
                                         Bsz * Ss, Dd, Dd, NPF, NPF, NPF, 0, NPF, nullptr);
    sgemm_k<0><<<G(Bsz * Ss, Dd), 256>>>(ch, Dd, ch, Dd, Dd, val_w, val_b, chval,
                                         Bsz * Ss, Dd, Dd, NPF, NPF, NPF, 0, NPF, nullptr);
    // norm over S, causal self-attn, att
    norm_k<<<(Bsz * Dd + 255) / 256, 256>>>(chkey, normed);
    gram_k<<<dim3(TBsz, TS), 256>>>(normed, Amat);
    attv_k<<<dim3(TBsz, TS), 256>>>(Amat, chval, att);
    // know_proj, kp2 (loop-invariant)
    sgemm_k<0><<<G(MKB, Dd), 256>>>(knowledge, Dd, knowledge, Dd, Dd, kproj_w, kproj_b, kp,
                                    MKB, Dd, Dd, NPF, NPF, NPF, 0, NPF, nullptr);
    sgemm_k<0><<<G(MKB, Dd), 256>>>(kp, Dd, kp, Dd, Dd,
                                    concat_w + (size_t)Dd * Dd, concat_b, kp2,
                                    MKB, Dd, Dd, NPF, NPF, NPF, 0, NPF, nullptr);
    // memory init
    bcast_k<<<(Bsz * Dd + 255) / 256, 256>>>(init_mem, mem0);

    float* mcur = mem0;
    float* mnext = mem1;
    for (int i = 0; i < Ss; i++) {
        // mp = memory @ mproj_w + mproj_b
        sgemm_k<0><<<G(Bsz, Dd), 256>>>(mcur, Dd, mcur, Dd, Dd, mproj_w, mproj_b, mp,
                                        Bsz, Dd, Dd, NPF, NPF, NPF, 0, NPF, nullptr);
        // E1 = elu((kp * mp[b]) @ concat_w_top + kp2)
        sgemm_k<2><<<G(MKB, Dd), 256>>>(kp, Dd, kp, Dd, Dd, concat_w, NPF, e1,
                                        MKB, Dd, Dd, mp, kp2, NPF, 0, NPF, nullptr);
        // scores: s[m] = sum_n elu((E1@concat2_w + b)*control)*rattn_w
        zero_k<<<(MKB + 255) / 256, 256>>>(sbuf, MKB);
        sgemm_k<3><<<G(MKB, Dd), 256>>>(e1, Dd, e1, Dd, Dd, concat2_w, concat2_b, nullptr,
                                        MKB, Dd, Dd, NPF, NPF,
                                        att + (size_t)i * Dd, Ss * Dd, rattn_w, sbuf);
        // softmax over KB + weighted read of knowledge
        read_k<<<Bsz, 256>>>(sbuf, knowledge, readv);
        // memory' = [memory, read] @ write_w + write_b
        sgemm_k<0><<<G(Bsz, Dd), 256>>>(mcur, Dd, readv, Dd, Dd, write_w, write_b, mnext,
                                        Bsz, 2 * Dd, Dd, NPF, NPF, NPF, 0, NPF, nullptr);
        float* t = mcur; mcur = mnext; mnext = t;
    }

    out_k<<<(Bsz * Dd + 255) / 256, 256>>>(mcur, att, out, out_size);
}

// round 4
// speedup vs baseline: 1.3799x; 1.3799x over previous
#include <cuda_runtime.h>
#include <math.h>

// Problem constants
#define Bsz 640
#define Dd 512
#define Ss 4
#define Tt 10
#define TBsz 64
#define Ll 30
#define KBsz 196
#define MKB (Bsz*KBsz)   // 125440
#define TS 40            // T*S

// ---------------- scratch (static device globals; no allocations) ----------
__device__ float g_q0[Bsz*Dd];
__device__ float g_qall[Ss*Bsz*Dd];
__device__ float g_ch[Bsz*Ss*Dd];
__device__ float g_chkey[Bsz*Ss*Dd];
__device__ float g_chval[Bsz*Ss*Dd];
__device__ float g_normed[Bsz*Ss*Dd];
__device__ float g_Amat[TBsz*TS*TS];
__device__ float g_att[Bsz*Ss*Dd];
__device__ float g_kp [(size_t)MKB*Dd];      // know_proj raw
__device__ float g_kph[(size_t)MKB*Dd];      // know_proj tf32 hi
__device__ float g_kpl[(size_t)MKB*Dd];      // know_proj tf32 lo
__device__ float g_kp2[(size_t)MKB*Dd];      // kp @ concat_w[D:] + concat_b
__device__ float g_e1h[(size_t)MKB*Dd];
__device__ float g_e1l[(size_t)MKB*Dd];
__device__ float g_ah [(size_t)MKB*Dd];      // (kp*mp) hi
__device__ float g_al [(size_t)MKB*Dd];      // (kp*mp) lo
__device__ float g_knh[(size_t)MKB*Dd];      // knowledge hi
__device__ float g_knl[(size_t)MKB*Dd];      // knowledge lo
__device__ float g_wh[4][Dd*Dd];             // weight splits hi
__device__ float g_wl[4][Dd*Dd];             // weight splits lo
__device__ float g_mp[Bsz*Dd];
__device__ float g_s[MKB];
__device__ float g_read[Bsz*Dd];
__device__ float g_mem0[Bsz*Dd];
__device__ float g_mem1[Bsz*Dd];

__device__ __forceinline__ float eluf(float x){ return x > 0.f ? x : expm1f(x); }

__device__ __forceinline__ unsigned tf32r(float x){
    unsigned r; asm("cvt.rna.tf32.f32 %0, %1;" : "=r"(r) : "f"(x)); return r;
}
__device__ __forceinline__ void split2(float x, float& hi, float& lo){
    hi = __uint_as_float(tf32r(x));
    lo = __uint_as_float(tf32r(x - hi));
}

__device__ __forceinline__ void mma8(float* cc, const unsigned* a, const unsigned* b){
    asm("mma.sync.aligned.m16n8k8.row.col.f32.tf32.tf32.f32 "
        "{%0,%1,%2,%3}, {%4,%5,%6,%7}, {%8,%9}, {%0,%1,%2,%3};"
        : "+f"(cc[0]), "+f"(cc[1]), "+f"(cc[2]), "+f"(cc[3])
        : "r"(a[0]), "r"(a[1]), "r"(a[2]), "r"(a[3]), "r"(b[0]), "r"(b[1]));
}

__device__ __forceinline__ void cpa16(void* sdst, const void* gsrc){
    unsigned s = (unsigned)__cvta_generic_to_shared(sdst);
    asm volatile("cp.async.cg.shared.global [%0], [%1], 16;" :: "r"(s), "l"(gsrc));
}
__device__ __forceinline__ void cpa_commit(){ asm volatile("cp.async.commit_group;"); }

// =====================  big tensor-core GEMM (K=N=512)  =====================
// C = epilogue( A @ B ), A pre-split hi/lo [M,512] row-major, B pre-split
// hi/lo [512,512] row-major. Split-tf32 3-pass (hi*hi + lo*hi + hi*lo).
// MODE 0: Craw = acc + bias
// MODE 1: Craw/Chi/Clo = acc + bias (split outputs too)
// MODE 2: t = elu(acc + addmat); Chi/Clo = split(t)
// MODE 3: svec[m] += sum_n elu((acc+bias[n])*colmul[(m/KB)*cmStride+n])*rvec[n]
#define TGK 512
#define TGN 512
#define APAD 20
#define BPAD 136
#define NKIT (TGK/16)

template<int MODE>
__global__ __launch_bounds__(256)
void tgemm_k(const float* __restrict__ Ahg, const float* __restrict__ Alg,
             const float* __restrict__ Bhg, const float* __restrict__ Blg,
             const float* __restrict__ bias,
             float* __restrict__ Craw, float* __restrict__ Chi, float* __restrict__ Clo,
             const float* __restrict__ addmat,
             const float* __restrict__ colmul, int cmStride,
             const float* __restrict__ rvec, float* __restrict__ svec)
{
    extern __shared__ float smem[];
    // layout: A tiles: [stage][h/l][128][APAD]  then B tiles [stage][h/l][16][BPAD]
    float* Abase = smem;                         // 2*2*128*20
    float* Bbase = smem + 2*2*128*APAD;          // 2*2*16*136

    const int bm = blockIdx.y * 128;
    const int bn = blockIdx.x * 128;
    const int tid = threadIdx.x;
    const int wid = tid >> 5, lane = tid & 31;
    const int warp_m = wid & 1;
    const int warp_n = wid >> 1;
    const int r = lane >> 2, c = lane & 3;

    float acc[4][4][4];
    #pragma unroll
    for (int i = 0; i < 4; i++)
        #pragma unroll
        for (int j = 0; j < 4; j++)
            #pragma unroll
            for (int q = 0; q < 4; q++) acc[i][j][q] = 0.f;

    // copy one K-stage (16 columns) into buffers
    auto do_copy = [&](int k0, int st){
        float* As[2] = { Abase + (st*2+0)*128*APAD, Abase + (st*2+1)*128*APAD };
        float* Bs[2] = { Bbase + (st*2+0)*16*BPAD,  Bbase + (st*2+1)*16*BPAD  };
        const float* Ag[2] = { Ahg, Alg };
        const float* Bg[2] = { Bhg, Blg };
        #pragma unroll
        for (int h = 0; h < 2; h++) {
            #pragma unroll
            for (int e2 = 0; e2 < 2; e2++) {
                int e   = tid * 2 + e2;          // 0..511
                int row = e >> 2;                // 0..127
                int kq  = (e & 3) * 4;
                cpa16(As[h] + row*APAD + kq,
                      Ag[h] + (size_t)(bm + row)*TGK + k0*16 + kq);
            }
            #pragma unroll
            for (int e2 = 0; e2 < 2; e2++) {
                int e   = tid * 2 + e2;
                int row = e >> 5;                // 0..15
                int c4  = (e & 31) * 4;
                cpa16(Bs[h] + row*BPAD + c4,
                      Bg[h] + (size_t)(k0*16 + row)*TGN + bn + c4);
            }
        }
        cpa_commit();
    };

    do_copy(0, 0);

    for (int k0 = 0; k0 < NKIT; k0++) {
        int st = k0 & 1;
        if (k0 + 1 < NKIT) {
            do_copy(k0 + 1, st ^ 1);
            asm volatile("cp.async.wait_group 1;" ::: "memory");
        } else {
            asm volatile("cp.async.wait_group 0;" ::: "memory");
        }
        __syncthreads();

        const float* Ash = Abase + (st*2+0)*128*APAD;
        const float* Asl = Abase + (st*2+1)*128*APAD;
        const float* Bsh = Bbase + (st*2+0)*16*BPAD;
        const float* Bsl = Bbase + (st*2+1)*16*BPAD;

        #pragma unroll
        for (int kk = 0; kk < 16; kk += 8) {
            unsigned ah[4][4], al[4][4], bh[4][2], bl[4][2];
            #pragma unroll
            for (int mt = 0; mt < 4; mt++) {
                int m0 = warp_m*64 + mt*16 + r;
                ah[mt][0] = __float_as_uint(Ash[(m0    )*APAD + kk + c    ]);
                ah[mt][1] = __float_as_uint(Ash[(m0 + 8)*APAD + kk + c    ]);
                ah[mt][2] = __float_as_uint(Ash[(m0    )*APAD + kk + c + 4]);
                ah[mt][3] = __float_as_uint(Ash[(m0 + 8)*APAD + kk + c + 4]);
                al[mt][0] = __float_as_uint(Asl[(m0    )*APAD + kk + c    ]);
                al[mt][1] = __float_as_uint(Asl[(m0 + 8)*APAD + kk + c    ]);
                al[mt][2] = __float_as_uint(Asl[(m0    )*APAD + kk + c + 4]);
                al[mt][3] = __float_as_uint(Asl[(m0 + 8)*APAD + kk + c + 4]);
            }
            #pragma unroll
            for (int nt = 0; nt < 4; nt++) {
                int n0 = warp_n*32 + nt*8 + r;
                bh[nt][0] = __float_as_uint(Bsh[(kk + c    )*BPAD + n0]);
                bh[nt][1] = __float_as_uint(Bsh[(kk + c + 4)*BPAD + n0]);
                bl[nt][0] = __float_as_uint(Bsl[(kk + c    )*BPAD + n0]);
                bl[nt][1] = __float_as_uint(Bsl[(kk + c + 4)*BPAD + n0]);
            }
            #pragma unroll
            for (int mt = 0; mt < 4; mt++)
                #pragma unroll
                for (int nt = 0; nt < 4; nt++)
                    mma8(acc[mt][nt], ah[mt], bh[nt]);
            #pragma unroll
            for (int mt = 0; mt < 4; mt++)
                #pragma unroll
                for (int nt = 0; nt < 4; nt++)
                    mma8(acc[mt][nt], al[mt], bh[nt]);
            #pragma unroll
            for (int mt = 0; mt < 4; mt++)
                #pragma unroll
                for (int nt = 0; nt < 4; nt++)
                    mma8(acc[mt][nt], ah[mt], bl[nt]);
        }
        __syncthreads();
    }

    if (MODE == 3) {
        __shared__ float sred[128];
        if (tid < 128) sred[tid] = 0.f;
        __syncthreads();
        #pragma unroll
        for (int mt = 0; mt < 4; mt++) {
            int mloc = warp_m*64 + mt*16 + r;
            int m0 = bm + mloc;
            int b0 = m0 / KBsz;
            int b1 = (m0 + 8) / KBsz;
            float p0 = 0.f, p1 = 0.f;
            #pragma unroll
            for (int nt = 0; nt < 4; nt++) {
                int n0 = bn + warp_n*32 + nt*8 + 2*c;
                float v;
                v = eluf((acc[mt][nt][0] + bias[n0  ]) * colmul[(size_t)b0*cmStride + n0  ]); p0 += v*rvec[n0];
                v = eluf((acc[mt][nt][1] + bias[n0+1]) * colmul[(size_t)b0*cmStride + n0+1]); p0 += v*rvec[n0+1];
                v = eluf((acc[mt][nt][2] + bias[n0  ]) * colmul[(size_t)b1*cmStride + n0  ]); p1 += v*rvec[n0];
                v = eluf((acc[mt][nt][3] + bias[n0+1]) * colmul[(size_t)b1*cmStride + n0+1]); p1 += v*rvec[n0+1];
            }
            p0 += __shfl_xor_sync(0xffffffffu, p0, 1);
            p0 += __shfl_xor_sync(0xffffffffu, p0, 2);
            p1 += __shfl_xor_sync(0xffffffffu, p1, 1);
            p1 += __shfl_xor_sync(0xffffffffu, p1, 2);
            if (c == 0) { atomicAdd(&sred[mloc], p0); atomicAdd(&sred[mloc + 8], p1); }
        }
        __syncthreads();
        if (tid < 128) atomicAdd(&svec[bm + tid], sred[tid]);
        return;
    }

    #pragma unroll
    for (int mt = 0; mt < 4; mt++) {
        int m0 = bm + warp_m*64 + mt*16 + r;
        #pragma unroll
        for (int nt = 0; nt < 4; nt++) {
            int n0 = bn + warp_n*32 + nt*8 + 2*c;
            #pragma unroll
            for (int half = 0; half < 2; half++) {
                int mm = m0 + half*8;
                float vx = acc[mt][nt][2*half], vy = acc[mt][nt][2*half+1];
                if (MODE == 2) {
                    float2 ad = *(const float2*)(addmat + (size_t)mm*TGN + n0);
                    vx = eluf(vx + ad.x); vy = eluf(vy + ad.y);
                    float hx, lx, hy, ly;
                    split2(vx, hx, lx); split2(vy, hy, ly);
                    *(float2*)(Chi + (size_t)mm*TGN + n0) = make_float2(hx, hy);
                    *(float2*)(Clo + (size_t)mm*TGN + n0) = make_float2(lx, ly);
                } else {
                    vx += bias[n0]; vy += bias[n0+1];
                    *(float2*)(Craw + (size_t)mm*TGN + n0) = make_float2(vx, vy);
                    if (MODE == 1) {
                        float hx, lx, hy, ly;
                        split2(vx, hx, lx); split2(vy, hy, ly);
                        *(float2*)(Chi + (size_t)mm*TGN + n0) = make_float2(hx, hy);
                        *(float2*)(Clo + (size_t)mm*TGN + n0) = make_float2(lx, ly);
                    }
                }
            }
        }
    }
}

// ---------------- pre-split kernels ------------------------------------------
__global__ void splitmat_k(const float* __restrict__ src,
                           float* __restrict__ hi, float* __restrict__ lo, int n)
{
    int i = (blockIdx.x * blockDim.x + threadIdx.x) * 4;
    if (i >= n) return;
    float4 v = *(const float4*)(src + i);
    float4 h, l;
    split2(v.x, h.x, l.x); split2(v.y, h.y, l.y);
    split2(v.z, h.z, l.z); split2(v.w, h.w, l.w);
    *(float4*)(hi + i) = h;
    *(float4*)(lo + i) = l;
}

__global__ void scale_split_k(const float* __restrict__ kp,
                              const float* __restrict__ mp,
                              float* __restrict__ hi, float* __restrict__ lo)
{
    size_t i = ((size_t)blockIdx.x * blockDim.x + threadIdx.x) * 4;
    if (i >= (size_t)MKB * Dd) return;
    int m = (int)(i >> 9);
    int d = (int)(i & 511);
    int b = m / KBsz;
    float4 v = *(const float4*)(kp + i);
    float4 s = *(const float4*)(mp + (size_t)b * Dd + d);
    v.x *= s.x; v.y *= s.y; v.z *= s.z; v.w *= s.w;
    float4 h, l;
    split2(v.x, h.x, l.x); split2(v.y, h.y, l.y);
    split2(v.z, h.z, l.z); split2(v.w, h.w, l.w);
    *(float4*)(hi + i) = h;
    *(float4*)(lo + i) = l;
}

// =====================  small FFMA2 GEMM (M=640 ops)  ========================
__device__ __forceinline__ unsigned long long pack2(float lo, float hi) {
    unsigned long long r;
    asm("mov.b64 %0, {%1, %2};" : "=l"(r) : "f"(lo), "f"(hi));
    return r;
}
__device__ __forceinline__ void unpack2(unsigned long long v, float& lo, float& hi) {
    asm("mov.b64 {%0, %1}, %2;" : "=f"(lo), "=f"(hi) : "l"(v));
}
__device__ __forceinline__ void fma2(unsigned long long& d,
                                     unsigned long long a, unsigned long long b) {
    asm("fma.rn.f32x2 %0, %1, %2, %0;" : "+l"(d) : "l"(a), "l"(b));
}

#define BM 128
#define BN 128
#define BKK 16

// MODE 0: C = acc + bias ; MODE 1: C = tanh(acc + bias)
template<int MODE>
__global__ __launch_bounds__(256, 2)
void sgemm_k(const float* __restrict__ A, int lda,
             const float* __restrict__ A2, int lda2, int splitK,
             const float* __restrict__ W,
             const float* __restrict__ bias,
             float* __restrict__ C,
             int M, int K, int N)
{
    __shared__ float As[BKK][BM];
    __shared__ float Bs[BKK][BN];

    const int bm = blockIdx.y * BM;
    const int bn = blockIdx.x * BN;
    const int tid = threadIdx.x;
    const int ty = tid >> 4;
    const int tx = tid & 15;

    unsigned long long acc2[8][4];
    #pragma unroll
    for (int i = 0; i < 8; i++)
        #pragma unroll
        for (int j = 0; j < 4; j++) acc2[i][j] = 0ull;

    for (int k0 = 0; k0 < K; k0 += BKK) {
        #pragma unroll
        for (int e2 = 0; e2 < 2; e2++) {
            int e   = tid * 2 + e2;
            int row = e >> 2;
            int kq  = (e & 3) * 4;
            int m   = bm + row;
            int k   = k0 + kq;
            const float* src = (k < splitK)
                ? (A  + (size_t)m * lda  + k)
                : (A2 + (size_t)m * lda2 + (k - splitK));
            float4 v = *(const float4*)src;
            As[kq + 0][row] = v.x; As[kq + 1][row] = v.y;
            As[kq + 2][row] = v.z; As[kq + 3][row] = v.w;
        }
        #pragma unroll
        for (int e2 = 0; e2 < 2; e2++) {
            int e   = tid * 2 + e2;
            int row = e >> 5;
            int cc  = (e & 31) * 4;
            float4 v = *(const float4*)(W + (size_t)(k0 + row) * N + bn + cc);
            *(float4*)&Bs[row][cc] = v;
        }
        __syncthreads();
        #pragma unroll
        for (int kk = 0; kk < BKK; kk++) {
            float a[8];
            unsigned long long b2[4];
            #pragma unroll
            for (int i = 0; i < 8; i++) a[i] = As[kk][ty * 8 + i];
            #pragma unroll
            for (int j = 0; j < 4; j++)
                b2[j] = *(const unsigned long long*)&Bs[kk][tx * 8 + j * 2];
            #pragma unroll
            for (int i = 0; i < 8; i++) {
                unsigned long long pa = pack2(a[i], a[i]);
                #pragma unroll
                for (int j = 0; j < 4; j++)
                    fma2(acc2[i][j], pa, b2[j]);
            }
        }
        __syncthreads();
    }

    float acc[8][8];
    #pragma unroll
    for (int i = 0; i < 8; i++)
        #pragma unroll
        for (int j = 0; j < 4; j++)
            unpack2(acc2[i][j], acc[i][2*j], acc[i][2*j+1]);

    #pragma unroll
    for (int i = 0; i < 8; i++) {
        int m = bm + ty * 8 + i;
        #pragma unroll
        for (int j = 0; j < 8; j += 4) {
            int n = bn + tx * 8 + j;
            float4 v;
            v.x = acc[i][j] + bias[n];   v.y = acc[i][j+1] + bias[n+1];
            v.z = acc[i][j+2] + bias[n+2]; v.w = acc[i][j+3] + bias[n+3];
            if (MODE == 1) { v.x = tanhf(v.x); v.y = tanhf(v.y); v.z = tanhf(v.z); v.w = tanhf(v.w); }
            *(float4*)(C + (size_t)m * N + n) = v;
        }
    }
}

// ---------------- attention / misc kernels (unchanged, validated) ------------
__global__ void word_attn_k(const float* __restrict__ qall,
                            const float* __restrict__ qword,
                            const float* __restrict__ caw,
                            float* __restrict__ ch)
{
    int b = blockIdx.x, s = blockIdx.y;
    __shared__ float qs[Dd];
    __shared__ float lg[Ll];
    int tid = threadIdx.x;
    for (int d = tid; d < Dd; d += 256)
        qs[d] = qall[((size_t)s * Bsz + b) * Dd + d] * caw[d];
    __syncthreads();
    int wid = tid >> 5, lane = tid & 31;
    for (int l = wid; l < Ll; l += 8) {
        const float* qw = qword + ((size_t)b * Ll + l) * Dd;
        float a = 0.f;
        for (int d = lane; d < Dd; d += 32) a += qs[d] * qw[d];
        #pragma unroll
        for (int o = 16; o; o >>= 1) a += __shfl_xor_sync(0xffffffffu, a, o);
        if (lane == 0) lg[l] = a;
    }
    __syncthreads();
    if (tid == 0) {
        float mx = -INFINITY;
        for (int l = 0; l < Ll; l++) mx = fmaxf(mx, lg[l]);
        float sm = 0.f;
        for (int l = 0; l < Ll; l++) { float e = expf(lg[l] - mx); lg[l] = e; sm += e; }
        float inv = 1.f / sm;
        for (int l = 0; l < Ll; l++) lg[l] *= inv;
    }
    __syncthreads();
    for (int d = tid; d < Dd; d += 256) {
        float a = 0.f;
        for (int l = 0; l < Ll; l++) a += lg[l] * qword[((size_t)b * Ll + l) * Dd + d];
        ch[((size_t)b * Ss + s) * Dd + d] = a;
    }
}

__global__ void norm_k(const float* __restrict__ chkey, float* __restrict__ normed)
{
    int i = blockIdx.x * blockDim.x + threadIdx.x;
    if (i >= Bsz * Dd) return;
    int b = i >> 9, d = i & 511;
    size_t base = (size_t)b * Ss * Dd + d;
    float ss = 0.f;
    #pragma unroll
    for (int s = 0; s < Ss; s++) { float v = chkey[base + s * Dd]; ss += v * v; }
    float inv = 1.f / sqrtf(ss);
    #pragma unroll
    for (int s = 0; s < Ss; s++) normed[base + s * Dd] = chkey[base + s * Dd] * inv;
}

__global__ void gram_k(const float* __restrict__ normed, float* __restrict__ Amat)
{
    int tb = blockIdx.x, i = blockIdx.y;
    __shared__ float Ki[Dd];
    __shared__ float lg[TS];
    int tid = threadIdx.x;
    int ti = i / Ss, si = i % Ss;
    size_t rowi = ((size_t)(ti * TBsz + tb) * Ss + si) * Dd;
    for (int d = tid; d < Dd; d += 256) Ki[d] = normed[rowi + d];
    __syncthreads();
    int wid = tid >> 5, lane = tid & 31;
    for (int j = wid; j < TS; j += 8) {
        float a;
        if (j > i) a = -1e30f;
        else {
            int tj = j / Ss, sj = j % Ss;
            size_t rowj = ((size_t)(tj * TBsz + tb) * Ss + sj) * Dd;
            a = 0.f;
            for (int d = lane; d < Dd; d += 32) a += Ki[d] * normed[rowj + d];
            #pragma unroll
            for (int o = 16; o; o >>= 1) a += __shfl_xor_sync(0xffffffffu, a, o);
        }
        if (lane == 0) lg[j] = a;
    }
    __syncthreads();
    if (tid == 0) {
        float mx = -INFINITY;
        for (int j = 0; j < TS; j++) mx = fmaxf(mx, lg[j]);
        float sm = 0.f;
        for (int j = 0; j < TS; j++) { float e = expf(lg[j] - mx); lg[j] = e; sm += e; }
        float inv = 1.f / sm;
        for (int j = 0; j < TS; j++) lg[j] *= inv;
    }
    __syncthreads();
    if (tid < TS) Amat[((size_t)tb * TS + i) * TS + tid] = lg[tid];
}

__global__ void attv_k(const float* __restrict__ Amat,
                       const float* __restrict__ chval,
                       float* __restrict__ att)
{
    int tb = blockIdx.x, i = blockIdx.y;
    __shared__ float aw[TS];
    int tid = threadIdx.x;
    if (tid < TS) aw[tid] = Amat[((size_t)tb * TS + i) * TS + tid];
    __syncthreads();
    int ti = i / Ss, si = i % Ss;
    for (int d = tid; d < Dd; d += 256) {
        float a = 0.f;
        for (int j = 0; j <= i; j++) {
            int tj = j / Ss, sj = j % Ss;
            a += aw[j] * chval[((size_t)(tj * TBsz + tb) * Ss + sj) * Dd + d];
        }
        att[((size_t)(ti * TBsz + tb) * Ss + si) * Dd + d] = a;
    }
}

__global__ void bcast_k(const float* __restrict__ src, float* __restrict__ dst)
{
    int i = blockIdx.x * blockDim.x + threadIdx.x;
    if (i < Bsz * Dd) dst[i] = src[i & 511];
}

__global__ void zero_k(float* __restrict__ p, int n)
{
    int i = blockIdx.x * blockDim.x + threadIdx.x;
    if (i < n) p[i] = 0.f;
}

__global__ void read_k(const float* __restrict__ s,
                       const float* __restrict__ knowledge,
                       float* __restrict__ readv)
{
    int b = blockIdx.x;
    __shared__ float sv[KBsz];
    int tid = threadIdx.x;
    if (tid < KBsz) sv[tid] = s[(size_t)b * KBsz + tid];
    __syncthreads();
    if (tid == 0) {
        float mx = -INFINITY;
        for (int k = 0; k < KBsz; k++) mx = fmaxf(mx, sv[k]);
        float sm = 0.f;
        for (int k = 0; k < KBsz; k++) { float e = expf(sv[k] - mx); sv[k] = e; sm += e; }
        float inv = 1.f / sm;
        for (int k = 0; k < KBsz; k++) sv[k] *= inv;
    }
    __syncthreads();
    for (int d = tid; d < Dd; d += 256) {
        float a = 0.f;
        for (int k = 0; k < KBsz; k++)
            a += sv[k] * knowledge[((size_t)b * KBsz + k) * Dd + d];
        readv[(size_t)b * Dd + d] = a;
    }
}

__global__ void out_k(const float* __restrict__ mem,
                      const float* __restrict__ att,
                      float* __restrict__ out, int out_size)
{
    int i = blockIdx.x * blockDim.x + threadIdx.x;
    const int BD = Bsz * Dd;
    if (i >= BD) return;
    if (i < out_size) out[i] = mem[i];
    if (out_size >= 2 * BD) {
        int b = i >> 9, d = i & 511;
        out[BD + i] = att[((size_t)b * Ss + (Ss - 1)) * Dd + d];
    }
}

// ---------------- launch -----------------------------------------------------
static float* sym(const void* s) { void* p = nullptr; cudaGetSymbolAddress(&p, s); return (float*)p; }

#define TG_SMEM (2*2*128*APAD*4 + 2*2*16*BPAD*4)

extern "C" void kernel_launch(void* const* d_in, const int* in_sizes, int n_in,
                              void* d_out, int out_size)
{
    const float* qword     = (const float*)d_in[0];
    const float* qemb      = (const float*)d_in[1];
    const float* knowledge = (const float*)d_in[2];
    const float* ci_w     = (const float*)d_in[4];
    const float* ci_b     = (const float*)d_in[5];
    const float* ciu_w    = (const float*)d_in[6];
    const float* ciu_b    = (const float*)d_in[7];
    const float* ca_w     = (const float*)d_in[8];
    const float* kproj_w  = (const float*)d_in[10];
    const float* kproj_b  = (const float*)d_in[11];
    const float* mproj_w  = (const float*)d_in[12];
    const float* mproj_b  = (const float*)d_in[13];
    const float* concat_w = (const float*)d_in[14];
    const float* concat_b = (const float*)d_in[15];
    const float* concat2_w= (const float*)d_in[16];
    const float* concat2_b= (const float*)d_in[17];
    const float* rattn_w  = (const float*)d_in[18];
    const float* write_w  = (const float*)d_in[20];
    const float* write_b  = (const float*)d_in[21];
    const float* init_mem = (const float*)d_in[22];
    const float* kq_w     = (const float*)d_in[23];
    const float* kq_b     = (const float*)d_in[24];
    const float* val_w    = (const float*)d_in[25];
    const float* val_b    = (const float*)d_in[26];
    float* out = (float*)d_out;

    float* q0    = sym(g_q0);
    float* qall  = sym(g_qall);
    float* ch    = sym(g_ch);
    float* chkey = sym(g_chkey);
    float* chval = sym(g_chval);
    float* normed= sym(g_normed);
    float* Amat  = sym(g_Amat);
    float* att   = sym(g_att);
    float* kp    = sym(g_kp);
    float* kph   = sym(g_kph);
    float* kpl   = sym(g_kpl);
    float* kp2   = sym(g_kp2);
    float* e1h   = sym(g_e1h);
    float* e1l   = sym(g_e1l);
    float* ah    = sym(g_ah);
    float* al    = sym(g_al);
    float* knh   = sym(g_knh);
    float* knl   = sym(g_knl);
    float* wh    = sym(g_wh);
    float* wl    = sym(g_wl);
    float* mp    = sym(g_mp);
    float* sbuf  = sym(g_s);
    float* readv = sym(g_read);
    float* mem0  = sym(g_mem0);
    float* mem1  = sym(g_mem1);

    // allow >48KB dynamic smem for tgemm (idempotent)
    static bool attr_done = false;
    if (!attr_done) {
        cudaFuncSetAttribute(tgemm_k<0>, cudaFuncAttributeMaxDynamicSharedMemorySize, TG_SMEM);
        cudaFuncSetAttribute(tgemm_k<1>, cudaFuncAttributeMaxDynamicSharedMemorySize, TG_SMEM);
        cudaFuncSetAttribute(tgemm_k<2>, cudaFuncAttributeMaxDynamicSharedMemorySize, TG_SMEM);
        cudaFuncSetAttribute(tgemm_k<3>, cudaFuncAttributeMaxDynamicSharedMemorySize, TG_SMEM);
        attr_done = true;
    }

    auto Gs = [](int M, int N) { return dim3(N / BN, M / BM); };
    const dim3 GT(TGN / 128, MKB / 128);   // (4, 980)
    const float* NPF = nullptr;

    // --- question path (small, FFMA2) ---
    sgemm_k<1><<<Gs(Bsz, Dd), 256>>>(qemb, Dd, qemb, Dd, Dd, ci_w, ci_b, q0, Bsz, Dd, Dd);
    for (int s = 0; s < Ss; s++)
        sgemm_k<0><<<Gs(Bsz, Dd), 256>>>(q0, Dd, q0, Dd, Dd,
                                         ciu_w + (size_t)s * Dd * Dd, ciu_b + s * Dd,
                                         qall + (size_t)s * Bsz * Dd, Bsz, Dd, Dd);
    word_attn_k<<<dim3(Bsz, Ss), 256>>>(qall, qword, ca_w, ch);
    sgemm_k<0><<<Gs(Bsz * Ss, Dd), 256>>>(ch, Dd, ch, Dd, Dd, kq_w, kq_b, chkey, Bsz * Ss, Dd, Dd);
    sgemm_k<0><<<Gs(Bsz * Ss, Dd), 256>>>(ch, Dd, ch, Dd, Dd, val_w, val_b, chval, Bsz * Ss, Dd, Dd);
    norm_k<<<(Bsz * Dd + 255) / 256, 256>>>(chkey, normed);
    gram_k<<<dim3(TBsz, TS), 256>>>(normed, Amat);
    attv_k<<<dim3(TBsz, TS), 256>>>(Amat, chval, att);

    // --- pre-splits ---
    {
        size_t nk = (size_t)MKB * Dd;
        splitmat_k<<<(unsigned)((nk / 4 + 255) / 256), 256>>>(knowledge, knh, knl, (int)nk);
        int nw = Dd * Dd;
        splitmat_k<<<(nw / 4 + 255) / 256, 256>>>(kproj_w, wh + 0 * Dd * Dd, wl + 0 * Dd * Dd, nw);  // kproj
        splitmat_k<<<(nw / 4 + 255) / 256, 256>>>(concat_w, wh + 1 * Dd * Dd, wl + 1 * Dd * Dd, nw); // concat top
        splitmat_k<<<(nw / 4 + 255) / 256, 256>>>(concat_w + (size_t)Dd * Dd,
                                                  wh + 2 * Dd * Dd, wl + 2 * Dd * Dd, nw);           // concat bottom
        splitmat_k<<<(nw / 4 + 255) / 256, 256>>>(concat2_w, wh + 3 * Dd * Dd, wl + 3 * Dd * Dd, nw);// concat2
    }

    // --- knowledge path precompute (tensor cores) ---
    // kp = knowledge @ kproj_w + kproj_b    (raw + split outputs)
    tgemm_k<1><<<GT, 256, TG_SMEM>>>(knh, knl, wh + 0 * Dd * Dd, wl + 0 * Dd * Dd,
                                     kproj_b, kp, kph, kpl, NPF, NPF, 0, NPF, nullptr);
    // kp2 = kp @ concat_w_bottom + concat_b (raw only)
    tgemm_k<0><<<GT, 256, TG_SMEM>>>(kph, kpl, wh + 2 * Dd * Dd, wl + 2 * Dd * Dd,
                                     concat_b, kp2, nullptr, nullptr, NPF, NPF, 0, NPF, nullptr);

    bcast_k<<<(Bsz * Dd + 255) / 256, 256>>>(init_mem, mem0);

    float* mcur = mem0;
    float* mnext = mem1;
    for (int i = 0; i < Ss; i++) {
        sgemm_k<0><<<Gs(Bsz, Dd), 256>>>(mcur, Dd, mcur, Dd, Dd, mproj_w, mproj_b, mp, Bsz, Dd, Dd);
        // A = split(kp * mp[b])
        {
            size_t nk = (size_t)MKB * Dd;
            scale_split_k<<<(unsigned)((nk / 4 + 255) / 256), 256>>>(kp, mp, ah, al);
        }
        // e1 = elu(A @ concat_w_top + kp2) -> split outputs
        tgemm_k<2><<<GT, 256, TG_SMEM>>>(ah, al, wh + 1 * Dd * Dd, wl + 1 * Dd * Dd,
                                         NPF, nullptr, e1h, e1l, kp2, NPF, 0, NPF, nullptr);
        // scores
        zero_k<<<(MKB + 255) / 256, 256>>>(sbuf, MKB);
        tgemm_k<3><<<GT, 256, TG_SMEM>>>(e1h, e1l, wh + 3 * Dd * Dd, wl + 3 * Dd * Dd,
                                         concat2_b, nullptr, nullptr, nullptr,
                                         NPF, att + (size_t)i * Dd, Ss * Dd, rattn_w, sbuf);
        read_k<<<Bsz, 256>>>(sbuf, knowledge, readv);
        sgemm_k<0><<<Gs(Bsz, Dd), 256>>>(mcur, Dd, readv, Dd, Dd, write_w, write_b, mnext,
                                         Bsz, 2 * Dd, Dd);
        float* t = mcur; mcur = mnext; mnext = t;
    }

    out_k<<<(Bsz * Dd + 255) / 256, 256>>>(mcur, att, out, out_size);
}

// round 5
// speedup vs baseline: 2.1499x; 1.5580x over previous
#include <cuda_runtime.h>
#include <cuda_bf16.h>
#include <math.h>

// Problem constants
#define Bsz 640
#define Dd 512
#define Ss 4
#define Tt 10
#define TBsz 64
#define Ll 30
#define KBsz 196
#define MKB (Bsz*KBsz)   // 125440
#define TS 40            // T*S

typedef __nv_bfloat16 bf16;

// ---------------- scratch (static device globals; no allocations) ----------
__device__ float g_q0[Bsz*Dd];
__device__ float g_qall[Ss*Bsz*Dd];
__device__ float g_ch[Bsz*Ss*Dd];
__device__ float g_chkey[Bsz*Ss*Dd];
__device__ float g_chval[Bsz*Ss*Dd];
__device__ float g_normed[Bsz*Ss*Dd];
__device__ float g_Amat[TBsz*TS*TS];
__device__ float g_att[Bsz*Ss*Dd];
__device__ float g_kp [(size_t)MKB*Dd];      // know_proj raw fp32
__device__ float g_kp2[(size_t)MKB*Dd];      // kp @ concat_w[D:] + concat_b (fp32)
__device__ bf16  g_kph[(size_t)MKB*Dd];      // kp split hi/lo
__device__ bf16  g_kpl[(size_t)MKB*Dd];
__device__ bf16  g_e1h[(size_t)MKB*Dd];
__device__ bf16  g_e1l[(size_t)MKB*Dd];
__device__ bf16  g_ah [(size_t)MKB*Dd];      // (kp*mp) split
__device__ bf16  g_al [(size_t)MKB*Dd];
__device__ bf16  g_knh[(size_t)MKB*Dd];      // knowledge split
__device__ bf16  g_knl[(size_t)MKB*Dd];
__device__ bf16  g_wbh[4][Dd*Dd];            // weight splits hi
__device__ bf16  g_wbl[4][Dd*Dd];            // weight splits lo
__device__ float g_mp[Bsz*Dd];
__device__ float g_s[MKB];
__device__ float g_read[Bsz*Dd];
__device__ float g_mem0[Bsz*Dd];
__device__ float g_mem1[Bsz*Dd];

__device__ __forceinline__ float eluf(float x){ return x > 0.f ? x : expm1f(x); }

__device__ __forceinline__ void splitbf(float x, bf16& h, bf16& l){
    h = __float2bfloat16_rn(x);
    l = __float2bfloat16_rn(x - __bfloat162float(h));
}

__device__ __forceinline__ void mma_bf16(float* cc, const unsigned* a, const unsigned* b){
    asm("mma.sync.aligned.m16n8k16.row.col.f32.bf16.bf16.f32 "
        "{%0,%1,%2,%3}, {%4,%5,%6,%7}, {%8,%9}, {%0,%1,%2,%3};"
        : "+f"(cc[0]), "+f"(cc[1]), "+f"(cc[2]), "+f"(cc[3])
        : "r"(a[0]), "r"(a[1]), "r"(a[2]), "r"(a[3]), "r"(b[0]), "r"(b[1]));
}
__device__ __forceinline__ void ldm4(unsigned* r, const bf16* p){
    unsigned addr = (unsigned)__cvta_generic_to_shared(p);
    asm volatile("ldmatrix.sync.aligned.m8n8.x4.shared.b16 {%0,%1,%2,%3}, [%4];"
                 : "=r"(r[0]), "=r"(r[1]), "=r"(r[2]), "=r"(r[3]) : "r"(addr));
}
__device__ __forceinline__ void ldm4t(unsigned* r, const bf16* p){
    unsigned addr = (unsigned)__cvta_generic_to_shared(p);
    asm volatile("ldmatrix.sync.aligned.m8n8.x4.trans.shared.b16 {%0,%1,%2,%3}, [%4];"
                 : "=r"(r[0]), "=r"(r[1]), "=r"(r[2]), "=r"(r[3]) : "r"(addr));
}
__device__ __forceinline__ void cpa16(void* sdst, const void* gsrc){
    unsigned s = (unsigned)__cvta_generic_to_shared(sdst);
    asm volatile("cp.async.cg.shared.global [%0], [%1], 16;" :: "r"(s), "l"(gsrc));
}
__device__ __forceinline__ void cpa_commit(){ asm volatile("cp.async.commit_group;"); }

// =============  big tensor-core GEMM: split-bf16 3-pass, ldmatrix  ===========
// A pre-split hi/lo bf16 [M,512] row-major, B pre-split hi/lo bf16 [512,512].
// MODE 0: Craw = acc + bias
// MODE 1: Craw = acc + bias ; Chi/Clo = splitbf(Craw)
// MODE 2: t = elu(acc + addmat); Chi/Clo = splitbf(t)
// MODE 3: svec[m] += sum_n elu((acc+bias[n])*colmul[(m/KB)*cmStride+n])*rvec[n]
#define TGK 512
#define TGN 512
#define TBK 32            // bf16 K per tile
#define NKIT (TGK/TBK)    // 16
#define NSTG 3
#define ALD 40            // A smem row stride (bf16): 80B -> conflict-free
#define BLD 136           // B smem row stride (bf16): 272B -> conflict-free
#define A_ST (128*ALD)    // bf16 units per A buffer
#define B_ST (TBK*BLD)

template<int MODE>
__global__ __launch_bounds__(256)
void tgemm_k(const bf16* __restrict__ Ahg, const bf16* __restrict__ Alg,
             const bf16* __restrict__ Bhg, const bf16* __restrict__ Blg,
             const float* __restrict__ bias,
             float* __restrict__ Craw, bf16* __restrict__ Chi, bf16* __restrict__ Clo,
             const float* __restrict__ addmat,
             const float* __restrict__ colmul, int cmStride,
             const float* __restrict__ rvec, float* __restrict__ svec)
{
    extern __shared__ bf16 smem[];
    bf16* Abase = smem;                    // [NSTG][2][128][ALD]
    bf16* Bbase = smem + NSTG*2*A_ST;      // [NSTG][2][TBK][BLD]

    const int bm = blockIdx.y * 128;
    const int bn = blockIdx.x * 128;
    const int tid = threadIdx.x;
    const int wid = tid >> 5, lane = tid & 31;
    const int warp_m = wid & 1;            // 64 rows each
    const int warp_n = wid >> 1;           // 32 cols each
    const int r = lane >> 2, c = lane & 3;
    const int lrow = lane & 15, lcol = (lane >> 4) * 8;

    float acc[4][4][4];
    #pragma unroll
    for (int i = 0; i < 4; i++)
        #pragma unroll
        for (int j = 0; j < 4; j++)
            #pragma unroll
            for (int q = 0; q < 4; q++) acc[i][j][q] = 0.f;

    auto do_copy = [&](int k0, int st){
        const bf16* Ag[2] = { Ahg, Alg };
        const bf16* Bg[2] = { Bhg, Blg };
        #pragma unroll
        for (int h = 0; h < 2; h++) {
            bf16* As = Abase + (st*2 + h) * A_ST;
            bf16* Bs = Bbase + (st*2 + h) * B_ST;
            #pragma unroll
            for (int e2 = 0; e2 < 2; e2++) {
                int e   = tid * 2 + e2;        // 0..511
                int row = e >> 2;              // 0..127
                int seg = (e & 3) * 8;         // bf16 offset, 16B chunks
                cpa16(As + row * ALD + seg,
                      Ag[h] + (size_t)(bm + row) * TGK + k0 * TBK + seg);
            }
            #pragma unroll
            for (int e2 = 0; e2 < 2; e2++) {
                int e   = tid * 2 + e2;        // 0..511
                int row = e >> 4;              // 0..31
                int seg = (e & 15) * 8;        // 0..120
                cpa16(Bs + row * BLD + seg,
                      Bg[h] + (size_t)(k0 * TBK + row) * TGN + bn + seg);
            }
        }
        cpa_commit();
    };

    do_copy(0, 0);
    do_copy(1, 1);

    for (int k0 = 0; k0 < NKIT; k0++) {
        int st = k0 % NSTG;
        if (k0 + 2 < NKIT) {
            do_copy(k0 + 2, (k0 + 2) % NSTG);
            asm volatile("cp.async.wait_group 2;" ::: "memory");
        } else if (k0 + 1 < NKIT) {
            asm volatile("cp.async.wait_group 1;" ::: "memory");
        } else {
            asm volatile("cp.async.wait_group 0;" ::: "memory");
        }
        __syncthreads();

        const bf16* Ash = Abase + (st*2 + 0) * A_ST;
        const bf16* Asl = Abase + (st*2 + 1) * A_ST;
        const bf16* Bsh = Bbase + (st*2 + 0) * B_ST;
        const bf16* Bsl = Bbase + (st*2 + 1) * B_ST;

        #pragma unroll
        for (int ks = 0; ks < 2; ks++) {       // two k16 steps per tile
            unsigned ah[4][4], al[4][4], bh[4][2], bl[4][2];
            #pragma unroll
            for (int mt = 0; mt < 4; mt++) {
                int row = warp_m * 64 + mt * 16 + lrow;
                ldm4(ah[mt], Ash + row * ALD + ks * 16 + lcol);
                ldm4(al[mt], Asl + row * ALD + ks * 16 + lcol);
            }
            #pragma unroll
            for (int p = 0; p < 2; p++) {      // each covers two n8 tiles
                unsigned t[4];
                int rr = ks * 16 + lrow;
                int ccol = warp_n * 32 + p * 16 + lcol;
                ldm4t(t, Bsh + rr * BLD + ccol);
                bh[2*p][0] = t[0]; bh[2*p][1] = t[1];
                bh[2*p+1][0] = t[2]; bh[2*p+1][1] = t[3];
                ldm4t(t, Bsl + rr * BLD + ccol);
                bl[2*p][0] = t[0]; bl[2*p][1] = t[1];
                bl[2*p+1][0] = t[2]; bl[2*p+1][1] = t[3];
            }
            #pragma unroll
            for (int mt = 0; mt < 4; mt++)
                #pragma unroll
                for (int nt = 0; nt < 4; nt++)
                    mma_bf16(acc[mt][nt], ah[mt], bh[nt]);   // hi*hi
            #pragma unroll
            for (int mt = 0; mt < 4; mt++)
                #pragma unroll
                for (int nt = 0; nt < 4; nt++)
                    mma_bf16(acc[mt][nt], al[mt], bh[nt]);   // lo*hi
            #pragma unroll
            for (int mt = 0; mt < 4; mt++)
                #pragma unroll
                for (int nt = 0; nt < 4; nt++)
                    mma_bf16(acc[mt][nt], ah[mt], bl[nt]);   // hi*lo
        }
        __syncthreads();
    }

    if (MODE == 3) {
        __shared__ float sred[128];
        if (tid < 128) sred[tid] = 0.f;
        __syncthreads();
        #pragma unroll
        for (int mt = 0; mt < 4; mt++) {
            int mloc = warp_m*64 + mt*16 + r;
            int m0 = bm + mloc;
            int b0 = m0 / KBsz;
            int b1 = (m0 + 8) / KBsz;
            float p0 = 0.f, p1 = 0.f;
            #pragma unroll
            for (int nt = 0; nt < 4; nt++) {
                int n0 = bn + warp_n*32 + nt*8 + 2*c;
                float v;
                v = eluf((acc[mt][nt][0] + bias[n0  ]) * colmul[(size_t)b0*cmStride + n0  ]); p0 += v*rvec[n0];
                v = eluf((acc[mt][nt][1] + bias[n0+1]) * colmul[(size_t)b0*cmStride + n0+1]); p0 += v*rvec[n0+1];
                v = eluf((acc[mt][nt][2] + bias[n0  ]) * colmul[(size_t)b1*cmStride + n0  ]); p1 += v*rvec[n0];
                v = eluf((acc[mt][nt][3] + bias[n0+1]) * colmul[(size_t)b1*cmStride + n0+1]); p1 += v*rvec[n0+1];
            }
            p0 += __shfl_xor_sync(0xffffffffu, p0, 1);
            p0 += __shfl_xor_sync(0xffffffffu, p0, 2);
            p1 += __shfl_xor_sync(0xffffffffu, p1, 1);
            p1 += __shfl_xor_sync(0xffffffffu, p1, 2);
            if (c == 0) { atomicAdd(&sred[mloc], p0); atomicAdd(&sred[mloc + 8], p1); }
        }
        __syncthreads();
        if (tid < 128) atomicAdd(&svec[bm + tid], sred[tid]);
        return;
    }

    #pragma unroll
    for (int mt = 0; mt < 4; mt++) {
        int m0 = bm + warp_m*64 + mt*16 + r;
        #pragma unroll
        for (int nt = 0; nt < 4; nt++) {
            int n0 = bn + warp_n*32 + nt*8 + 2*c;
            #pragma unroll
            for (int half = 0; half < 2; half++) {
                int mm = m0 + half*8;
                float vx = acc[mt][nt][2*half], vy = acc[mt][nt][2*half+1];
                if (MODE == 2) {
                    float2 ad = *(const float2*)(addmat + (size_t)mm*TGN + n0);
                    vx = eluf(vx + ad.x); vy = eluf(vy + ad.y);
                    bf16 hx, lx, hy, ly;
                    splitbf(vx, hx, lx); splitbf(vy, hy, ly);
                    *(__nv_bfloat162*)(Chi + (size_t)mm*TGN + n0) = __nv_bfloat162(hx, hy);
                    *(__nv_bfloat162*)(Clo + (size_t)mm*TGN + n0) = __nv_bfloat162(lx, ly);
                } else {
                    vx += bias[n0]; vy += bias[n0+1];
                    *(float2*)(Craw + (size_t)mm*TGN + n0) = make_float2(vx, vy);
                    if (MODE == 1) {
                        bf16 hx, lx, hy, ly;
                        splitbf(vx, hx, lx); splitbf(vy, hy, ly);
                        *(__nv_bfloat162*)(Chi + (size_t)mm*TGN + n0) = __nv_bfloat162(hx, hy);
                        *(__nv_bfloat162*)(Clo + (size_t)mm*TGN + n0) = __nv_bfloat162(lx, ly);
                    }
                }
            }
        }
    }
}

// ---------------- split kernels ----------------------------------------------
__global__ void splitbf_k(const float* __restrict__ src,
                          bf16* __restrict__ hi, bf16* __restrict__ lo, size_t n)
{
    size_t i = ((size_t)blockIdx.x * blockDim.x + threadIdx.x) * 4;
    if (i >= n) return;
    float4 v = *(const float4*)(src + i);
    bf16 h0,l0,h1,l1,h2,l2,h3,l3;
    splitbf(v.x,h0,l0); splitbf(v.y,h1,l1); splitbf(v.z,h2,l2); splitbf(v.w,h3,l3);
    *(__nv_bfloat162*)(hi + i)     = __nv_bfloat162(h0, h1);
    *(__nv_bfloat162*)(hi + i + 2) = __nv_bfloat162(h2, h3);
    *(__nv_bfloat162*)(lo + i)     = __nv_bfloat162(l0, l1);
    *(__nv_bfloat162*)(lo + i + 2) = __nv_bfloat162(l2, l3);
}

__global__ void scale_split_k(const float* __restrict__ kp,
                              const float* __restrict__ mp,
                              bf16* __restrict__ hi, bf16* __restrict__ lo)
{
    size_t i = ((size_t)blockIdx.x * blockDim.x + threadIdx.x) * 4;
    if (i >= (size_t)MKB * Dd) return;
    int m = (int)(i >> 9);
    int d = (int)(i & 511);
    int b = m / KBsz;
    float4 v = *(const float4*)(kp + i);
    float4 s = *(const float4*)(mp + (size_t)b * Dd + d);
    v.x *= s.x; v.y *= s.y; v.z *= s.z; v.w *= s.w;
    bf16 h0,l0,h1,l1,h2,l2,h3,l3;
    splitbf(v.x,h0,l0); splitbf(v.y,h1,l1); splitbf(v.z,h2,l2); splitbf(v.w,h3,l3);
    *(__nv_bfloat162*)(hi + i)     = __nv_bfloat162(h0, h1);
    *(__nv_bfloat162*)(hi + i + 2) = __nv_bfloat162(h2, h3);
    *(__nv_bfloat162*)(lo + i)     = __nv_bfloat162(l0, l1);
    *(__nv_bfloat162*)(lo + i + 2) = __nv_bfloat162(l2, l3);
}

// =====================  small FFMA2 GEMM (M=640 ops)  ========================
__device__ __forceinline__ unsigned long long pack2(float lo, float hi) {
    unsigned long long r;
    asm("mov.b64 %0, {%1, %2};" : "=l"(r) : "f"(lo), "f"(hi));
    return r;
}
__device__ __forceinline__ void unpack2(unsigned long long v, float& lo, float& hi) {
    asm("mov.b64 {%0, %1}, %2;" : "=f"(lo), "=f"(hi) : "l"(v));
}
__device__ __forceinline__ void fma2(unsigned long long& d,
                                     unsigned long long a, unsigned long long b) {
    asm("fma.rn.f32x2 %0, %1, %2, %0;" : "+l"(d) : "l"(a), "l"(b));
}

#define BM 128
#define BN 128
#define BKK 16

template<int MODE>
__global__ __launch_bounds__(256, 2)
void sgemm_k(const float* __restrict__ A, int lda,
             const float* __restrict__ A2, int lda2, int splitK,
             const float* __restrict__ W,
             const float* __restrict__ bias,
             float* __restrict__ C,
             int M, int K, int N)
{
    __shared__ float As[BKK][BM];
    __shared__ float Bs[BKK][BN];

    const int bm = blockIdx.y * BM;
    const int bn = blockIdx.x * BN;
    const int tid = threadIdx.x;
    const int ty = tid >> 4;
    const int tx = tid & 15;

    unsigned long long acc2[8][4];
    #pragma unroll
    for (int i = 0; i < 8; i++)
        #pragma unroll
        for (int j = 0; j < 4; j++) acc2[i][j] = 0ull;

    for (int k0 = 0; k0 < K; k0 += BKK) {
        #pragma unroll
        for (int e2 = 0; e2 < 2; e2++) {
            int e   = tid * 2 + e2;
            int row = e >> 2;
            int kq  = (e & 3) * 4;
            int m   = bm + row;
            int k   = k0 + kq;
            const float* src = (k < splitK)
                ? (A  + (size_t)m * lda  + k)
                : (A2 + (size_t)m * lda2 + (k - splitK));
            float4 v = *(const float4*)src;
            As[kq + 0][row] = v.x; As[kq + 1][row] = v.y;
            As[kq + 2][row] = v.z; As[kq + 3][row] = v.w;
        }
        #pragma unroll
        for (int e2 = 0; e2 < 2; e2++) {
            int e   = tid * 2 + e2;
            int row = e >> 5;
            int cc  = (e & 31) * 4;
            float4 v = *(const float4*)(W + (size_t)(k0 + row) * N + bn + cc);
            *(float4*)&Bs[row][cc] = v;
        }
        __syncthreads();
        #pragma unroll
        for (int kk = 0; kk < BKK; kk++) {
            float a[8];
            unsigned long long b2[4];
            #pragma unroll
            for (int i = 0; i < 8; i++) a[i] = As[kk][ty * 8 + i];
            #pragma unroll
            for (int j = 0; j < 4; j++)
                b2[j] = *(const unsigned long long*)&Bs[kk][tx * 8 + j * 2];
            #pragma unroll
            for (int i = 0; i < 8; i++) {
                unsigned long long pa = pack2(a[i], a[i]);
                #pragma unroll
                for (int j = 0; j < 4; j++)
                    fma2(acc2[i][j], pa, b2[j]);
            }
        }
        __syncthreads();
    }

    float acc[8][8];
    #pragma unroll
    for (int i = 0; i < 8; i++)
        #pragma unroll
        for (int j = 0; j < 4; j++)
            unpack2(acc2[i][j], acc[i][2*j], acc[i][2*j+1]);

    #pragma unroll
    for (int i = 0; i < 8; i++) {
        int m = bm + ty * 8 + i;
        #pragma unroll
        for (int j = 0; j < 8; j += 4) {
            int n = bn + tx * 8 + j;
            float4 v;
            v.x = acc[i][j] + bias[n];     v.y = acc[i][j+1] + bias[n+1];
            v.z = acc[i][j+2] + bias[n+2]; v.w = acc[i][j+3] + bias[n+3];
            if (MODE == 1) { v.x = tanhf(v.x); v.y = tanhf(v.y); v.z = tanhf(v.z); v.w = tanhf(v.w); }
            *(float4*)(C + (size_t)m * N + n) = v;
        }
    }
}

// ---------------- attention / misc kernels (validated) -----------------------
__global__ void word_attn_k(const float* __restrict__ qall,
                            const float* __restrict__ qword,
                            const float* __restrict__ caw,
                            float* __restrict__ ch)
{
    int b = blockIdx.x, s = blockIdx.y;
    __shared__ float qs[Dd];
    __shared__ float lg[Ll];
    int tid = threadIdx.x;
    for (int d = tid; d < Dd; d += 256)
        qs[d] = qall[((size_t)s * Bsz + b) * Dd + d] * caw[d];
    __syncthreads();
    int wid = tid >> 5, lane = tid & 31;
    for (int l = wid; l < Ll; l += 8) {
        const float* qw = qword + ((size_t)b * Ll + l) * Dd;
        float a = 0.f;
        for (int d = lane; d < Dd; d += 32) a += qs[d] * qw[d];
        #pragma unroll
        for (int o = 16; o; o >>= 1) a += __shfl_xor_sync(0xffffffffu, a, o);
        if (lane == 0) lg[l] = a;
    }
    __syncthreads();
    if (tid == 0) {
        float mx = -INFINITY;
        for (int l = 0; l < Ll; l++) mx = fmaxf(mx, lg[l]);
        float sm = 0.f;
        for (int l = 0; l < Ll; l++) { float e = expf(lg[l] - mx); lg[l] = e; sm += e; }
        float inv = 1.f / sm;
        for (int l = 0; l < Ll; l++) lg[l] *= inv;
    }
    __syncthreads();
    for (int d = tid; d < Dd; d += 256) {
        float a = 0.f;
        for (int l = 0; l < Ll; l++) a += lg[l] * qword[((size_t)b * Ll + l) * Dd + d];
        ch[((size_t)b * Ss + s) * Dd + d] = a;
    }
}

__global__ void norm_k(const float* __restrict__ chkey, float* __restrict__ normed)
{
    int i = blockIdx.x * blockDim.x + threadIdx.x;
    if (i >= Bsz * Dd) return;
    int b = i >> 9, d = i & 511;
    size_t base = (size_t)b * Ss * Dd + d;
    float ss = 0.f;
    #pragma unroll
    for (int s = 0; s < Ss; s++) { float v = chkey[base + s * Dd]; ss += v * v; }
    float inv = 1.f / sqrtf(ss);
    #pragma unroll
    for (int s = 0; s < Ss; s++) normed[base + s * Dd] = chkey[base + s * Dd] * inv;
}

__global__ void gram_k(const float* __restrict__ normed, float* __restrict__ Amat)
{
    int tb = blockIdx.x, i = blockIdx.y;
    __shared__ float Ki[Dd];
    __shared__ float lg[TS];
    int tid = threadIdx.x;
    int ti = i / Ss, si = i % Ss;
    size_t rowi = ((size_t)(ti * TBsz + tb) * Ss + si) * Dd;
    for (int d = tid; d < Dd; d += 256) Ki[d] = normed[rowi + d];
    __syncthreads();
    int wid = tid >> 5, lane = tid & 31;
    for (int j = wid; j < TS; j += 8) {
        float a;
        if (j > i) a = -1e30f;
        else {
            int tj = j / Ss, sj = j % Ss;
            size_t rowj = ((size_t)(tj * TBsz + tb) * Ss + sj) * Dd;
            a = 0.f;
            for (int d = lane; d < Dd; d += 32) a += Ki[d] * normed[rowj + d];
            #pragma unroll
            for (int o = 16; o; o >>= 1) a += __shfl_xor_sync(0xffffffffu, a, o);
        }
        if (lane == 0) lg[j] = a;
    }
    __syncthreads();
    if (tid == 0) {
        float mx = -INFINITY;
        for (int j = 0; j < TS; j++) mx = fmaxf(mx, lg[j]);
        float sm = 0.f;
        for (int j = 0; j < TS; j++) { float e = expf(lg[j] - mx); lg[j] = e; sm += e; }
        float inv = 1.f / sm;
        for (int j = 0; j < TS; j++) lg[j] *= inv;
    }
    __syncthreads();
    if (tid < TS) Amat[((size_t)tb * TS + i) * TS + tid] = lg[tid];
}

__global__ void attv_k(const float* __restrict__ Amat,
                       const float* __restrict__ chval,
                       float* __restrict__ att)
{
    int tb = blockIdx.x, i = blockIdx.y;
    __shared__ float aw[TS];
    int tid = threadIdx.x;
    if (tid < TS) aw[tid] = Amat[((size_t)tb * TS + i) * TS + tid];
    __syncthreads();
    int ti = i / Ss, si = i % Ss;
    for (int d = tid; d < Dd; d += 256) {
        float a = 0.f;
        for (int j = 0; j <= i; j++) {
            int tj = j / Ss, sj = j % Ss;
            a += aw[j] * chval[((size_t)(tj * TBsz + tb) * Ss + sj) * Dd + d];
        }
        att[((size_t)(ti * TBsz + tb) * Ss + si) * Dd + d] = a;
    }
}

__global__ void bcast_k(const float* __restrict__ src, float* __restrict__ dst)
{
    int i = blockIdx.x * blockDim.x + threadIdx.x;
    if (i < Bsz * Dd) dst[i] = src[i & 511];
}

__global__ void zero_k(float* __restrict__ p, int n)
{
    int i = blockIdx.x * blockDim.x + threadIdx.x;
    if (i < n) p[i] = 0.f;
}

__global__ void read_k(const float* __restrict__ s,
                       const float* __restrict__ knowledge,
                       float* __restrict__ readv)
{
    int b = blockIdx.x;
    __shared__ float sv[KBsz];
    int tid = threadIdx.x;
    if (tid < KBsz) sv[tid] = s[(size_t)b * KBsz + tid];
    __syncthreads();
    if (tid == 0) {
        float mx = -INFINITY;
        for (int k = 0; k < KBsz; k++) mx = fmaxf(mx, sv[k]);
        float sm = 0.f;
        for (int k = 0; k < KBsz; k++) { float e = expf(sv[k] - mx); sv[k] = e; sm += e; }
        float inv = 1.f / sm;
        for (int k = 0; k < KBsz; k++) sv[k] *= inv;
    }
    __syncthreads();
    for (int d = tid; d < Dd; d += 256) {
        float a = 0.f;
        for (int k = 0; k < KBsz; k++)
            a += sv[k] * knowledge[((size_t)b * KBsz + k) * Dd + d];
        readv[(size_t)b * Dd + d] = a;
    }
}

__global__ void out_k(const float* __restrict__ mem,
                      const float* __restrict__ att,
                      float* __restrict__ out, int out_size)
{
    int i = blockIdx.x * blockDim.x + threadIdx.x;
    const int BD = Bsz * Dd;
    if (i >= BD) return;
    if (i < out_size) out[i] = mem[i];
    if (out_size >= 2 * BD) {
        int b = i >> 9, d = i & 511;
        out[BD + i] = att[((size_t)b * Ss + (Ss - 1)) * Dd + d];
    }
}

// ---------------- launch -----------------------------------------------------
static float* symf(const void* s) { void* p = nullptr; cudaGetSymbolAddress(&p, s); return (float*)p; }
static bf16*  symb(const void* s) { void* p = nullptr; cudaGetSymbolAddress(&p, s); return (bf16*)p; }

#define TG_SMEM (int)((NSTG*2*A_ST + NSTG*2*B_ST) * sizeof(bf16))

extern "C" void kernel_launch(void* const* d_in, const int* in_sizes, int n_in,
                              void* d_out, int out_size)
{
    const float* qword     = (const float*)d_in[0];
    const float* qemb      = (const float*)d_in[1];
    const float* knowledge = (const float*)d_in[2];
    const float* ci_w     = (const float*)d_in[4];
    const float* ci_b     = (const float*)d_in[5];
    const float* ciu_w    = (const float*)d_in[6];
    const float* ciu_b    = (const float*)d_in[7];
    const float* ca_w     = (const float*)d_in[8];
    const float* kproj_w  = (const float*)d_in[10];
    const float* kproj_b  = (const float*)d_in[11];
    const float* mproj_w  = (const float*)d_in[12];
    const float* mproj_b  = (const float*)d_in[13];
    const float* concat_w = (const float*)d_in[14];
    const float* concat_b = (const float*)d_in[15];
    const float* concat2_w= (const float*)d_in[16];
    const float* concat2_b= (const float*)d_in[17];
    const float* rattn_w  = (const float*)d_in[18];
    const float* write_w  = (const float*)d_in[20];
    const float* write_b  = (const float*)d_in[21];
    const float* init_mem = (const float*)d_in[22];
    const float* kq_w     = (const float*)d_in[23];
    const float* kq_b     = (const float*)d_in[24];
    const float* val_w    = (const float*)d_in[25];
    const float* val_b    = (const float*)d_in[26];
    float* out = (float*)d_out;

    float* q0    = symf(g_q0);
    float* qall  = symf(g_qall);
    float* ch    = symf(g_ch);
    float* chkey = symf(g_chkey);
    float* chval = symf(g_chval);
    float* normed= symf(g_normed);
    float* Amat  = symf(g_Amat);
    float* att   = symf(g_att);
    float* kp    = symf(g_kp);
    float* kp2   = symf(g_kp2);
    bf16*  kph   = symb(g_kph);
    bf16*  kpl   = symb(g_kpl);
    bf16*  e1h   = symb(g_e1h);
    bf16*  e1l   = symb(g_e1l);
    bf16*  ahb   = symb(g_ah);
    bf16*  alb   = symb(g_al);
    bf16*  knh   = symb(g_knh);
    bf16*  knl   = symb(g_knl);
    bf16*  wbh   = symb(g_wbh);
    bf16*  wbl   = symb(g_wbl);
    float* mp    = symf(g_mp);
    float* sbuf  = symf(g_s);
    float* readv = symf(g_read);
    float* mem0  = symf(g_mem0);
    float* mem1  = symf(g_mem1);

    static bool attr_done = false;
    if (!attr_done) {
        cudaFuncSetAttribute(tgemm_k<0>, cudaFuncAttributeMaxDynamicSharedMemorySize, TG_SMEM);
        cudaFuncSetAttribute(tgemm_k<1>, cudaFuncAttributeMaxDynamicSharedMemorySize, TG_SMEM);
        cudaFuncSetAttribute(tgemm_k<2>, cudaFuncAttributeMaxDynamicSharedMemorySize, TG_SMEM);
        cudaFuncSetAttribute(tgemm_k<3>, cudaFuncAttributeMaxDynamicSharedMemorySize, TG_SMEM);
        attr_done = true;
    }

    auto Gs = [](int M, int N) { return dim3(N / BN, M / BM); };
    const dim3 GT(TGN / 128, MKB / 128);   // (4, 980)
    const float* NPF = nullptr;
    bf16* NPB = nullptr;

    // --- question path (small, FFMA2) ---
    sgemm_k<1><<<Gs(Bsz, Dd), 256>>>(qemb, Dd, qemb, Dd, Dd, ci_w, ci_b, q0, Bsz, Dd, Dd);
    for (int s = 0; s < Ss; s++)
        sgemm_k<0><<<Gs(Bsz, Dd), 256>>>(q0, Dd, q0, Dd, Dd,
                                         ciu_w + (size_t)s * Dd * Dd, ciu_b + s * Dd,
                                         qall + (size_t)s * Bsz * Dd, Bsz, Dd, Dd);
    word_attn_k<<<dim3(Bsz, Ss), 256>>>(qall, qword, ca_w, ch);
    sgemm_k<0><<<Gs(Bsz * Ss, Dd), 256>>>(ch, Dd, ch, Dd, Dd, kq_w, kq_b, chkey, Bsz * Ss, Dd, Dd);
    sgemm_k<0><<<Gs(Bsz * Ss, Dd), 256>>>(ch, Dd, ch, Dd, Dd, val_w, val_b, chval, Bsz * Ss, Dd, Dd);
    norm_k<<<(Bsz * Dd + 255) / 256, 256>>>(chkey, normed);
    gram_k<<<dim3(TBsz, TS), 256>>>(normed, Amat);
    attv_k<<<dim3(TBsz, TS), 256>>>(Amat, chval, att);

    // --- pre-splits (bf16) ---
    {
        size_t nk = (size_t)MKB * Dd;
        splitbf_k<<<(unsigned)((nk / 4 + 255) / 256), 256>>>(knowledge, knh, knl, nk);
        size_t nw = (size_t)Dd * Dd;
        splitbf_k<<<(unsigned)((nw / 4 + 255) / 256), 256>>>(kproj_w,  wbh + 0*Dd*Dd, wbl + 0*Dd*Dd, nw);
        splitbf_k<<<(unsigned)((nw / 4 + 255) / 256), 256>>>(concat_w, wbh + 1*Dd*Dd, wbl + 1*Dd*Dd, nw);
        splitbf_k<<<(unsigned)((nw / 4 + 255) / 256), 256>>>(concat_w + (size_t)Dd*Dd,
                                                             wbh + 2*Dd*Dd, wbl + 2*Dd*Dd, nw);
        splitbf_k<<<(unsigned)((nw / 4 + 255) / 256), 256>>>(concat2_w, wbh + 3*Dd*Dd, wbl + 3*Dd*Dd, nw);
    }

    // --- knowledge path precompute (bf16 tensor cores) ---
    tgemm_k<1><<<GT, 256, TG_SMEM>>>(knh, knl, wbh + 0*Dd*Dd, wbl + 0*Dd*Dd,
                                     kproj_b, kp, kph, kpl, NPF, NPF, 0, NPF, nullptr);
    tgemm_k<0><<<GT, 256, TG_SMEM>>>(kph, kpl, wbh + 2*Dd*Dd, wbl + 2*Dd*Dd,
                                     concat_b, kp2, NPB, NPB, NPF, NPF, 0, NPF, nullptr);

    bcast_k<<<(Bsz * Dd + 255) / 256, 256>>>(init_mem, mem0);

    float* mcur = mem0;
    float* mnext = mem1;
    for (int i = 0; i < Ss; i++) {
        sgemm_k<0><<<Gs(Bsz, Dd), 256>>>(mcur, Dd, mcur, Dd, Dd, mproj_w, mproj_b, mp, Bsz, Dd, Dd);
        {
            size_t nk = (size_t)MKB * Dd;
            scale_split_k<<<(unsigned)((nk / 4 + 255) / 256), 256>>>(kp, mp, ahb, alb);
        }
        tgemm_k<2><<<GT, 256, TG_SMEM>>>(ahb, alb, wbh + 1*Dd*Dd, wbl + 1*Dd*Dd,
                                         NPF, nullptr, e1h, e1l, kp2, NPF, 0, NPF, nullptr);
        zero_k<<<(MKB + 255) / 256, 256>>>(sbuf, MKB);
        tgemm_k<3><<<GT, 256, TG_SMEM>>>(e1h, e1l, wbh + 3*Dd*Dd, wbl + 3*Dd*Dd,
                                         concat2_b, nullptr, NPB, NPB,
                                         NPF, att + (size_t)i * Dd, Ss * Dd, rattn_w, sbuf);
        read_k<<<Bsz, 256>>>(sbuf, knowledge, readv);
        sgemm_k<0><<<Gs(Bsz, Dd), 256>>>(mcur, Dd, readv, Dd, Dd, write_w, write_b, mnext,
                                         Bsz, 2 * Dd, Dd);
        float* t = mcur; mcur = mnext; mnext = t;
    }

    out_k<<<(Bsz * Dd + 255) / 256, 256>>>(mcur, att, out, out_size);
}

// round 6
// speedup vs baseline: 2.7251x; 1.2676x over previous
#include <cuda_runtime.h>
#include <cuda_bf16.h>
#include <math.h>

// Problem constants
#define Bsz 640
#define Dd 512
#define Ss 4
#define Tt 10
#define TBsz 64
#define Ll 30
#define KBsz 196
#define MKB (Bsz*KBsz)   // 125440
#define TS 40            // T*S

typedef __nv_bfloat16 bf16;

// ---------------- scratch (static device globals; no allocations) ----------
__device__ float g_q0[Bsz*Dd];
__device__ float g_qall[Ss*Bsz*Dd];
__device__ float g_ch[Bsz*Ss*Dd];
__device__ float g_chkey[Bsz*Ss*Dd];
__device__ float g_chval[Bsz*Ss*Dd];
__device__ float g_normed[Bsz*Ss*Dd];
__device__ float g_Amat[TBsz*TS*TS];
__device__ float g_att[Bsz*Ss*Dd];
__device__ float g_kp [(size_t)MKB*Dd];      // know_proj raw fp32
__device__ float g_kp2[(size_t)MKB*Dd];      // kp @ concat_w[D:] + concat_b (fp32)
__device__ bf16  g_kph[(size_t)MKB*Dd];      // kp split hi/lo
__device__ bf16  g_kpl[(size_t)MKB*Dd];
__device__ bf16  g_e1h[(size_t)MKB*Dd];
__device__ bf16  g_e1l[(size_t)MKB*Dd];
__device__ bf16  g_ah [(size_t)MKB*Dd];      // (kp*mp) split
__device__ bf16  g_al [(size_t)MKB*Dd];
__device__ bf16  g_knh[(size_t)MKB*Dd];      // knowledge split
__device__ bf16  g_knl[(size_t)MKB*Dd];
__device__ bf16  g_wbh[4][Dd*Dd];            // weight splits hi
__device__ bf16  g_wbl[4][Dd*Dd];            // weight splits lo
__device__ float g_mp[Bsz*Dd];
__device__ float g_s[MKB];
__device__ float g_read[Bsz*Dd];
__device__ float g_mem0[Bsz*Dd];
__device__ float g_mem1[Bsz*Dd];

__device__ __forceinline__ float eluf(float x){ return x > 0.f ? x : expm1f(x); }

__device__ __forceinline__ void splitbf(float x, bf16& h, bf16& l){
    h = __float2bfloat16_rn(x);
    l = __float2bfloat16_rn(x - __bfloat162float(h));
}

__device__ __forceinline__ void mma_bf16(float* cc, const unsigned* a, const unsigned* b){
    asm("mma.sync.aligned.m16n8k16.row.col.f32.bf16.bf16.f32 "
        "{%0,%1,%2,%3}, {%4,%5,%6,%7}, {%8,%9}, {%0,%1,%2,%3};"
        : "+f"(cc[0]), "+f"(cc[1]), "+f"(cc[2]), "+f"(cc[3])
        : "r"(a[0]), "r"(a[1]), "r"(a[2]), "r"(a[3]), "r"(b[0]), "r"(b[1]));
}
__device__ __forceinline__ void ldm4(unsigned* r, const bf16* p){
    unsigned addr = (unsigned)__cvta_generic_to_shared(p);
    asm volatile("ldmatrix.sync.aligned.m8n8.x4.shared.b16 {%0,%1,%2,%3}, [%4];"
                 : "=r"(r[0]), "=r"(r[1]), "=r"(r[2]), "=r"(r[3]) : "r"(addr));
}
__device__ __forceinline__ void ldm4t(unsigned* r, const bf16* p){
    unsigned addr = (unsigned)__cvta_generic_to_shared(p);
    asm volatile("ldmatrix.sync.aligned.m8n8.x4.trans.shared.b16 {%0,%1,%2,%3}, [%4];"
                 : "=r"(r[0]), "=r"(r[1]), "=r"(r[2]), "=r"(r[3]) : "r"(addr));
}
__device__ __forceinline__ void cpa16(void* sdst, const void* gsrc){
    unsigned s = (unsigned)__cvta_generic_to_shared(sdst);
    asm volatile("cp.async.cg.shared.global [%0], [%1], 16;" :: "r"(s), "l"(gsrc));
}
__device__ __forceinline__ void cpa_commit(){ asm volatile("cp.async.commit_group;"); }

// =============  big tensor-core GEMM: split-bf16 3-pass, ldmatrix  ===========
// 2-stage cp.async pipeline, 2 CTAs/SM (75.8KB smem, regs capped at 128).
// MODE 0: Craw = acc + bias
// MODE 1: Craw = acc + bias ; Chi/Clo = splitbf(Craw)
// MODE 2: t = elu(acc + addmat); Chi/Clo = splitbf(t)
// MODE 3: svec[m] += sum_n elu((acc+bias[n])*colmul[(m/KB)*cmStride+n])*rvec[n]
#define TGK 512
#define TGN 512
#define TBK 32            // bf16 K per tile
#define NKIT (TGK/TBK)    // 16
#define NSTG 2
#define ALD 40            // A smem row stride (bf16): 80B -> conflict-free
#define BLD 136           // B smem row stride (bf16): 272B -> conflict-free
#define A_ST (128*ALD)
#define B_ST (TBK*BLD)

template<int MODE>
__global__ __launch_bounds__(256, 2)
void tgemm_k(const bf16* __restrict__ Ahg, const bf16* __restrict__ Alg,
             const bf16* __restrict__ Bhg, const bf16* __restrict__ Blg,
             const float* __restrict__ bias,
             float* __restrict__ Craw, bf16* __restrict__ Chi, bf16* __restrict__ Clo,
             const float* __restrict__ addmat,
             const float* __restrict__ colmul, int cmStride,
             const float* __restrict__ rvec, float* __restrict__ svec)
{
    extern __shared__ bf16 smem[];
    bf16* Abase = smem;                    // [NSTG][2][128][ALD]
    bf16* Bbase = smem + NSTG*2*A_ST;      // [NSTG][2][TBK][BLD]

    const int bm = blockIdx.y * 128;
    const int bn = blockIdx.x * 128;
    const int tid = threadIdx.x;
    const int wid = tid >> 5, lane = tid & 31;
    const int warp_m = wid & 1;            // 64 rows each
    const int warp_n = wid >> 1;           // 32 cols each
    const int r = lane >> 2, c = lane & 3;
    const int lrow = lane & 15, lcol = (lane >> 4) * 8;

    float acc[4][4][4];
    #pragma unroll
    for (int i = 0; i < 4; i++)
        #pragma unroll
        for (int j = 0; j < 4; j++)
            #pragma unroll
            for (int q = 0; q < 4; q++) acc[i][j][q] = 0.f;

    auto do_copy = [&](int k0, int st){
        const bf16* Ag[2] = { Ahg, Alg };
        const bf16* Bg[2] = { Bhg, Blg };
        #pragma unroll
        for (int h = 0; h < 2; h++) {
            bf16* As = Abase + (st*2 + h) * A_ST;
            bf16* Bs = Bbase + (st*2 + h) * B_ST;
            #pragma unroll
            for (int e2 = 0; e2 < 2; e2++) {
                int e   = tid * 2 + e2;        // 0..511
                int row = e >> 2;              // 0..127
                int seg = (e & 3) * 8;
                cpa16(As + row * ALD + seg,
                      Ag[h] + (size_t)(bm + row) * TGK + k0 * TBK + seg);
            }
            #pragma unroll
            for (int e2 = 0; e2 < 2; e2++) {
                int e   = tid * 2 + e2;        // 0..511
                int row = e >> 4;              // 0..31
                int seg = (e & 15) * 8;        // 0..120
                cpa16(Bs + row * BLD + seg,
                      Bg[h] + (size_t)(k0 * TBK + row) * TGN + bn + seg);
            }
        }
        cpa_commit();
    };

    do_copy(0, 0);

    for (int k0 = 0; k0 < NKIT; k0++) {
        int st = k0 & 1;
        if (k0 + 1 < NKIT) {
            do_copy(k0 + 1, st ^ 1);
            asm volatile("cp.async.wait_group 1;" ::: "memory");
        } else {
            asm volatile("cp.async.wait_group 0;" ::: "memory");
        }
        __syncthreads();

        const bf16* Ash = Abase + (st*2 + 0) * A_ST;
        const bf16* Asl = Abase + (st*2 + 1) * A_ST;
        const bf16* Bsh = Bbase + (st*2 + 0) * B_ST;
        const bf16* Bsl = Bbase + (st*2 + 1) * B_ST;

        #pragma unroll
        for (int ks = 0; ks < 2; ks++) {       // two k16 steps per tile
            unsigned ah[4][4], al[4][4], bh[4][2], bl[4][2];
            #pragma unroll
            for (int mt = 0; mt < 4; mt++) {
                int row = warp_m * 64 + mt * 16 + lrow;
                ldm4(ah[mt], Ash + row * ALD + ks * 16 + lcol);
                ldm4(al[mt], Asl + row * ALD + ks * 16 + lcol);
            }
            #pragma unroll
            for (int p = 0; p < 2; p++) {      // each covers two n8 tiles
                unsigned t[4];
                int rr = ks * 16 + lrow;
                int ccol = warp_n * 32 + p * 16 + lcol;
                ldm4t(t, Bsh + rr * BLD + ccol);
                bh[2*p][0] = t[0]; bh[2*p][1] = t[1];
                bh[2*p+1][0] = t[2]; bh[2*p+1][1] = t[3];
                ldm4t(t, Bsl + rr * BLD + ccol);
                bl[2*p][0] = t[0]; bl[2*p][1] = t[1];
                bl[2*p+1][0] = t[2]; bl[2*p+1][1] = t[3];
            }
            #pragma unroll
            for (int mt = 0; mt < 4; mt++)
                #pragma unroll
                for (int nt = 0; nt < 4; nt++)
                    mma_bf16(acc[mt][nt], ah[mt], bh[nt]);   // hi*hi
            #pragma unroll
            for (int mt = 0; mt < 4; mt++)
                #pragma unroll
                for (int nt = 0; nt < 4; nt++)
                    mma_bf16(acc[mt][nt], al[mt], bh[nt]);   // lo*hi
            #pragma unroll
            for (int mt = 0; mt < 4; mt++)
                #pragma unroll
                for (int nt = 0; nt < 4; nt++)
                    mma_bf16(acc[mt][nt], ah[mt], bl[nt]);   // hi*lo
        }
        __syncthreads();
    }

    if (MODE == 3) {
        __shared__ float sred[128];
        if (tid < 128) sred[tid] = 0.f;
        __syncthreads();
        #pragma unroll
        for (int mt = 0; mt < 4; mt++) {
            int mloc = warp_m*64 + mt*16 + r;
            int m0 = bm + mloc;
            int b0 = m0 / KBsz;
            int b1 = (m0 + 8) / KBsz;
            float p0 = 0.f, p1 = 0.f;
            #pragma unroll
            for (int nt = 0; nt < 4; nt++) {
                int n0 = bn + warp_n*32 + nt*8 + 2*c;
                float v;
                v = eluf((acc[mt][nt][0] + bias[n0  ]) * colmul[(size_t)b0*cmStride + n0  ]); p0 += v*rvec[n0];
                v = eluf((acc[mt][nt][1] + bias[n0+1]) * colmul[(size_t)b0*cmStride + n0+1]); p0 += v*rvec[n0+1];
                v = eluf((acc[mt][nt][2] + bias[n0  ]) * colmul[(size_t)b1*cmStride + n0  ]); p1 += v*rvec[n0];
                v = eluf((acc[mt][nt][3] + bias[n0+1]) * colmul[(size_t)b1*cmStride + n0+1]); p1 += v*rvec[n0+1];
            }
            p0 += __shfl_xor_sync(0xffffffffu, p0, 1);
            p0 += __shfl_xor_sync(0xffffffffu, p0, 2);
            p1 += __shfl_xor_sync(0xffffffffu, p1, 1);
            p1 += __shfl_xor_sync(0xffffffffu, p1, 2);
            if (c == 0) { atomicAdd(&sred[mloc], p0); atomicAdd(&sred[mloc + 8], p1); }
        }
        __syncthreads();
        if (tid < 128) atomicAdd(&svec[bm + tid], sred[tid]);
        return;
    }

    #pragma unroll
    for (int mt = 0; mt < 4; mt++) {
        int m0 = bm + warp_m*64 + mt*16 + r;
        #pragma unroll
        for (int nt = 0; nt < 4; nt++) {
            int n0 = bn + warp_n*32 + nt*8 + 2*c;
            #pragma unroll
            for (int half = 0; half < 2; half++) {
                int mm = m0 + half*8;
                float vx = acc[mt][nt][2*half], vy = acc[mt][nt][2*half+1];
                if (MODE == 2) {
                    float2 ad = *(const float2*)(addmat + (size_t)mm*TGN + n0);
                    vx = eluf(vx + ad.x); vy = eluf(vy + ad.y);
                    bf16 hx, lx, hy, ly;
                    splitbf(vx, hx, lx); splitbf(vy, hy, ly);
                    *(__nv_bfloat162*)(Chi + (size_t)mm*TGN + n0) = __nv_bfloat162(hx, hy);
                    *(__nv_bfloat162*)(Clo + (size_t)mm*TGN + n0) = __nv_bfloat162(lx, ly);
                } else {
                    vx += bias[n0]; vy += bias[n0+1];
                    *(float2*)(Craw + (size_t)mm*TGN + n0) = make_float2(vx, vy);
                    if (MODE == 1) {
                        bf16 hx, lx, hy, ly;
                        splitbf(vx, hx, lx); splitbf(vy, hy, ly);
                        *(__nv_bfloat162*)(Chi + (size_t)mm*TGN + n0) = __nv_bfloat162(hx, hy);
                        *(__nv_bfloat162*)(Clo + (size_t)mm*TGN + n0) = __nv_bfloat162(lx, ly);
                    }
                }
            }
        }
    }
}

// ---------------- split kernels ----------------------------------------------
__global__ void splitbf_k(const float* __restrict__ src,
                          bf16* __restrict__ hi, bf16* __restrict__ lo, size_t n)
{
    size_t i = ((size_t)blockIdx.x * blockDim.x + threadIdx.x) * 4;
    if (i >= n) return;
    float4 v = *(const float4*)(src + i);
    bf16 h0,l0,h1,l1,h2,l2,h3,l3;
    splitbf(v.x,h0,l0); splitbf(v.y,h1,l1); splitbf(v.z,h2,l2); splitbf(v.w,h3,l3);
    *(__nv_bfloat162*)(hi + i)     = __nv_bfloat162(h0, h1);
    *(__nv_bfloat162*)(hi + i + 2) = __nv_bfloat162(h2, h3);
    *(__nv_bfloat162*)(lo + i)     = __nv_bfloat162(l0, l1);
    *(__nv_bfloat162*)(lo + i + 2) = __nv_bfloat162(l2, l3);
}

__global__ void scale_split_k(const float* __restrict__ kp,
                              const float* __restrict__ mp,
                              bf16* __restrict__ hi, bf16* __restrict__ lo)
{
    size_t i = ((size_t)blockIdx.x * blockDim.x + threadIdx.x) * 4;
    if (i >= (size_t)MKB * Dd) return;
    int m = (int)(i >> 9);
    int d = (int)(i & 511);
    int b = m / KBsz;
    float4 v = *(const float4*)(kp + i);
    float4 s = *(const float4*)(mp + (size_t)b * Dd + d);
    v.x *= s.x; v.y *= s.y; v.z *= s.z; v.w *= s.w;
    bf16 h0,l0,h1,l1,h2,l2,h3,l3;
    splitbf(v.x,h0,l0); splitbf(v.y,h1,l1); splitbf(v.z,h2,l2); splitbf(v.w,h3,l3);
    *(__nv_bfloat162*)(hi + i)     = __nv_bfloat162(h0, h1);
    *(__nv_bfloat162*)(hi + i + 2) = __nv_bfloat162(h2, h3);
    *(__nv_bfloat162*)(lo + i)     = __nv_bfloat162(l0, l1);
    *(__nv_bfloat162*)(lo + i + 2) = __nv_bfloat162(l2, l3);
}

// =====================  small FFMA2 GEMM (M=640 ops)  ========================
__device__ __forceinline__ unsigned long long pack2(float lo, float hi) {
    unsigned long long r;
    asm("mov.b64 %0, {%1, %2};" : "=l"(r) : "f"(lo), "f"(hi));
    return r;
}
__device__ __forceinline__ void unpack2(unsigned long long v, float& lo, float& hi) {
    asm("mov.b64 {%0, %1}, %2;" : "=f"(lo), "=f"(hi) : "l"(v));
}
__device__ __forceinline__ void fma2(unsigned long long& d,
                                     unsigned long long a, unsigned long long b) {
    asm("fma.rn.f32x2 %0, %1, %2, %0;" : "+l"(d) : "l"(a), "l"(b));
}

#define BM 128
#define BN 128
#define BKK 16

// z-batched: A += z*strideA, W += z*strideW, bias += z*strideBias, C += z*strideC
template<int MODE>
__global__ __launch_bounds__(256, 2)
void sgemm_k(const float* __restrict__ A, int lda,
             const float* __restrict__ A2, int lda2, int splitK,
             const float* __restrict__ W,
             const float* __restrict__ bias,
             float* __restrict__ C,
             int M, int K, int N,
             size_t strideA, size_t strideW, size_t strideBias, size_t strideC)
{
    A    += (size_t)blockIdx.z * strideA;
    A2   += (size_t)blockIdx.z * strideA;
    W    += (size_t)blockIdx.z * strideW;
    bias += (size_t)blockIdx.z * strideBias;
    C    += (size_t)blockIdx.z * strideC;

    __shared__ float As[BKK][BM];
    __shared__ float Bs[BKK][BN];

    const int bm = blockIdx.y * BM;
    const int bn = blockIdx.x * BN;
    const int tid = threadIdx.x;
    const int ty = tid >> 4;
    const int tx = tid & 15;

    unsigned long long acc2[8][4];
    #pragma unroll
    for (int i = 0; i < 8; i++)
        #pragma unroll
        for (int j = 0; j < 4; j++) acc2[i][j] = 0ull;

    for (int k0 = 0; k0 < K; k0 += BKK) {
        #pragma unroll
        for (int e2 = 0; e2 < 2; e2++) {
            int e   = tid * 2 + e2;
            int row = e >> 2;
            int kq  = (e & 3) * 4;
            int m   = bm + row;
            int k   = k0 + kq;
            const float* src = (k < splitK)
                ? (A  + (size_t)m * lda  + k)
                : (A2 + (size_t)m * lda2 + (k - splitK));
            float4 v = *(const float4*)src;
            As[kq + 0][row] = v.x; As[kq + 1][row] = v.y;
            As[kq + 2][row] = v.z; As[kq + 3][row] = v.w;
        }
        #pragma unroll
        for (int e2 = 0; e2 < 2; e2++) {
            int e   = tid * 2 + e2;
            int row = e >> 5;
            int cc  = (e & 31) * 4;
            float4 v = *(const float4*)(W + (size_t)(k0 + row) * N + bn + cc);
            *(float4*)&Bs[row][cc] = v;
        }
        __syncthreads();
        #pragma unroll
        for (int kk = 0; kk < BKK; kk++) {
            float a[8];
            unsigned long long b2[4];
            #pragma unroll
            for (int i = 0; i < 8; i++) a[i] = As[kk][ty * 8 + i];
            #pragma unroll
            for (int j = 0; j < 4; j++)
                b2[j] = *(const unsigned long long*)&Bs[kk][tx * 8 + j * 2];
            #pragma unroll
            for (int i = 0; i < 8; i++) {
                unsigned long long pa = pack2(a[i], a[i]);
                #pragma unroll
                for (int j = 0; j < 4; j++)
                    fma2(acc2[i][j], pa, b2[j]);
            }
        }
        __syncthreads();
    }

    float acc[8][8];
    #pragma unroll
    for (int i = 0; i < 8; i++)
        #pragma unroll
        for (int j = 0; j < 4; j++)
            unpack2(acc2[i][j], acc[i][2*j], acc[i][2*j+1]);

    #pragma unroll
    for (int i = 0; i < 8; i++) {
        int m = bm + ty * 8 + i;
        #pragma unroll
        for (int j = 0; j < 8; j += 4) {
            int n = bn + tx * 8 + j;
            float4 v;
            v.x = acc[i][j] + bias[n];     v.y = acc[i][j+1] + bias[n+1];
            v.z = acc[i][j+2] + bias[n+2]; v.w = acc[i][j+3] + bias[n+3];
            if (MODE == 1) { v.x = tanhf(v.x); v.y = tanhf(v.y); v.z = tanhf(v.z); v.w = tanhf(v.w); }
            *(float4*)(C + (size_t)m * N + n) = v;
        }
    }
}

// ---------------- attention / misc kernels (validated) -----------------------
__global__ void word_attn_k(const float* __restrict__ qall,
                            const float* __restrict__ qword,
                            const float* __restrict__ caw,
                            float* __restrict__ ch)
{
    int b = blockIdx.x, s = blockIdx.y;
    __shared__ float qs[Dd];
    __shared__ float lg[Ll];
    int tid = threadIdx.x;
    for (int d = tid; d < Dd; d += 256)
        qs[d] = qall[((size_t)s * Bsz + b) * Dd + d] * caw[d];
    __syncthreads();
    int wid = tid >> 5, lane = tid & 31;
    for (int l = wid; l < Ll; l += 8) {
        const float* qw = qword + ((size_t)b * Ll + l) * Dd;
        float a = 0.f;
        for (int d = lane; d < Dd; d += 32) a += qs[d] * qw[d];
        #pragma unroll
        for (int o = 16; o; o >>= 1) a += __shfl_xor_sync(0xffffffffu, a, o);
        if (lane == 0) lg[l] = a;
    }
    __syncthreads();
    if (tid == 0) {
        float mx = -INFINITY;
        for (int l = 0; l < Ll; l++) mx = fmaxf(mx, lg[l]);
        float sm = 0.f;
        for (int l = 0; l < Ll; l++) { float e = expf(lg[l] - mx); lg[l] = e; sm += e; }
        float inv = 1.f / sm;
        for (int l = 0; l < Ll; l++) lg[l] *= inv;
    }
    __syncthreads();
    for (int d = tid; d < Dd; d += 256) {
        float a = 0.f;
        for (int l = 0; l < Ll; l++) a += lg[l] * qword[((size_t)b * Ll + l) * Dd + d];
        ch[((size_t)b * Ss + s) * Dd + d] = a;
    }
}

__global__ void norm_k(const float* __restrict__ chkey, float* __restrict__ normed)
{
    int i = blockIdx.x * blockDim.x + threadIdx.x;
    if (i >= Bsz * Dd) return;
    int b = i >> 9, d = i & 511;
    size_t base = (size_t)b * Ss * Dd + d;
    float ss = 0.f;
    #pragma unroll
    for (int s = 0; s < Ss; s++) { float v = chkey[base + s * Dd]; ss += v * v; }
    float inv = 1.f / sqrtf(ss);
    #pragma unroll
    for (int s = 0; s < Ss; s++) normed[base + s * Dd] = chkey[base + s * Dd] * inv;
}

__global__ void gram_k(const float* __restrict__ normed, float* __restrict__ Amat)
{
    int tb = blockIdx.x, i = blockIdx.y;
    __shared__ float Ki[Dd];
    __shared__ float lg[TS];
    int tid = threadIdx.x;
    int ti = i / Ss, si = i % Ss;
    size_t rowi = ((size_t)(ti * TBsz + tb) * Ss + si) * Dd;
    for (int d = tid; d < Dd; d += 256) Ki[d] = normed[rowi + d];
    __syncthreads();
    int wid = tid >> 5, lane = tid & 31;
    for (int j = wid; j < TS; j += 8) {
        float a;
        if (j > i) a = -1e30f;
        else {
            int tj = j / Ss, sj = j % Ss;
            size_t rowj = ((size_t)(tj * TBsz + tb) * Ss + sj) * Dd;
            a = 0.f;
            for (int d = lane; d < Dd; d += 32) a += Ki[d] * normed[rowj + d];
            #pragma unroll
            for (int o = 16; o; o >>= 1) a += __shfl_xor_sync(0xffffffffu, a, o);
        }
        if (lane == 0) lg[j] = a;
    }
    __syncthreads();
    if (tid == 0) {
        float mx = -INFINITY;
        for (int j = 0; j < TS; j++) mx = fmaxf(mx, lg[j]);
        float sm = 0.f;
        for (int j = 0; j < TS; j++) { float e = expf(lg[j] - mx); lg[j] = e; sm += e; }
        float inv = 1.f / sm;
        for (int j = 0; j < TS; j++) lg[j] *= inv;
    }
    __syncthreads();
    if (tid < TS) Amat[((size_t)tb * TS + i) * TS + tid] = lg[tid];
}

__global__ void attv_k(const float* __restrict__ Amat,
                       const float* __restrict__ chval,
                       float* __restrict__ att)
{
    int tb = blockIdx.x, i = blockIdx.y;
    __shared__ float aw[TS];
    int tid = threadIdx.x;
    if (tid < TS) aw[tid] = Amat[((size_t)tb * TS + i) * TS + tid];
    __syncthreads();
    int ti = i / Ss, si = i % Ss;
    for (int d = tid; d < Dd; d += 256) {
        float a = 0.f;
        for (int j = 0; j <= i; j++) {
            int tj = j / Ss, sj = j % Ss;
            a += aw[j] * chval[((size_t)(tj * TBsz + tb) * Ss + sj) * Dd + d];
        }
        att[((size_t)(ti * TBsz + tb) * Ss + si) * Dd + d] = a;
    }
}

__global__ void bcast_k(const float* __restrict__ src, float* __restrict__ dst)
{
    int i = blockIdx.x * blockDim.x + threadIdx.x;
    if (i < Bsz * Dd) dst[i] = src[i & 511];
}

__global__ void zero_k(float* __restrict__ p, int n)
{
    int i = blockIdx.x * blockDim.x + threadIdx.x;
    if (i < n) p[i] = 0.f;
}

__global__ void read_k(const float* __restrict__ s,
                       const float* __restrict__ knowledge,
                       float* __restrict__ readv)
{
    int b = blockIdx.x;
    __shared__ float sv[KBsz];
    int tid = threadIdx.x;
    if (tid < KBsz) sv[tid] = s[(size_t)b * KBsz + tid];
    __syncthreads();
    if (tid == 0) {
        float mx = -INFINITY;
        for (int k = 0; k < KBsz; k++) mx = fmaxf(mx, sv[k]);
        float sm = 0.f;
        for (int k = 0; k < KBsz; k++) { float e = expf(sv[k] - mx); sv[k] = e; sm += e; }
        float inv = 1.f / sm;
        for (int k = 0; k < KBsz; k++) sv[k] *= inv;
    }
    __syncthreads();
    for (int d = tid; d < Dd; d += 256) {
        float a = 0.f;
        for (int k = 0; k < KBsz; k++)
            a += sv[k] * knowledge[((size_t)b * KBsz + k) * Dd + d];
        readv[(size_t)b * Dd + d] = a;
    }
}

__global__ void out_k(const float* __restrict__ mem,
                      const float* __restrict__ att,
                      float* __restrict__ out, int out_size)
{
    int i = blockIdx.x * blockDim.x + threadIdx.x;
    const int BD = Bsz * Dd;
    if (i >= BD) return;
    if (i < out_size) out[i] = mem[i];
    if (out_size >= 2 * BD) {
        int b = i >> 9, d = i & 511;
        out[BD + i] = att[((size_t)b * Ss + (Ss - 1)) * Dd + d];
    }
}

// ---------------- launch -----------------------------------------------------
static float* symf(const void* s) { void* p = nullptr; cudaGetSymbolAddress(&p, s); return (float*)p; }
static bf16*  symb(const void* s) { void* p = nullptr; cudaGetSymbolAddress(&p, s); return (bf16*)p; }

#define TG_SMEM (int)((NSTG*2*A_ST + NSTG*2*B_ST) * sizeof(bf16))

extern "C" void kernel_launch(void* const* d_in, const int* in_sizes, int n_in,
                              void* d_out, int out_size)
{
    const float* qword     = (const float*)d_in[0];
    const float* qemb      = (const float*)d_in[1];
    const float* knowledge = (const float*)d_in[2];
    const float* ci_w     = (const float*)d_in[4];
    const float* ci_b     = (const float*)d_in[5];
    const float* ciu_w    = (const float*)d_in[6];
    const float* ciu_b    = (const float*)d_in[7];
    const float* ca_w     = (const float*)d_in[8];
    const float* kproj_w  = (const float*)d_in[10];
    const float* kproj_b  = (const float*)d_in[11];
    const float* mproj_w  = (const float*)d_in[12];
    const float* mproj_b  = (const float*)d_in[13];
    const float* concat_w = (const float*)d_in[14];
    const float* concat_b = (const float*)d_in[15];
    const float* concat2_w= (const float*)d_in[16];
    const float* concat2_b= (const float*)d_in[17];
    const float* rattn_w  = (const float*)d_in[18];
    const float* write_w  = (const float*)d_in[20];
    const float* write_b  = (const float*)d_in[21];
    const float* init_mem = (const float*)d_in[22];
    const float* kq_w     = (const float*)d_in[23];
    const float* kq_b     = (const float*)d_in[24];
    const float* val_w    = (const float*)d_in[25];
    const float* val_b    = (const float*)d_in[26];
    float* out = (float*)d_out;

    float* q0    = symf(g_q0);
    float* qall  = symf(g_qall);
    float* ch    = symf(g_ch);
    float* chkey = symf(g_chkey);
    float* chval = symf(g_chval);
    float* normed= symf(g_normed);
    float* Amat  = symf(g_Amat);
    float* att   = symf(g_att);
    float* kp    = symf(g_kp);
    float* kp2   = symf(g_kp2);
    bf16*  kph   = symb(g_kph);
    bf16*  kpl   = symb(g_kpl);
    bf16*  e1h   = symb(g_e1h);
    bf16*  e1l   = symb(g_e1l);
    bf16*  ahb   = symb(g_ah);
    bf16*  alb   = symb(g_al);
    bf16*  knh   = symb(g_knh);
    bf16*  knl   = symb(g_knl);
    bf16*  wbh   = symb(g_wbh);
    bf16*  wbl   = symb(g_wbl);
    float* mp    = symf(g_mp);
    float* sbuf  = symf(g_s);
    float* readv = symf(g_read);
    float* mem0  = symf(g_mem0);
    float* mem1  = symf(g_mem1);

    static bool attr_done = false;
    if (!attr_done) {
        cudaFuncSetAttribute(tgemm_k<0>, cudaFuncAttributeMaxDynamicSharedMemorySize, TG_SMEM);
        cudaFuncSetAttribute(tgemm_k<1>, cudaFuncAttributeMaxDynamicSharedMemorySize, TG_SMEM);
        cudaFuncSetAttribute(tgemm_k<2>, cudaFuncAttributeMaxDynamicSharedMemorySize, TG_SMEM);
        cudaFuncSetAttribute(tgemm_k<3>, cudaFuncAttributeMaxDynamicSharedMemorySize, TG_SMEM);
        attr_done = true;
    }

    auto Gs = [](int M, int N, int Z) { return dim3(N / BN, M / BM, Z); };
    const dim3 GT(TGN / 128, MKB / 128);   // (4, 980)
    const float* NPF = nullptr;
    bf16* NPB = nullptr;

    // --- question path (small, FFMA2) ---
    sgemm_k<1><<<Gs(Bsz, Dd, 1), 256>>>(qemb, Dd, qemb, Dd, Dd, ci_w, ci_b, q0,
                                        Bsz, Dd, Dd, 0, 0, 0, 0);
    // 4 ciu GEMMs batched over z
    sgemm_k<0><<<Gs(Bsz, Dd, Ss), 256>>>(q0, Dd, q0, Dd, Dd, ciu_w, ciu_b, qall,
                                         Bsz, Dd, Dd,
                                         0, (size_t)Dd * Dd, Dd, (size_t)Bsz * Dd);
    word_attn_k<<<dim3(Bsz, Ss), 256>>>(qall, qword, ca_w, ch);
    sgemm_k<0><<<Gs(Bsz * Ss, Dd, 1), 256>>>(ch, Dd, ch, Dd, Dd, kq_w, kq_b, chkey,
                                             Bsz * Ss, Dd, Dd, 0, 0, 0, 0);
    sgemm_k<0><<<Gs(Bsz * Ss, Dd, 1), 256>>>(ch, Dd, ch, Dd, Dd, val_w, val_b, chval,
                                             Bsz * Ss, Dd, Dd, 0, 0, 0, 0);
    norm_k<<<(Bsz * Dd + 255) / 256, 256>>>(chkey, normed);
    gram_k<<<dim3(TBsz, TS), 256>>>(normed, Amat);
    attv_k<<<dim3(TBsz, TS), 256>>>(Amat, chval, att);

    // --- pre-splits (bf16) ---
    {
        size_t nk = (size_t)MKB * Dd;
        splitbf_k<<<(unsigned)((nk / 4 + 255) / 256), 256>>>(knowledge, knh, knl, nk);
        size_t nw = (size_t)Dd * Dd;
        splitbf_k<<<(unsigned)((nw / 4 + 255) / 256), 256>>>(kproj_w,  wbh + 0*Dd*Dd, wbl + 0*Dd*Dd, nw);
        splitbf_k<<<(unsigned)((nw / 4 + 255) / 256), 256>>>(concat_w, wbh + 1*Dd*Dd, wbl + 1*Dd*Dd, nw);
        splitbf_k<<<(unsigned)((nw / 4 + 255) / 256), 256>>>(concat_w + (size_t)Dd*Dd,
                                                             wbh + 2*Dd*Dd, wbl + 2*Dd*Dd, nw);
        splitbf_k<<<(unsigned)((nw / 4 + 255) / 256), 256>>>(concat2_w, wbh + 3*Dd*Dd, wbl + 3*Dd*Dd, nw);
    }

    // --- knowledge path precompute (bf16 tensor cores) ---
    tgemm_k<1><<<GT, 256, TG_SMEM>>>(knh, knl, wbh + 0*Dd*Dd, wbl + 0*Dd*Dd,
                                     kproj_b, kp, kph, kpl, NPF, NPF, 0, NPF, nullptr);
    tgemm_k<0><<<GT, 256, TG_SMEM>>>(kph, kpl, wbh + 2*Dd*Dd, wbl + 2*Dd*Dd,
                                     concat_b, kp2, NPB, NPB, NPF, NPF, 0, NPF, nullptr);

    bcast_k<<<(Bsz * Dd + 255) / 256, 256>>>(init_mem, mem0);

    float* mcur = mem0;
    float* mnext = mem1;
    for (int i = 0; i < Ss; i++) {
        sgemm_k<0><<<Gs(Bsz, Dd, 1), 256>>>(mcur, Dd, mcur, Dd, Dd, mproj_w, mproj_b, mp,
                                            Bsz, Dd, Dd, 0, 0, 0, 0);
        {
            size_t nk = (size_t)MKB * Dd;
            scale_split_k<<<(unsigned)((nk / 4 + 255) / 256), 256>>>(kp, mp, ahb, alb);
        }
        tgemm_k<2><<<GT, 256, TG_SMEM>>>(ahb, alb, wbh + 1*Dd*Dd, wbl + 1*Dd*Dd,
                                         NPF, nullptr, e1h, e1l, kp2, NPF, 0, NPF, nullptr);
        zero_k<<<(MKB + 255) / 256, 256>>>(sbuf, MKB);
        tgemm_k<3><<<GT, 256, TG_SMEM>>>(e1h, e1l, wbh + 3*Dd*Dd, wbl + 3*Dd*Dd,
                                         concat2_b, nullptr, NPB, NPB,
                                         NPF, att + (size_t)i * Dd, Ss * Dd, rattn_w, sbuf);
        read_k<<<Bsz, 256>>>(sbuf, knowledge, readv);
        sgemm_k<0><<<Gs(Bsz, Dd, 1), 256>>>(mcur, Dd, readv, Dd, Dd, write_w, write_b, mnext,
                                            Bsz, 2 * Dd, Dd, 0, 0, 0, 0);
        float* t = mcur; mcur = mnext; mnext = t;
    }

    out_k<<<(Bsz * Dd + 255) / 256, 256>>>(mcur, att, out, out_size);
}

// round 9
// speedup vs baseline: 2.7394x; 1.0052x over previous
#include <cuda_runtime.h>
#include <cuda_bf16.h>
#include <math.h>

// Problem constants
#define Bsz 640
#define Dd 512
#define Ss 4
#define Tt 10
#define TBsz 64
#define Ll 30
#define KBsz 196
#define MKB (Bsz*KBsz)   // 125440
#define TS 40            // T*S

typedef __nv_bfloat16 bf16;

// ---------------- scratch (static device globals; no allocations) ----------
__device__ float g_q0[Bsz*Dd];
__device__ float g_qall[Ss*Bsz*Dd];
__device__ float g_ch[Bsz*Ss*Dd];
__device__ float g_chkey[Bsz*Ss*Dd];
__device__ float g_chval[Bsz*Ss*Dd];
__device__ float g_normed[Bsz*Ss*Dd];
__device__ float g_Amat[TBsz*TS*TS];
__device__ float g_att[Bsz*Ss*Dd];
__device__ bf16  g_kph[(size_t)MKB*Dd];      // kp split hi/lo (raw kp never stored)
__device__ bf16  g_kpl[(size_t)MKB*Dd];
__device__ bf16  g_kp2h[(size_t)MKB*Dd];     // kp2 split hi/lo (raw never stored)
__device__ bf16  g_kp2l[(size_t)MKB*Dd];
__device__ bf16  g_e1h[(size_t)MKB*Dd];
__device__ bf16  g_e1l[(size_t)MKB*Dd];
__device__ bf16  g_ah [(size_t)MKB*Dd];      // (kp*mp) split
__device__ bf16  g_al [(size_t)MKB*Dd];
__device__ bf16  g_knh[(size_t)MKB*Dd];      // knowledge split
__device__ bf16  g_knl[(size_t)MKB*Dd];
__device__ bf16  g_wbh[4][Dd*Dd];            // weight splits hi
__device__ bf16  g_wbl[4][Dd*Dd];            // weight splits lo
__device__ float g_mp[Bsz*Dd];
__device__ float g_s4[4*(size_t)MKB];        // score partials per N-slice
__device__ float g_read[Bsz*Dd];
__device__ float g_mem0[Bsz*Dd];
__device__ float g_mem1[Bsz*Dd];

__device__ __forceinline__ float eluf(float x){ return x > 0.f ? x : expm1f(x); }

__device__ __forceinline__ void splitbf(float x, bf16& h, bf16& l){
    h = __float2bfloat16_rn(x);
    l = __float2bfloat16_rn(x - __bfloat162float(h));
}

__device__ __forceinline__ void mma_bf16(float* cc, const unsigned* a, const unsigned* b){
    asm("mma.sync.aligned.m16n8k16.row.col.f32.bf16.bf16.f32 "
        "{%0,%1,%2,%3}, {%4,%5,%6,%7}, {%8,%9}, {%0,%1,%2,%3};"
        : "+f"(cc[0]), "+f"(cc[1]), "+f"(cc[2]), "+f"(cc[3])
        : "r"(a[0]), "r"(a[1]), "r"(a[2]), "r"(a[3]), "r"(b[0]), "r"(b[1]));
}
__device__ __forceinline__ void ldm4(unsigned* r, const bf16* p){
    unsigned addr = (unsigned)__cvta_generic_to_shared(p);
    asm volatile("ldmatrix.sync.aligned.m8n8.x4.shared.b16 {%0,%1,%2,%3}, [%4];"
                 : "=r"(r[0]), "=r"(r[1]), "=r"(r[2]), "=r"(r[3]) : "r"(addr));
}
__device__ __forceinline__ void ldm4t(unsigned* r, const bf16* p){
    unsigned addr = (unsigned)__cvta_generic_to_shared(p);
    asm volatile("ldmatrix.sync.aligned.m8n8.x4.trans.shared.b16 {%0,%1,%2,%3}, [%4];"
                 : "=r"(r[0]), "=r"(r[1]), "=r"(r[2]), "=r"(r[3]) : "r"(addr));
}
__device__ __forceinline__ void cpa16(void* sdst, const void* gsrc){
    unsigned s = (unsigned)__cvta_generic_to_shared(sdst);
    asm volatile("cp.async.cg.shared.global [%0], [%1], 16;" :: "r"(s), "l"(gsrc));
}
__device__ __forceinline__ void cpa_commit(){ asm volatile("cp.async.commit_group;"); }

// =============  big tensor-core GEMM: split-bf16 3-pass, ldmatrix  ===========
// 2-stage cp.async pipeline, 2 CTAs/SM (75.8KB smem, regs capped at 128).
// MODE 2: t = elu(acc + (addh+addl)); Chi/Clo = splitbf(t)
// MODE 3: svec[slice][m] = sum_n elu((acc+bias[n])*colmul[(m/KB)*cmStride+n])*rvec[n]
// MODE 4: v = acc + bias; Chi/Clo = splitbf(v)
#define TGK 512
#define TGN 512
#define TBK 32            // bf16 K per tile
#define NKIT (TGK/TBK)    // 16
#define NSTG 2
#define ALD 40
#define BLD 136
#define A_ST (128*ALD)
#define B_ST (TBK*BLD)

template<int MODE>
__global__ __launch_bounds__(256, 2)
void tgemm_k(const bf16* __restrict__ Ahg, const bf16* __restrict__ Alg,
             const bf16* __restrict__ Bhg, const bf16* __restrict__ Blg,
             const float* __restrict__ bias,
             bf16* __restrict__ Chi, bf16* __restrict__ Clo,
             const bf16* __restrict__ addh, const bf16* __restrict__ addl,
             const float* __restrict__ colmul, int cmStride,
             const float* __restrict__ rvec, float* __restrict__ svec)
{
    extern __shared__ bf16 smem[];
    bf16* Abase = smem;                    // [NSTG][2][128][ALD]
    bf16* Bbase = smem + NSTG*2*A_ST;      // [NSTG][2][TBK][BLD]

    const int bm = blockIdx.y * 128;
    const int bn = blockIdx.x * 128;
    const int tid = threadIdx.x;
    const int wid = tid >> 5, lane = tid & 31;
    const int warp_m = wid & 1;
    const int warp_n = wid >> 1;
    const int r = lane >> 2, c = lane & 3;
    const int lrow = lane & 15, lcol = (lane >> 4) * 8;

    float acc[4][4][4];
    #pragma unroll
    for (int i = 0; i < 4; i++)
        #pragma unroll
        for (int j = 0; j < 4; j++)
            #pragma unroll
            for (int q = 0; q < 4; q++) acc[i][j][q] = 0.f;

    auto do_copy = [&](int k0, int st){
        const bf16* Ag[2] = { Ahg, Alg };
        const bf16* Bg[2] = { Bhg, Blg };
        #pragma unroll
        for (int h = 0; h < 2; h++) {
            bf16* As = Abase + (st*2 + h) * A_ST;
            bf16* Bs = Bbase + (st*2 + h) * B_ST;
            #pragma unroll
            for (int e2 = 0; e2 < 2; e2++) {
                int e   = tid * 2 + e2;
                int row = e >> 2;
                int seg = (e & 3) * 8;
                cpa16(As + row * ALD + seg,
                      Ag[h] + (size_t)(bm + row) * TGK + k0 * TBK + seg);
            }
            #pragma unroll
            for (int e2 = 0; e2 < 2; e2++) {
                int e   = tid * 2 + e2;
                int row = e >> 4;
                int seg = (e & 15) * 8;
                cpa16(Bs + row * BLD + seg,
                      Bg[h] + (size_t)(k0 * TBK + row) * TGN + bn + seg);
            }
        }
        cpa_commit();
    };

    do_copy(0, 0);

    for (int k0 = 0; k0 < NKIT; k0++) {
        int st = k0 & 1;
        if (k0 + 1 < NKIT) {
            do_copy(k0 + 1, st ^ 1);
            asm volatile("cp.async.wait_group 1;" ::: "memory");
        } else {
            asm volatile("cp.async.wait_group 0;" ::: "memory");
        }
        __syncthreads();

        const bf16* Ash = Abase + (st*2 + 0) * A_ST;
        const bf16* Asl = Abase + (st*2 + 1) * A_ST;
        const bf16* Bsh = Bbase + (st*2 + 0) * B_ST;
        const bf16* Bsl = Bbase + (st*2 + 1) * B_ST;

        #pragma unroll
        for (int ks = 0; ks < 2; ks++) {
            unsigned ah[4][4], al[4][4], bh[4][2], bl[4][2];
            #pragma unroll
            for (int mt = 0; mt < 4; mt++) {
                int row = warp_m * 64 + mt * 16 + lrow;
                ldm4(ah[mt], Ash + row * ALD + ks * 16 + lcol);
                ldm4(al[mt], Asl + row * ALD + ks * 16 + lcol);
            }
            #pragma unroll
            for (int p = 0; p < 2; p++) {
                unsigned t[4];
                int rr = ks * 16 + lrow;
                int ccol = warp_n * 32 + p * 16 + lcol;
                ldm4t(t, Bsh + rr * BLD + ccol);
                bh[2*p][0] = t[0]; bh[2*p][1] = t[1];
                bh[2*p+1][0] = t[2]; bh[2*p+1][1] = t[3];
                ldm4t(t, Bsl + rr * BLD + ccol);
                bl[2*p][0] = t[0]; bl[2*p][1] = t[1];
                bl[2*p+1][0] = t[2]; bl[2*p+1][1] = t[3];
            }
            #pragma unroll
            for (int mt = 0; mt < 4; mt++)
                #pragma unroll
                for (int nt = 0; nt < 4; nt++)
                    mma_bf16(acc[mt][nt], ah[mt], bh[nt]);   // hi*hi
            #pragma unroll
            for (int mt = 0; mt < 4; mt++)
                #pragma unroll
                for (int nt = 0; nt < 4; nt++)
                    mma_bf16(acc[mt][nt], al[mt], bh[nt]);   // lo*hi
            #pragma unroll
            for (int mt = 0; mt < 4; mt++)
                #pragma unroll
                for (int nt = 0; nt < 4; nt++)
                    mma_bf16(acc[mt][nt], ah[mt], bl[nt]);   // hi*lo
        }
        __syncthreads();
    }

    if (MODE == 3) {
        __shared__ float sred[128];
        if (tid < 128) sred[tid] = 0.f;
        __syncthreads();
        #pragma unroll
        for (int mt = 0; mt < 4; mt++) {
            int mloc = warp_m*64 + mt*16 + r;
            int m0 = bm + mloc;
            int b0 = m0 / KBsz;
            int b1 = (m0 + 8) / KBsz;
            float p0 = 0.f, p1 = 0.f;
            #pragma unroll
            for (int nt = 0; nt < 4; nt++) {
                int n0 = bn + warp_n*32 + nt*8 + 2*c;
                float v;
                v = eluf((acc[mt][nt][0] + bias[n0  ]) * colmul[(size_t)b0*cmStride + n0  ]); p0 += v*rvec[n0];
                v = eluf((acc[mt][nt][1] + bias[n0+1]) * colmul[(size_t)b0*cmStride + n0+1]); p0 += v*rvec[n0+1];
                v = eluf((acc[mt][nt][2] + bias[n0  ]) * colmul[(size_t)b1*cmStride + n0  ]); p1 += v*rvec[n0];
                v = eluf((acc[mt][nt][3] + bias[n0+1]) * colmul[(size_t)b1*cmStride + n0+1]); p1 += v*rvec[n0+1];
            }
            p0 += __shfl_xor_sync(0xffffffffu, p0, 1);
            p0 += __shfl_xor_sync(0xffffffffu, p0, 2);
            p1 += __shfl_xor_sync(0xffffffffu, p1, 1);
            p1 += __shfl_xor_sync(0xffffffffu, p1, 2);
            if (c == 0) { atomicAdd(&sred[mloc], p0); atomicAdd(&sred[mloc + 8], p1); }
        }
        __syncthreads();
        if (tid < 128)
            svec[(size_t)blockIdx.x * MKB + bm + tid] = sred[tid];   // partial slice
        return;
    }

    #pragma unroll
    for (int mt = 0; mt < 4; mt++) {
        int m0 = bm + warp_m*64 + mt*16 + r;
        #pragma unroll
        for (int nt = 0; nt < 4; nt++) {
            int n0 = bn + warp_n*32 + nt*8 + 2*c;
            #pragma unroll
            for (int half = 0; half < 2; half++) {
                int mm = m0 + half*8;
                float vx = acc[mt][nt][2*half], vy = acc[mt][nt][2*half+1];
                size_t gm = (size_t)mm*TGN + n0;
                if (MODE == 2) {
                    __nv_bfloat162 adh = *(const __nv_bfloat162*)(addh + gm);
                    __nv_bfloat162 adl = *(const __nv_bfloat162*)(addl + gm);
                    vx = eluf(vx + __bfloat162float(adh.x) + __bfloat162float(adl.x));
                    vy = eluf(vy + __bfloat162float(adh.y) + __bfloat162float(adl.y));
                } else { // MODE 4
                    vx += bias[n0]; vy += bias[n0+1];
                }
                bf16 hx, lx, hy, ly;
                splitbf(vx, hx, lx); splitbf(vy, hy, ly);
                *(__nv_bfloat162*)(Chi + gm) = __nv_bfloat162(hx, hy);
                *(__nv_bfloat162*)(Clo + gm) = __nv_bfloat162(lx, ly);
            }
        }
    }
}

// ---------------- split kernels ----------------------------------------------
__global__ void splitbf_k(const float* __restrict__ src,
                          bf16* __restrict__ hi, bf16* __restrict__ lo, size_t n)
{
    size_t i = ((size_t)blockIdx.x * blockDim.x + threadIdx.x) * 4;
    if (i >= n) return;
    float4 v = *(const float4*)(src + i);
    bf16 h0,l0,h1,l1,h2,l2,h3,l3;
    splitbf(v.x,h0,l0); splitbf(v.y,h1,l1); splitbf(v.z,h2,l2); splitbf(v.w,h3,l3);
    *(__nv_bfloat162*)(hi + i)     = __nv_bfloat162(h0, h1);
    *(__nv_bfloat162*)(hi + i + 2) = __nv_bfloat162(h2, h3);
    *(__nv_bfloat162*)(lo + i)     = __nv_bfloat162(l0, l1);
    *(__nv_bfloat162*)(lo + i + 2) = __nv_bfloat162(l2, l3);
}

// scale by mp then split: reads kp as hi/lo bf16 pair (reconstructed)
__global__ void scale_split_k(const bf16* __restrict__ kph,
                              const bf16* __restrict__ kpl,
                              const float* __restrict__ mp,
                              bf16* __restrict__ hi, bf16* __restrict__ lo)
{
    size_t i = ((size_t)blockIdx.x * blockDim.x + threadIdx.x) * 4;
    if (i >= (size_t)MKB * Dd) return;
    int m = (int)(i >> 9);
    int d = (int)(i & 511);
    int b = m / KBsz;
    __nv_bfloat162 h01 = *(const __nv_bfloat162*)(kph + i);
    __nv_bfloat162 h23 = *(const __nv_bfloat162*)(kph + i + 2);
    __nv_bfloat162 l01 = *(const __nv_bfloat162*)(kpl + i);
    __nv_bfloat162 l23 = *(const __nv_bfloat162*)(kpl + i + 2);
    float4 s = *(const float4*)(mp + (size_t)b * Dd + d);
    float v0 = (__bfloat162float(h01.x) + __bfloat162float(l01.x)) * s.x;
    float v1 = (__bfloat162float(h01.y) + __bfloat162float(l01.y)) * s.y;
    float v2 = (__bfloat162float(h23.x) + __bfloat162float(l23.x)) * s.z;
    float v3 = (__bfloat162float(h23.y) + __bfloat162float(l23.y)) * s.w;
    bf16 h0,l0,h1,l1,h2,l2,h3,l3;
    splitbf(v0,h0,l0); splitbf(v1,h1,l1); splitbf(v2,h2,l2); splitbf(v3,h3,l3);
    *(__nv_bfloat162*)(hi + i)     = __nv_bfloat162(h0, h1);
    *(__nv_bfloat162*)(hi + i + 2) = __nv_bfloat162(h2, h3);
    *(__nv_bfloat162*)(lo + i)     = __nv_bfloat162(l0, l1);
    *(__nv_bfloat162*)(lo + i + 2) = __nv_bfloat162(l2, l3);
}

// =====================  small FFMA2 GEMM (M=640 ops)  ========================
__device__ __forceinline__ unsigned long long pack2(float lo, float hi) {
    unsigned long long r;
    asm("mov.b64 %0, {%1, %2};" : "=l"(r) : "f"(lo), "f"(hi));
    return r;
}
__device__ __forceinline__ void unpack2(unsigned long long v, float& lo, float& hi) {
    asm("mov.b64 {%0, %1}, %2;" : "=f"(lo), "=f"(hi) : "l"(v));
}
__device__ __forceinline__ void fma2(unsigned long long& d,
                                     unsigned long long a, unsigned long long b) {
    asm("fma.rn.f32x2 %0, %1, %2, %0;" : "+l"(d) : "l"(a), "l"(b));
}

#define BM 128
#define BN 128
#define BKK 16

template<int MODE>
__global__ __launch_bounds__(256, 2)
void sgemm_k(const float* __restrict__ A, int lda,
             const float* __restrict__ A2, int lda2, int splitK,
             const float* __restrict__ W,
             const float* __restrict__ bias,
             float* __restrict__ C,
             int M, int K, int N,
             size_t strideA, size_t strideW, size_t strideBias, size_t strideC)
{
    A    += (size_t)blockIdx.z * strideA;
    A2   += (size_t)blockIdx.z * strideA;
    W    += (size_t)blockIdx.z * strideW;
    bias += (size_t)blockIdx.z * strideBias;
    C    += (size_t)blockIdx.z * strideC;

    __shared__ float As[BKK][BM];
    __shared__ float Bs[BKK][BN];

    const int bm = blockIdx.y * BM;
    const int bn = blockIdx.x * BN;
    const int tid = threadIdx.x;
    const int ty = tid >> 4;
    const int tx = tid & 15;

    unsigned long long acc2[8][4];
    #pragma unroll
    for (int i = 0; i < 8; i++)
        #pragma unroll
        for (int j = 0; j < 4; j++) acc2[i][j] = 0ull;

    for (int k0 = 0; k0 < K; k0 += BKK) {
        #pragma unroll
        for (int e2 = 0; e2 < 2; e2++) {
            int e   = tid * 2 + e2;
            int row = e >> 2;
            int kq  = (e & 3) * 4;
            int m   = bm + row;
            int k   = k0 + kq;
            const float* src = (k < splitK)
                ? (A  + (size_t)m * lda  + k)
                : (A2 + (size_t)m * lda2 + (k - splitK));
            float4 v = *(const float4*)src;
            As[kq + 0][row] = v.x; As[kq + 1][row] = v.y;
            As[kq + 2][row] = v.z; As[kq + 3][row] = v.w;
        }
        #pragma unroll
        for (int e2 = 0; e2 < 2; e2++) {
            int e   = tid * 2 + e2;
            int row = e >> 5;
            int cc  = (e & 31) * 4;
            float4 v = *(const float4*)(W + (size_t)(k0 + row) * N + bn + cc);
            *(float4*)&Bs[row][cc] = v;
        }
        __syncthreads();
        #pragma unroll
        for (int kk = 0; kk < BKK; kk++) {
            float a[8];
            unsigned long long b2[4];
            #pragma unroll
            for (int i = 0; i < 8; i++) a[i] = As[kk][ty * 8 + i];
            #pragma unroll
            for (int j = 0; j < 4; j++)
                b2[j] = *(const unsigned long long*)&Bs[kk][tx * 8 + j * 2];
            #pragma unroll
            for (int i = 0; i < 8; i++) {
                unsigned long long pa = pack2(a[i], a[i]);
                #pragma unroll
                for (int j = 0; j < 4; j++)
                    fma2(acc2[i][j], pa, b2[j]);
            }
        }
        __syncthreads();
    }

    float acc[8][8];
    #pragma unroll
    for (int i = 0; i < 8; i++)
        #pragma unroll
        for (int j = 0; j < 4; j++)
            unpack2(acc2[i][j], acc[i][2*j], acc[i][2*j+1]);

    #pragma unroll
    for (int i = 0; i < 8; i++) {
        int m = bm + ty * 8 + i;
        #pragma unroll
        for (int j = 0; j < 8; j += 4) {
            int n = bn + tx * 8 + j;
            float4 v;
            v.x = acc[i][j] + bias[n];     v.y = acc[i][j+1] + bias[n+1];
            v.z = acc[i][j+2] + bias[n+2]; v.w = acc[i][j+3] + bias[n+3];
            if (MODE == 1) { v.x = tanhf(v.x); v.y = tanhf(v.y); v.z = tanhf(v.z); v.w = tanhf(v.w); }
            *(float4*)(C + (size_t)m * N + n) = v;
        }
    }
}

// ---------------- attention / misc kernels (validated) -----------------------
__global__ void word_attn_k(const float* __restrict__ qall,
                            const float* __restrict__ qword,
                            const float* __restrict__ caw,
                            float* __restrict__ ch)
{
    int b = blockIdx.x, s = blockIdx.y;
    __shared__ float qs[Dd];
    __shared__ float lg[Ll];
    int tid = threadIdx.x;
    for (int d = tid; d < Dd; d += 256)
        qs[d] = qall[((size_t)s * Bsz + b) * Dd + d] * caw[d];
    __syncthreads();
    int wid = tid >> 5, lane = tid & 31;
    for (int l = wid; l < Ll; l += 8) {
        const float* qw = qword + ((size_t)b * Ll + l) * Dd;
        float a = 0.f;
        for (int d = lane; d < Dd; d += 32) a += qs[d] * qw[d];
        #pragma unroll
        for (int o = 16; o; o >>= 1) a += __shfl_xor_sync(0xffffffffu, a, o);
        if (lane == 0) lg[l] = a;
    }
    __syncthreads();
    if (tid == 0) {
        float mx = -INFINITY;
        for (int l = 0; l < Ll; l++) mx = fmaxf(mx, lg[l]);
        float sm = 0.f;
        for (int l = 0; l < Ll; l++) { float e = expf(lg[l] - mx); lg[l] = e; sm += e; }
        float inv = 1.f / sm;
        for (int l = 0; l < Ll; l++) lg[l] *= inv;
    }
    __syncthreads();
    for (int d = tid; d < Dd; d += 256) {
        float a = 0.f;
        for (int l = 0; l < Ll; l++) a += lg[l] * qword[((size_t)b * Ll + l) * Dd + d];
        ch[((size_t)b * Ss + s) * Dd + d] = a;
    }
}

__global__ void norm_k(const float* __restrict__ chkey, float* __restrict__ normed)
{
    int i = blockIdx.x * blockDim.x + threadIdx.x;
    if (i >= Bsz * Dd) return;
    int b = i >> 9, d = i & 511;
    size_t base = (size_t)b * Ss * Dd + d;
    float ss = 0.f;
    #pragma unroll
    for (int s = 0; s < Ss; s++) { float v = chkey[base + s * Dd]; ss += v * v; }
    float inv = 1.f / sqrtf(ss);
    #pragma unroll
    for (int s = 0; s < Ss; s++) normed[base + s * Dd] = chkey[base + s * Dd] * inv;
}

__global__ void gram_k(const float* __restrict__ normed, float* __restrict__ Amat)
{
    int tb = blockIdx.x, i = blockIdx.y;
    __shared__ float Ki[Dd];
    __shared__ float lg[TS];
    int tid = threadIdx.x;
    int ti = i / Ss, si = i % Ss;
    size_t rowi = ((size_t)(ti * TBsz + tb) * Ss + si) * Dd;
    for (int d = tid; d < Dd; d += 256) Ki[d] = normed[rowi + d];
    __syncthreads();
    int wid = tid >> 5, lane = tid & 31;
    for (int j = wid; j < TS; j += 8) {
        float a;
        if (j > i) a = -1e30f;
        else {
            int tj = j / Ss, sj = j % Ss;
            size_t rowj = ((size_t)(tj * TBsz + tb) * Ss + sj) * Dd;
            a = 0.f;
            for (int d = lane; d < Dd; d += 32) a += Ki[d] * normed[rowj + d];
            #pragma unroll
            for (int o = 16; o; o >>= 1) a += __shfl_xor_sync(0xffffffffu, a, o);
        }
        if (lane == 0) lg[j] = a;
    }
    __syncthreads();
    if (tid == 0) {
        float mx = -INFINITY;
        for (int j = 0; j < TS; j++) mx = fmaxf(mx, lg[j]);
        float sm = 0.f;
        for (int j = 0; j < TS; j++) { float e = expf(lg[j] - mx); lg[j] = e; sm += e; }
        float inv = 1.f / sm;
        for (int j = 0; j < TS; j++) lg[j] *= inv;
    }
    __syncthreads();
    if (tid < TS) Amat[((size_t)tb * TS + i) * TS + tid] = lg[tid];
}

__global__ void attv_k(const float* __restrict__ Amat,
                       const float* __restrict__ chval,
                       float* __restrict__ att)
{
    int tb = blockIdx.x, i = blockIdx.y;
    __shared__ float aw[TS];
    int tid = threadIdx.x;
    if (tid < TS) aw[tid] = Amat[((size_t)tb * TS + i) * TS + tid];
    __syncthreads();
    int ti = i / Ss, si = i % Ss;
    for (int d = tid; d < Dd; d += 256) {
        float a = 0.f;
        for (int j = 0; j <= i; j++) {
            int tj = j / Ss, sj = j % Ss;
            a += aw[j] * chval[((size_t)(tj * TBsz + tb) * Ss + sj) * Dd + d];
        }
        att[((size_t)(ti * TBsz + tb) * Ss + si) * Dd + d] = a;
    }
}

__global__ void bcast_k(const float* __restrict__ src, float* __restrict__ dst)
{
    int i = blockIdx.x * blockDim.x + threadIdx.x;
    if (i < Bsz * Dd) dst[i] = src[i & 511];
}

// softmax over KB (summing the 4 N-slice partials) + weighted read of knowledge
__global__ void read_k(const float* __restrict__ s4,
                       const float* __restrict__ knowledge,
                       float* __restrict__ readv)
{
    int b = blockIdx.x;
    __shared__ float sv[KBsz];
    int tid = threadIdx.x;
    if (tid < KBsz) {
        size_t base = (size_t)b * KBsz + tid;
        sv[tid] = s4[base] + s4[(size_t)MKB + base]
                + s4[2*(size_t)MKB + base] + s4[3*(size_t)MKB + base];
    }
    __syncthreads();
    if (tid == 0) {
        float mx = -INFINITY;
        for (int k = 0; k < KBsz; k++) mx = fmaxf(mx, sv[k]);
        float sm = 0.f;
        for (int k = 0; k < KBsz; k++) { float e = expf(sv[k] - mx); sv[k] = e; sm += e; }
        float inv = 1.f / sm;
        for (int k = 0; k < KBsz; k++) sv[k] *= inv;
    }
    __syncthreads();
    for (int d = tid; d < Dd; d += 256) {
        float a = 0.f;
        for (int k = 0; k < KBsz; k++)
            a += sv[k] * knowledge[((size_t)b * KBsz + k) * Dd + d];
        readv[(size_t)b * Dd + d] = a;
    }
}

__global__ void out_k(const float* __restrict__ mem,
                      const float* __restrict__ att,
                      float* __restrict__ out, int out_size)
{
    int i = blockIdx.x * blockDim.x + threadIdx.x;
    const int BD = Bsz * Dd;
    if (i >= BD) return;
    if (i < out_size) out[i] = mem[i];
    if (out_size >= 2 * BD) {
        int b = i >> 9, d = i & 511;
        out[BD + i] = att[((size_t)b * Ss + (Ss - 1)) * Dd + d];
    }
}

// ---------------- launch -----------------------------------------------------
static float* symf(const void* s) { void* p = nullptr; cudaGetSymbolAddress(&p, s); return (float*)p; }
static bf16*  symb(const void* s) { void* p = nullptr; cudaGetSymbolAddress(&p, s); return (bf16*)p; }

#define TG_SMEM (int)((NSTG*2*A_ST + NSTG*2*B_ST) * sizeof(bf16))

extern "C" void kernel_launch(void* const* d_in, const int* in_sizes, int n_in,
                              void* d_out, int out_size)
{
    const float* qword     = (const float*)d_in[0];
    const float* qemb      = (const float*)d_in[1];
    const float* knowledge = (const float*)d_in[2];
    const float* ci_w     = (const float*)d_in[4];
    const float* ci_b     = (const float*)d_in[5];
    const float* ciu_w    = (const float*)d_in[6];
    const float* ciu_b    = (const float*)d_in[7];
    const float* ca_w     = (const float*)d_in[8];
    const float* kproj_w  = (const float*)d_in[10];
    const float* kproj_b  = (const float*)d_in[11];
    const float* mproj_w  = (const float*)d_in[12];
    const float* mproj_b  = (const float*)d_in[13];
    const float* concat_w = (const float*)d_in[14];
    const float* concat_b = (const float*)d_in[15];
    const float* concat2_w= (const float*)d_in[16];
    const float* concat2_b= (const float*)d_in[17];
    const float* rattn_w  = (const float*)d_in[18];
    const float* write_w  = (const float*)d_in[20];
    const float* write_b  = (const float*)d_in[21];
    const float* init_mem = (const float*)d_in[22];
    const float* kq_w     = (const float*)d_in[23];
    const float* kq_b     = (const float*)d_in[24];
    const float* val_w    = (const float*)d_in[25];
    const float* val_b    = (const float*)d_in[26];
    float* out = (float*)d_out;

    float* q0    = symf(g_q0);
    float* qall  = symf(g_qall);
    float* ch    = symf(g_ch);
    float* chkey = symf(g_chkey);
    float* chval = symf(g_chval);
    float* normed= symf(g_normed);
    float* Amat  = symf(g_Amat);
    float* att   = symf(g_att);
    bf16*  kph   = symb(g_kph);
    bf16*  kpl   = symb(g_kpl);
    bf16*  kp2h  = symb(g_kp2h);
    bf16*  kp2l  = symb(g_kp2l);
    bf16*  e1h   = symb(g_e1h);
    bf16*  e1l   = symb(g_e1l);
    bf16*  ahb   = symb(g_ah);
    bf16*  alb   = symb(g_al);
    bf16*  knh   = symb(g_knh);
    bf16*  knl   = symb(g_knl);
    bf16*  wbh   = symb(g_wbh);
    bf16*  wbl   = symb(g_wbl);
    float* mp    = symf(g_mp);
    float* s4    = symf(g_s4);
    float* readv = symf(g_read);
    float* mem0  = symf(g_mem0);
    float* mem1  = symf(g_mem1);

    // one-time init (runs on the uncaptured correctness call)
    static bool init_done = false;
    static cudaStream_t s2 = nullptr;
    static cudaEvent_t evFork = nullptr, evJoin = nullptr;
    if (!init_done) {
        cudaFuncSetAttribute(tgemm_k<2>, cudaFuncAttributeMaxDynamicSharedMemorySize, TG_SMEM);
        cudaFuncSetAttribute(tgemm_k<3>, cudaFuncAttributeMaxDynamicSharedMemorySize, TG_SMEM);
        cudaFuncSetAttribute(tgemm_k<4>, cudaFuncAttributeMaxDynamicSharedMemorySize, TG_SMEM);
        cudaStreamCreateWithFlags(&s2, cudaStreamNonBlocking);
        cudaEventCreateWithFlags(&evFork, cudaEventDisableTiming);
        cudaEventCreateWithFlags(&evJoin, cudaEventDisableTiming);
        init_done = true;
    }

    auto Gs = [](int M, int N, int Z) { return dim3(N / BN, M / BM, Z); };
    const dim3 GT(Dd / 128, MKB / 128);   // (4, 980)
    const float* NPF = nullptr;
    bf16* NPB = nullptr;

    // ---- fork: knowledge precompute on s2, question path on default ----
    cudaEventRecord(evFork, 0);
    cudaStreamWaitEvent(s2, evFork, 0);

    {   // stream s2: splits + kp + kp2 + mem init
        size_t nk = (size_t)MKB * Dd;
        splitbf_k<<<(unsigned)((nk / 4 + 255) / 256), 256, 0, s2>>>(knowledge, knh, knl, nk);
        size_t nw = (size_t)Dd * Dd;
        splitbf_k<<<(unsigned)((nw / 4 + 255) / 256), 256, 0, s2>>>(kproj_w,  wbh + 0*Dd*Dd, wbl + 0*Dd*Dd, nw);
        splitbf_k<<<(unsigned)((nw / 4 + 255) / 256), 256, 0, s2>>>(concat_w, wbh + 1*Dd*Dd, wbl + 1*Dd*Dd, nw);
        splitbf_k<<<(unsigned)((nw / 4 + 255) / 256), 256, 0, s2>>>(concat_w + (size_t)Dd*Dd,
                                                                    wbh + 2*Dd*Dd, wbl + 2*Dd*Dd, nw);
        splitbf_k<<<(unsigned)((nw / 4 + 255) / 256), 256, 0, s2>>>(concat2_w, wbh + 3*Dd*Dd, wbl + 3*Dd*Dd, nw);
        // kp (split only)
        tgemm_k<4><<<GT, 256, TG_SMEM, s2>>>(knh, knl, wbh + 0*Dd*Dd, wbl + 0*Dd*Dd,
                                             kproj_b, kph, kpl, NPB, NPB, NPF, 0, NPF, nullptr);
        // kp2 (split only)
        tgemm_k<4><<<GT, 256, TG_SMEM, s2>>>(kph, kpl, wbh + 2*Dd*Dd, wbl + 2*Dd*Dd,
                                             concat_b, kp2h, kp2l, NPB, NPB, NPF, 0, NPF, nullptr);
        bcast_k<<<(Bsz * Dd + 255) / 256, 256, 0, s2>>>(init_mem, mem0);
    }
    cudaEventRecord(evJoin, s2);

    // default stream: question path (small, FFMA2)
    sgemm_k<1><<<Gs(Bsz, Dd, 1), 256>>>(qemb, Dd, qemb, Dd, Dd, ci_w, ci_b, q0,
                                        Bsz, Dd, Dd, 0, 0, 0, 0);
    sgemm_k<0><<<Gs(Bsz, Dd, Ss), 256>>>(q0, Dd, q0, Dd, Dd, ciu_w, ciu_b, qall,
                                         Bsz, Dd, Dd,
                                         0, (size_t)Dd * Dd, Dd, (size_t)Bsz * Dd);
    word_attn_k<<<dim3(Bsz, Ss), 256>>>(qall, qword, ca_w, ch);
    sgemm_k<0><<<Gs(Bsz * Ss, Dd, 1), 256>>>(ch, Dd, ch, Dd, Dd, kq_w, kq_b, chkey,
                                             Bsz * Ss, Dd, Dd, 0, 0, 0, 0);
    sgemm_k<0><<<Gs(Bsz * Ss, Dd, 1), 256>>>(ch, Dd, ch, Dd, Dd, val_w, val_b, chval,
                                             Bsz * Ss, Dd, Dd, 0, 0, 0, 0);
    norm_k<<<(Bsz * Dd + 255) / 256, 256>>>(chkey, normed);
    gram_k<<<dim3(TBsz, TS), 256>>>(normed, Amat);
    attv_k<<<dim3(TBsz, TS), 256>>>(Amat, chval, att);

    // join
    cudaStreamWaitEvent(0, evJoin, 0);

    float* mcur = mem0;
    float* mnext = mem1;
    for (int i = 0; i < Ss; i++) {
        sgemm_k<0><<<Gs(Bsz, Dd, 1), 256>>>(mcur, Dd, mcur, Dd, Dd, mproj_w, mproj_b, mp,
                                            Bsz, Dd, Dd, 0, 0, 0, 0);
        {
            size_t nk = (size_t)MKB * Dd;
            scale_split_k<<<(unsigned)((nk / 4 + 255) / 256), 256>>>(kph, kpl, mp, ahb, alb);
        }
        tgemm_k<2><<<GT, 256, TG_SMEM>>>(ahb, alb, wbh + 1*Dd*Dd, wbl + 1*Dd*Dd,
                                         NPF, e1h, e1l, kp2h, kp2l, NPF, 0, NPF, nullptr);
        tgemm_k<3><<<GT, 256, TG_SMEM>>>(e1h, e1l, wbh + 3*Dd*Dd, wbl + 3*Dd*Dd,
                                         concat2_b, NPB, NPB, NPB, NPB,
                                         att + (size_t)i * Dd, Ss * Dd, rattn_w, s4);
        read_k<<<Bsz, 256>>>(s4, knowledge, readv);
        sgemm_k<0><<<Gs(Bsz, Dd, 1), 256>>>(mcur, Dd, readv, Dd, Dd, write_w, write_b, mnext,
                                            Bsz, 2 * Dd, Dd, 0, 0, 0, 0);
        float* t = mcur; mcur = mnext; mnext = t;
    }

    out_k<<<(Bsz * Dd + 255) / 256, 256>>>(mcur, att, out, out_size);
}

// round 10
// speedup vs baseline: 2.9325x; 1.0705x over previous
#include <cuda_runtime.h>
#include <cuda_bf16.h>
#include <math.h>

// Problem constants
#define Bsz 640
#define Dd 512
#define Ss 4
#define Tt 10
#define TBsz 64
#define Ll 30
#define KBsz 196
#define MKB (Bsz*KBsz)   // 125440
#define TS 40            // T*S
#define BD (Bsz*Dd)

typedef __nv_bfloat16 bf16;

// ---------------- scratch (static device globals; no allocations) ----------
__device__ float g_q0[BD];
__device__ float g_qall[Ss*BD];
__device__ float g_ch[Bsz*Ss*Dd];
__device__ float g_chkey[Bsz*Ss*Dd];
__device__ float g_chval[Bsz*Ss*Dd];
__device__ float g_normed[Bsz*Ss*Dd];
__device__ float g_Amat[TBsz*TS*TS];
__device__ float g_att[Bsz*Ss*Dd];
__device__ bf16  g_kph[(size_t)MKB*Dd];
__device__ bf16  g_kpl[(size_t)MKB*Dd];
__device__ bf16  g_kp2h[(size_t)MKB*Dd];
__device__ bf16  g_kp2l[(size_t)MKB*Dd];
__device__ bf16  g_e1h[(size_t)MKB*Dd];
__device__ bf16  g_e1l[(size_t)MKB*Dd];
__device__ bf16  g_ah [(size_t)MKB*Dd];
__device__ bf16  g_al [(size_t)MKB*Dd];
__device__ bf16  g_knh[(size_t)MKB*Dd];
__device__ bf16  g_knl[(size_t)MKB*Dd];
__device__ bf16  g_wbh[4][Dd*Dd];
__device__ bf16  g_wbl[4][Dd*Dd];
__device__ float g_s4[4*(size_t)MKB];        // score partials per N-slice
__device__ float g_read[BD];
__device__ float g_Wcat[2][2*Dd*Dd];         // [0]=write_w copy, [1]=W2=write_w@mproj_w
__device__ float g_biascat[2][Dd];           // [0]=write_b copy, [1]=bias2
__device__ float g_zero[Dd];                 // stays zero (.bss)
__device__ float g_tmp512[Dd];
__device__ float g_zbuf[4*BD];               // [p][q][BD]: q=0 memory, q=1 mp

__device__ __forceinline__ float eluf(float x){ return x > 0.f ? x : expm1f(x); }

__device__ __forceinline__ void splitbf(float x, bf16& h, bf16& l){
    h = __float2bfloat16_rn(x);
    l = __float2bfloat16_rn(x - __bfloat162float(h));
}

__device__ __forceinline__ void mma_bf16(float* cc, const unsigned* a, const unsigned* b){
    asm("mma.sync.aligned.m16n8k16.row.col.f32.bf16.bf16.f32 "
        "{%0,%1,%2,%3}, {%4,%5,%6,%7}, {%8,%9}, {%0,%1,%2,%3};"
        : "+f"(cc[0]), "+f"(cc[1]), "+f"(cc[2]), "+f"(cc[3])
        : "r"(a[0]), "r"(a[1]), "r"(a[2]), "r"(a[3]), "r"(b[0]), "r"(b[1]));
}
__device__ __forceinline__ void ldm4(unsigned* r, const bf16* p){
    unsigned addr = (unsigned)__cvta_generic_to_shared(p);
    asm volatile("ldmatrix.sync.aligned.m8n8.x4.shared.b16 {%0,%1,%2,%3}, [%4];"
                 : "=r"(r[0]), "=r"(r[1]), "=r"(r[2]), "=r"(r[3]) : "r"(addr));
}
__device__ __forceinline__ void ldm4t(unsigned* r, const bf16* p){
    unsigned addr = (unsigned)__cvta_generic_to_shared(p);
    asm volatile("ldmatrix.sync.aligned.m8n8.x4.trans.shared.b16 {%0,%1,%2,%3}, [%4];"
                 : "=r"(r[0]), "=r"(r[1]), "=r"(r[2]), "=r"(r[3]) : "r"(addr));
}
__device__ __forceinline__ void cpa16(void* sdst, const void* gsrc){
    unsigned s = (unsigned)__cvta_generic_to_shared(sdst);
    asm volatile("cp.async.cg.shared.global [%0], [%1], 16;" :: "r"(s), "l"(gsrc));
}
__device__ __forceinline__ void cpa_commit(){ asm volatile("cp.async.commit_group;"); }

// =============  big tensor-core GEMM: split-bf16 3-pass, ldmatrix  ===========
// MODE 2: t = elu(acc + (addh+addl)); Chi/Clo = splitbf(t)
// MODE 3: svec[slice][m] = sum_n elu((acc+bias[n])*colmul[(m/KB)*cmStride+n])*rvec[n]
// MODE 4: v = acc + bias; Chi/Clo = splitbf(v)
#define TGK 512
#define TGN 512
#define TBK 32
#define NKIT (TGK/TBK)
#define NSTG 2
#define ALD 40
#define BLD 136
#define A_ST (128*ALD)
#define B_ST (TBK*BLD)

template<int MODE>
__global__ __launch_bounds__(256, 2)
void tgemm_k(const bf16* __restrict__ Ahg, const bf16* __restrict__ Alg,
             const bf16* __restrict__ Bhg, const bf16* __restrict__ Blg,
             const float* __restrict__ bias,
             bf16* __restrict__ Chi, bf16* __restrict__ Clo,
             const bf16* __restrict__ addh, const bf16* __restrict__ addl,
             const float* __restrict__ colmul, int cmStride,
             const float* __restrict__ rvec, float* __restrict__ svec)
{
    extern __shared__ bf16 smem[];
    bf16* Abase = smem;
    bf16* Bbase = smem + NSTG*2*A_ST;

    const int bm = blockIdx.y * 128;
    const int bn = blockIdx.x * 128;
    const int tid = threadIdx.x;
    const int wid = tid >> 5, lane = tid & 31;
    const int warp_m = wid & 1;
    const int warp_n = wid >> 1;
    const int r = lane >> 2, c = lane & 3;
    const int lrow = lane & 15, lcol = (lane >> 4) * 8;

    float acc[4][4][4];
    #pragma unroll
    for (int i = 0; i < 4; i++)
        #pragma unroll
        for (int j = 0; j < 4; j++)
            #pragma unroll
            for (int q = 0; q < 4; q++) acc[i][j][q] = 0.f;

    auto do_copy = [&](int k0, int st){
        const bf16* Ag[2] = { Ahg, Alg };
        const bf16* Bg[2] = { Bhg, Blg };
        #pragma unroll
        for (int h = 0; h < 2; h++) {
            bf16* As = Abase + (st*2 + h) * A_ST;
            bf16* Bs = Bbase + (st*2 + h) * B_ST;
            #pragma unroll
            for (int e2 = 0; e2 < 2; e2++) {
                int e   = tid * 2 + e2;
                int row = e >> 2;
                int seg = (e & 3) * 8;
                cpa16(As + row * ALD + seg,
                      Ag[h] + (size_t)(bm + row) * TGK + k0 * TBK + seg);
            }
            #pragma unroll
            for (int e2 = 0; e2 < 2; e2++) {
                int e   = tid * 2 + e2;
                int row = e >> 4;
                int seg = (e & 15) * 8;
                cpa16(Bs + row * BLD + seg,
                      Bg[h] + (size_t)(k0 * TBK + row) * TGN + bn + seg);
            }
        }
        cpa_commit();
    };

    do_copy(0, 0);

    for (int k0 = 0; k0 < NKIT; k0++) {
        int st = k0 & 1;
        if (k0 + 1 < NKIT) {
            do_copy(k0 + 1, st ^ 1);
            asm volatile("cp.async.wait_group 1;" ::: "memory");
        } else {
            asm volatile("cp.async.wait_group 0;" ::: "memory");
        }
        __syncthreads();

        const bf16* Ash = Abase + (st*2 + 0) * A_ST;
        const bf16* Asl = Abase + (st*2 + 1) * A_ST;
        const bf16* Bsh = Bbase + (st*2 + 0) * B_ST;
        const bf16* Bsl = Bbase + (st*2 + 1) * B_ST;

        #pragma unroll
        for (int ks = 0; ks < 2; ks++) {
            unsigned ah[4][4], al[4][4], bh[4][2], bl[4][2];
            #pragma unroll
            for (int mt = 0; mt < 4; mt++) {
                int row = warp_m * 64 + mt * 16 + lrow;
                ldm4(ah[mt], Ash + row * ALD + ks * 16 + lcol);
                ldm4(al[mt], Asl + row * ALD + ks * 16 + lcol);
            }
            #pragma unroll
            for (int p = 0; p < 2; p++) {
                unsigned t[4];
                int rr = ks * 16 + lrow;
                int ccol = warp_n * 32 + p * 16 + lcol;
                ldm4t(t, Bsh + rr * BLD + ccol);
                bh[2*p][0] = t[0]; bh[2*p][1] = t[1];
                bh[2*p+1][0] = t[2]; bh[2*p+1][1] = t[3];
                ldm4t(t, Bsl + rr * BLD + ccol);
                bl[2*p][0] = t[0]; bl[2*p][1] = t[1];
                bl[2*p+1][0] = t[2]; bl[2*p+1][1] = t[3];
            }
            #pragma unroll
            for (int mt = 0; mt < 4; mt++)
                #pragma unroll
                for (int nt = 0; nt < 4; nt++)
                    mma_bf16(acc[mt][nt], ah[mt], bh[nt]);
            #pragma unroll
            for (int mt = 0; mt < 4; mt++)
                #pragma unroll
                for (int nt = 0; nt < 4; nt++)
                    mma_bf16(acc[mt][nt], al[mt], bh[nt]);
            #pragma unroll
            for (int mt = 0; mt < 4; mt++)
                #pragma unroll
                for (int nt = 0; nt < 4; nt++)
                    mma_bf16(acc[mt][nt], ah[mt], bl[nt]);
        }
        __syncthreads();
    }

    if (MODE == 3) {
        __shared__ float sred[128];
        if (tid < 128) sred[tid] = 0.f;
        __syncthreads();
        #pragma unroll
        for (int mt = 0; mt < 4; mt++) {
            int mloc = warp_m*64 + mt*16 + r;
            int m0 = bm + mloc;
            int b0 = m0 / KBsz;
            int b1 = (m0 + 8) / KBsz;
            float p0 = 0.f, p1 = 0.f;
            #pragma unroll
            for (int nt = 0; nt < 4; nt++) {
                int n0 = bn + warp_n*32 + nt*8 + 2*c;
                float v;
                v = eluf((acc[mt][nt][0] + bias[n0  ]) * colmul[(size_t)b0*cmStride + n0  ]); p0 += v*rvec[n0];
                v = eluf((acc[mt][nt][1] + bias[n0+1]) * colmul[(size_t)b0*cmStride + n0+1]); p0 += v*rvec[n0+1];
                v = eluf((acc[mt][nt][2] + bias[n0  ]) * colmul[(size_t)b1*cmStride + n0  ]); p1 += v*rvec[n0];
                v = eluf((acc[mt][nt][3] + bias[n0+1]) * colmul[(size_t)b1*cmStride + n0+1]); p1 += v*rvec[n0+1];
            }
            p0 += __shfl_xor_sync(0xffffffffu, p0, 1);
            p0 += __shfl_xor_sync(0xffffffffu, p0, 2);
            p1 += __shfl_xor_sync(0xffffffffu, p1, 1);
            p1 += __shfl_xor_sync(0xffffffffu, p1, 2);
            if (c == 0) { atomicAdd(&sred[mloc], p0); atomicAdd(&sred[mloc + 8], p1); }
        }
        __syncthreads();
        if (tid < 128)
            svec[(size_t)blockIdx.x * MKB + bm + tid] = sred[tid];
        return;
    }

    #pragma unroll
    for (int mt = 0; mt < 4; mt++) {
        int m0 = bm + warp_m*64 + mt*16 + r;
        #pragma unroll
        for (int nt = 0; nt < 4; nt++) {
            int n0 = bn + warp_n*32 + nt*8 + 2*c;
            #pragma unroll
            for (int half = 0; half < 2; half++) {
                int mm = m0 + half*8;
                float vx = acc[mt][nt][2*half], vy = acc[mt][nt][2*half+1];
                size_t gm = (size_t)mm*TGN + n0;
                if (MODE == 2) {
                    __nv_bfloat162 adh = *(const __nv_bfloat162*)(addh + gm);
                    __nv_bfloat162 adl = *(const __nv_bfloat162*)(addl + gm);
                    vx = eluf(vx + __bfloat162float(adh.x) + __bfloat162float(adl.x));
                    vy = eluf(vy + __bfloat162float(adh.y) + __bfloat162float(adl.y));
                } else { // MODE 4
                    vx += bias[n0]; vy += bias[n0+1];
                }
                bf16 hx, lx, hy, ly;
                splitbf(vx, hx, lx); splitbf(vy, hy, ly);
                *(__nv_bfloat162*)(Chi + gm) = __nv_bfloat162(hx, hy);
                *(__nv_bfloat162*)(Clo + gm) = __nv_bfloat162(lx, ly);
            }
        }
    }
}

// ---------------- split / helper kernels -------------------------------------
__global__ void splitbf_k(const float* __restrict__ src,
                          bf16* __restrict__ hi, bf16* __restrict__ lo, size_t n)
{
    size_t i = ((size_t)blockIdx.x * blockDim.x + threadIdx.x) * 4;
    if (i >= n) return;
    float4 v = *(const float4*)(src + i);
    bf16 h0,l0,h1,l1,h2,l2,h3,l3;
    splitbf(v.x,h0,l0); splitbf(v.y,h1,l1); splitbf(v.z,h2,l2); splitbf(v.w,h3,l3);
    *(__nv_bfloat162*)(hi + i)     = __nv_bfloat162(h0, h1);
    *(__nv_bfloat162*)(hi + i + 2) = __nv_bfloat162(h2, h3);
    *(__nv_bfloat162*)(lo + i)     = __nv_bfloat162(l0, l1);
    *(__nv_bfloat162*)(lo + i + 2) = __nv_bfloat162(l2, l3);
}

__global__ void scale_split_k(const bf16* __restrict__ kph,
                              const bf16* __restrict__ kpl,
                              const float* __restrict__ mp,
                              bf16* __restrict__ hi, bf16* __restrict__ lo)
{
    size_t i = ((size_t)blockIdx.x * blockDim.x + threadIdx.x) * 4;
    if (i >= (size_t)MKB * Dd) return;
    int m = (int)(i >> 9);
    int d = (int)(i & 511);
    int b = m / KBsz;
    __nv_bfloat162 h01 = *(const __nv_bfloat162*)(kph + i);
    __nv_bfloat162 h23 = *(const __nv_bfloat162*)(kph + i + 2);
    __nv_bfloat162 l01 = *(const __nv_bfloat162*)(kpl + i);
    __nv_bfloat162 l23 = *(const __nv_bfloat162*)(kpl + i + 2);
    float4 s = *(const float4*)(mp + (size_t)b * Dd + d);
    float v0 = (__bfloat162float(h01.x) + __bfloat162float(l01.x)) * s.x;
    float v1 = (__bfloat162float(h01.y) + __bfloat162float(l01.y)) * s.y;
    float v2 = (__bfloat162float(h23.x) + __bfloat162float(l23.x)) * s.z;
    float v3 = (__bfloat162float(h23.y) + __bfloat162float(l23.y)) * s.w;
    bf16 h0,l0,h1,l1,h2,l2,h3,l3;
    splitbf(v0,h0,l0); splitbf(v1,h1,l1); splitbf(v2,h2,l2); splitbf(v3,h3,l3);
    *(__nv_bfloat162*)(hi + i)     = __nv_bfloat162(h0, h1);
    *(__nv_bfloat162*)(hi + i + 2) = __nv_bfloat162(h2, h3);
    *(__nv_bfloat162*)(lo + i)     = __nv_bfloat162(l0, l1);
    *(__nv_bfloat162*)(lo + i + 2) = __nv_bfloat162(l2, l3);
}

// r[n] = vec[k] dot W[k][n] + b[n]   (512x512 W, 512 vec)
__global__ void vecmat_k(const float* __restrict__ vec,
                         const float* __restrict__ W,
                         const float* __restrict__ b,
                         float* __restrict__ r)
{
    int n = blockIdx.x * blockDim.x + threadIdx.x;
    if (n >= Dd) return;
    float a = b[n];
    for (int k = 0; k < Dd; k++) a += vec[k] * W[(size_t)k * Dd + n];
    r[n] = a;
}

__global__ void copyf_k(const float* __restrict__ src, float* __restrict__ dst, int n)
{
    int i = (blockIdx.x * blockDim.x + threadIdx.x) * 4;
    if (i < n) *(float4*)(dst + i) = *(const float4*)(src + i);
}

// =====================  small FFMA2 GEMM (64x128 tile)  ======================
__device__ __forceinline__ unsigned long long pack2(float lo, float hi) {
    unsigned long long r;
    asm("mov.b64 %0, {%1, %2};" : "=l"(r) : "f"(lo), "f"(hi));
    return r;
}
__device__ __forceinline__ void unpack2(unsigned long long v, float& lo, float& hi) {
    asm("mov.b64 {%0, %1}, %2;" : "=f"(lo), "=f"(hi) : "l"(v));
}
__device__ __forceinline__ void fma2(unsigned long long& d,
                                     unsigned long long a, unsigned long long b) {
    asm("fma.rn.f32x2 %0, %1, %2, %0;" : "+l"(d) : "l"(a), "l"(b));
}

#define SBM 64
#define SBN 128
#define BKK 16

// z-batched; A'[m,k] = (k < splitK ? A[m,k] : A2[m,k-splitK])
template<int MODE>
__global__ __launch_bounds__(256)
void sgemm_k(const float* __restrict__ A, int lda,
             const float* __restrict__ A2, int lda2, int splitK,
             const float* __restrict__ W,
             const float* __restrict__ bias,
             float* __restrict__ C,
             int M, int K, int N,
             size_t strideA, size_t strideW, size_t strideBias, size_t strideC)
{
    A    += (size_t)blockIdx.z * strideA;
    A2   += (size_t)blockIdx.z * strideA;
    W    += (size_t)blockIdx.z * strideW;
    bias += (size_t)blockIdx.z * strideBias;
    C    += (size_t)blockIdx.z * strideC;

    __shared__ float As[BKK][SBM];
    __shared__ float Bs[BKK][SBN];

    const int bm = blockIdx.y * SBM;
    const int bn = blockIdx.x * SBN;
    const int tid = threadIdx.x;
    const int ty = tid >> 5;        // 0..7
    const int tx = tid & 31;        // 0..31

    unsigned long long acc2[8][2];
    #pragma unroll
    for (int i = 0; i < 8; i++) { acc2[i][0] = 0ull; acc2[i][1] = 0ull; }

    for (int k0 = 0; k0 < K; k0 += BKK) {
        {
            int e   = tid;              // 0..255
            int row = e >> 2;           // 0..63
            int kq  = (e & 3) * 4;
            int m   = bm + row;
            int k   = k0 + kq;
            const float* src = (k < splitK)
                ? (A  + (size_t)m * lda  + k)
                : (A2 + (size_t)m * lda2 + (k - splitK));
            float4 v = *(const float4*)src;
            As[kq + 0][row] = v.x; As[kq + 1][row] = v.y;
            As[kq + 2][row] = v.z; As[kq + 3][row] = v.w;
        }
        #pragma unroll
        for (int e2 = 0; e2 < 2; e2++) {
            int e   = tid * 2 + e2;
            int row = e >> 5;
            int cc  = (e & 31) * 4;
            float4 v = *(const float4*)(W + (size_t)(k0 + row) * N + bn + cc);
            *(float4*)&Bs[row][cc] = v;
        }
        __syncthreads();
        #pragma unroll
        for (int kk = 0; kk < BKK; kk++) {
            float a[8];
            unsigned long long b2[2];
            #pragma unroll
            for (int i = 0; i < 8; i++) a[i] = As[kk][ty * 8 + i];
            b2[0] = *(const unsigned long long*)&Bs[kk][tx * 4];
            b2[1] = *(const unsigned long long*)&Bs[kk][tx * 4 + 2];
            #pragma unroll
            for (int i = 0; i < 8; i++) {
                unsigned long long pa = pack2(a[i], a[i]);
                fma2(acc2[i][0], pa, b2[0]);
                fma2(acc2[i][1], pa, b2[1]);
            }
        }
        __syncthreads();
    }

    #pragma unroll
    for (int i = 0; i < 8; i++) {
        int m = bm + ty * 8 + i;
        int n = bn + tx * 4;
        float4 v;
        unpack2(acc2[i][0], v.x, v.y);
        unpack2(acc2[i][1], v.z, v.w);
        v.x += bias[n]; v.y += bias[n+1]; v.z += bias[n+2]; v.w += bias[n+3];
        if (MODE == 1) { v.x = tanhf(v.x); v.y = tanhf(v.y); v.z = tanhf(v.z); v.w = tanhf(v.w); }
        *(float4*)(C + (size_t)m * N + n) = v;
    }
}

// ---------------- attention / misc kernels (validated) -----------------------
__global__ void word_attn_k(const float* __restrict__ qall,
                            const float* __restrict__ qword,
                            const float* __restrict__ caw,
                            float* __restrict__ ch)
{
    int b = blockIdx.x, s = blockIdx.y;
    __shared__ float qs[Dd];
    __shared__ float lg[Ll];
    int tid = threadIdx.x;
    for (int d = tid; d < Dd; d += 256)
        qs[d] = qall[((size_t)s * Bsz + b) * Dd + d] * caw[d];
    __syncthreads();
    int wid = tid >> 5, lane = tid & 31;
    for (int l = wid; l < Ll; l += 8) {
        const float* qw = qword + ((size_t)b * Ll + l) * Dd;
        float a = 0.f;
        for (int d = lane; d < Dd; d += 32) a += qs[d] * qw[d];
        #pragma unroll
        for (int o = 16; o; o >>= 1) a += __shfl_xor_sync(0xffffffffu, a, o);
        if (lane == 0) lg[l] = a;
    }
    __syncthreads();
    if (tid == 0) {
        float mx = -INFINITY;
        for (int l = 0; l < Ll; l++) mx = fmaxf(mx, lg[l]);
        float sm = 0.f;
        for (int l = 0; l < Ll; l++) { float e = expf(lg[l] - mx); lg[l] = e; sm += e; }
        float inv = 1.f / sm;
        for (int l = 0; l < Ll; l++) lg[l] *= inv;
    }
    __syncthreads();
    for (int d = tid; d < Dd; d += 256) {
        float a = 0.f;
        for (int l = 0; l < Ll; l++) a += lg[l] * qword[((size_t)b * Ll + l) * Dd + d];
        ch[((size_t)b * Ss + s) * Dd + d] = a;
    }
}

__global__ void norm_k(const float* __restrict__ chkey, float* __restrict__ normed)
{
    int i = blockIdx.x * blockDim.x + threadIdx.x;
    if (i >= BD) return;
    int b = i >> 9, d = i & 511;
    size_t base = (size_t)b * Ss * Dd + d;
    float ss = 0.f;
    #pragma unroll
    for (int s = 0; s < Ss; s++) { float v = chkey[base + s * Dd]; ss += v * v; }
    float inv = 1.f / sqrtf(ss);
    #pragma unroll
    for (int s = 0; s < Ss; s++) normed[base + s * Dd] = chkey[base + s * Dd] * inv;
}

__global__ void gram_k(const float* __restrict__ normed, float* __restrict__ Amat)
{
    int tb = blockIdx.x, i = blockIdx.y;
    __shared__ float Ki[Dd];
    __shared__ float lg[TS];
    int tid = threadIdx.x;
    int ti = i / Ss, si = i % Ss;
    size_t rowi = ((size_t)(ti * TBsz + tb) * Ss + si) * Dd;
    for (int d = tid; d < Dd; d += 256) Ki[d] = normed[rowi + d];
    __syncthreads();
    int wid = tid >> 5, lane = tid & 31;
    for (int j = wid; j < TS; j += 8) {
        float a;
        if (j > i) a = -1e30f;
        else {
            int tj = j / Ss, sj = j % Ss;
            size_t rowj = ((size_t)(tj * TBsz + tb) * Ss + sj) * Dd;
            a = 0.f;
            for (int d = lane; d < Dd; d += 32) a += Ki[d] * normed[rowj + d];
            #pragma unroll
            for (int o = 16; o; o >>= 1) a += __shfl_xor_sync(0xffffffffu, a, o);
        }
        if (lane == 0) lg[j] = a;
    }
    __syncthreads();
    if (tid == 0) {
        float mx = -INFINITY;
        for (int j = 0; j < TS; j++) mx = fmaxf(mx, lg[j]);
        float sm = 0.f;
        for (int j = 0; j < TS; j++) { float e = expf(lg[j] - mx); lg[j] = e; sm += e; }
        float inv = 1.f / sm;
        for (int j = 0; j < TS; j++) lg[j] *= inv;
    }
    __syncthreads();
    if (tid < TS) Amat[((size_t)tb * TS + i) * TS + tid] = lg[tid];
}

__global__ void attv_k(const float* __restrict__ Amat,
                       const float* __restrict__ chval,
                       float* __restrict__ att)
{
    int tb = blockIdx.x, i = blockIdx.y;
    __shared__ float aw[TS];
    int tid = threadIdx.x;
    if (tid < TS) aw[tid] = Amat[((size_t)tb * TS + i) * TS + tid];
    __syncthreads();
    int ti = i / Ss, si = i % Ss;
    for (int d = tid; d < Dd; d += 256) {
        float a = 0.f;
        for (int j = 0; j <= i; j++) {
            int tj = j / Ss, sj = j % Ss;
            a += aw[j] * chval[((size_t)(tj * TBsz + tb) * Ss + sj) * Dd + d];
        }
        att[((size_t)(ti * TBsz + tb) * Ss + si) * Dd + d] = a;
    }
}

__global__ void bcast_k(const float* __restrict__ src, float* __restrict__ dst)
{
    int i = blockIdx.x * blockDim.x + threadIdx.x;
    if (i < BD) dst[i] = src[i & 511];
}

// softmax over KB (summing the 4 N-slice partials) + weighted read of knowledge
__global__ void read_k(const float* __restrict__ s4,
                       const float* __restrict__ knowledge,
                       float* __restrict__ readv)
{
    int b = blockIdx.x;
    __shared__ float sv[KBsz];
    int tid = threadIdx.x;
    if (tid < KBsz) {
        size_t base = (size_t)b * KBsz + tid;
        sv[tid] = s4[base] + s4[(size_t)MKB + base]
                + s4[2*(size_t)MKB + base] + s4[3*(size_t)MKB + base];
    }
    __syncthreads();
    if (tid == 0) {
        float mx = -INFINITY;
        for (int k = 0; k < KBsz; k++) mx = fmaxf(mx, sv[k]);
        float sm = 0.f;
        for (int k = 0; k < KBsz; k++) { float e = expf(sv[k] - mx); sv[k] = e; sm += e; }
        float inv = 1.f / sm;
        for (int k = 0; k < KBsz; k++) sv[k] *= inv;
    }
    __syncthreads();
    for (int d = tid; d < Dd; d += 256) {
        float a = 0.f;
        for (int k = 0; k < KBsz; k++)
            a += sv[k] * knowledge[((size_t)b * KBsz + k) * Dd + d];
        readv[(size_t)b * Dd + d] = a;
    }
}

__global__ void out_k(const float* __restrict__ mem,
                      const float* __restrict__ att,
                      float* __restrict__ out, int out_size)
{
    int i = blockIdx.x * blockDim.x + threadIdx.x;
    if (i >= BD) return;
    if (i < out_size) out[i] = mem[i];
    if (out_size >= 2 * BD) {
        int b = i >> 9, d = i & 511;
        out[BD + i] = att[((size_t)b * Ss + (Ss - 1)) * Dd + d];
    }
}

// ---------------- launch -----------------------------------------------------
static float* symf(const void* s) { void* p = nullptr; cudaGetSymbolAddress(&p, s); return (float*)p; }
static bf16*  symb(const void* s) { void* p = nullptr; cudaGetSymbolAddress(&p, s); return (bf16*)p; }

#define TG_SMEM (int)((NSTG*2*A_ST + NSTG*2*B_ST) * sizeof(bf16))

extern "C" void kernel_launch(void* const* d_in, const int* in_sizes, int n_in,
                              void* d_out, int out_size)
{
    const float* qword     = (const float*)d_in[0];
    const float* qemb      = (const float*)d_in[1];
    const float* knowledge = (const float*)d_in[2];
    const float* ci_w     = (const float*)d_in[4];
    const float* ci_b     = (const float*)d_in[5];
    const float* ciu_w    = (const float*)d_in[6];
    const float* ciu_b    = (const float*)d_in[7];
    const float* ca_w     = (const float*)d_in[8];
    const float* kproj_w  = (const float*)d_in[10];
    const float* kproj_b  = (const float*)d_in[11];
    const float* mproj_w  = (const float*)d_in[12];
    const float* mproj_b  = (const float*)d_in[13];
    const float* concat_w = (const float*)d_in[14];
    const float* concat_b = (const float*)d_in[15];
    const float* concat2_w= (const float*)d_in[16];
    const float* concat2_b= (const float*)d_in[17];
    const float* rattn_w  = (const float*)d_in[18];
    const float* write_w  = (const float*)d_in[20];
    const float* write_b  = (const float*)d_in[21];
    const float* init_mem = (const float*)d_in[22];
    const float* kq_w     = (const float*)d_in[23];
    const float* kq_b     = (const float*)d_in[24];
    const float* val_w    = (const float*)d_in[25];
    const float* val_b    = (const float*)d_in[26];
    float* out = (float*)d_out;

    float* q0     = symf(g_q0);
    float* qall   = symf(g_qall);
    float* ch     = symf(g_ch);
    float* chkey  = symf(g_chkey);
    float* chval  = symf(g_chval);
    float* normed = symf(g_normed);
    float* Amat   = symf(g_Amat);
    float* att    = symf(g_att);
    bf16*  kph    = symb(g_kph);
    bf16*  kpl    = symb(g_kpl);
    bf16*  kp2h   = symb(g_kp2h);
    bf16*  kp2l   = symb(g_kp2l);
    bf16*  e1h    = symb(g_e1h);
    bf16*  e1l    = symb(g_e1l);
    bf16*  ahb    = symb(g_ah);
    bf16*  alb    = symb(g_al);
    bf16*  knh    = symb(g_knh);
    bf16*  knl    = symb(g_knl);
    bf16*  wbh    = symb(g_wbh);
    bf16*  wbl    = symb(g_wbl);
    float* s4     = symf(g_s4);
    float* readv  = symf(g_read);
    float* Wcat   = symf(g_Wcat);
    float* biascat= symf(g_biascat);
    float* zerov  = symf(g_zero);
    float* tmp512 = symf(g_tmp512);
    float* zbuf   = symf(g_zbuf);

    static bool init_done = false;
    static cudaStream_t s2 = nullptr;
    static cudaEvent_t evFork = nullptr, evJoin = nullptr;
    if (!init_done) {
        cudaFuncSetAttribute(tgemm_k<2>, cudaFuncAttributeMaxDynamicSharedMemorySize, TG_SMEM);
        cudaFuncSetAttribute(tgemm_k<3>, cudaFuncAttributeMaxDynamicSharedMemorySize, TG_SMEM);
        cudaFuncSetAttribute(tgemm_k<4>, cudaFuncAttributeMaxDynamicSharedMemorySize, TG_SMEM);
        cudaStreamCreateWithFlags(&s2, cudaStreamNonBlocking);
        cudaEventCreateWithFlags(&evFork, cudaEventDisableTiming);
        cudaEventCreateWithFlags(&evJoin, cudaEventDisableTiming);
        init_done = true;
    }

    auto Gs = [](int M, int N, int Z) { return dim3(N / SBN, M / SBM, Z); };
    const dim3 GT(Dd / 128, MKB / 128);
    const float* NPF = nullptr;
    bf16* NPB = nullptr;

    // ---- fork ----
    cudaEventRecord(evFork, 0);
    cudaStreamWaitEvent(s2, evFork, 0);

    {   // stream s2: splits + kp + kp2 + write/mproj fusion prep + init state
        size_t nk = (size_t)MKB * Dd;
        splitbf_k<<<(unsigned)((nk / 4 + 255) / 256), 256, 0, s2>>>(knowledge, knh, knl, nk);
        size_t nw = (size_t)Dd * Dd;
        splitbf_k<<<(unsigned)((nw / 4 + 255) / 256), 256, 0, s2>>>(kproj_w,  wbh + 0*Dd*Dd, wbl + 0*Dd*Dd, nw);
        splitbf_k<<<(unsigned)((nw / 4 + 255) / 256), 256, 0, s2>>>(concat_w, wbh + 1*Dd*Dd, wbl + 1*Dd*Dd, nw);
        splitbf_k<<<(unsigned)((nw / 4 + 255) / 256), 256, 0, s2>>>(concat_w + (size_t)Dd*Dd,
                                                                    wbh + 2*Dd*Dd, wbl + 2*Dd*Dd, nw);
        splitbf_k<<<(unsigned)((nw / 4 + 255) / 256), 256, 0, s2>>>(concat2_w, wbh + 3*Dd*Dd, wbl + 3*Dd*Dd, nw);
        // kp / kp2 (split-only outputs)
        tgemm_k<4><<<GT, 256, TG_SMEM, s2>>>(knh, knl, wbh + 0*Dd*Dd, wbl + 0*Dd*Dd,
                                             kproj_b, kph, kpl, NPB, NPB, NPF, 0, NPF, nullptr);
        tgemm_k<4><<<GT, 256, TG_SMEM, s2>>>(kph, kpl, wbh + 2*Dd*Dd, wbl + 2*Dd*Dd,
                                             concat_b, kp2h, kp2l, NPB, NPB, NPF, 0, NPF, nullptr);
        // W2 = write_w @ mproj_w (M=1024,K=512,N=512) into Wcat[1]; Wcat[0] = write_w
        sgemm_k<0><<<Gs(2*Dd, Dd, 1), 256, 0, s2>>>(write_w, Dd, write_w, Dd, Dd,
                                                    mproj_w, zerov, Wcat + (size_t)2*Dd*Dd,
                                                    2*Dd, Dd, Dd, 0, 0, 0, 0);
        copyf_k<<<(2*Dd*Dd / 4 + 255) / 256, 256, 0, s2>>>(write_w, Wcat, 2*Dd*Dd);
        copyf_k<<<(Dd / 4 + 255) / 256, 256, 0, s2>>>(write_b, biascat, Dd);
        vecmat_k<<<2, 256, 0, s2>>>(write_b, mproj_w, mproj_b, biascat + Dd);   // bias2
        // init state in zbuf[p=0]: memory0 + mp0
        bcast_k<<<(BD + 255) / 256, 256, 0, s2>>>(init_mem, zbuf);              // memory0
        vecmat_k<<<2, 256, 0, s2>>>(init_mem, mproj_w, mproj_b, tmp512);        // mp0 row
        bcast_k<<<(BD + 255) / 256, 256, 0, s2>>>(tmp512, zbuf + BD);           // mp0
    }
    cudaEventRecord(evJoin, s2);

    // default stream: question path
    sgemm_k<1><<<Gs(Bsz, Dd, 1), 256>>>(qemb, Dd, qemb, Dd, Dd, ci_w, ci_b, q0,
                                        Bsz, Dd, Dd, 0, 0, 0, 0);
    sgemm_k<0><<<Gs(Bsz, Dd, Ss), 256>>>(q0, Dd, q0, Dd, Dd, ciu_w, ciu_b, qall,
                                         Bsz, Dd, Dd,
                                         0, (size_t)Dd * Dd, Dd, (size_t)BD);
    word_attn_k<<<dim3(Bsz, Ss), 256>>>(qall, qword, ca_w, ch);
    sgemm_k<0><<<Gs(Bsz * Ss, Dd, 1), 256>>>(ch, Dd, ch, Dd, Dd, kq_w, kq_b, chkey,
                                             Bsz * Ss, Dd, Dd, 0, 0, 0, 0);
    sgemm_k<0><<<Gs(Bsz * Ss, Dd, 1), 256>>>(ch, Dd, ch, Dd, Dd, val_w, val_b, chval,
                                             Bsz * Ss, Dd, Dd, 0, 0, 0, 0);
    norm_k<<<(BD + 255) / 256, 256>>>(chkey, normed);
    gram_k<<<dim3(TBsz, TS), 256>>>(normed, Amat);
    attv_k<<<dim3(TBsz, TS), 256>>>(Amat, chval, att);

    cudaStreamWaitEvent(0, evJoin, 0);

    int p = 0;
    for (int i = 0; i < Ss; i++) {
        float* mcur = zbuf + (size_t)p * 2 * BD;
        float* mpcur = mcur + BD;
        {
            size_t nk = (size_t)MKB * Dd;
            scale_split_k<<<(unsigned)((nk / 4 + 255) / 256), 256>>>(kph, kpl, mpcur, ahb, alb);
        }
        tgemm_k<2><<<GT, 256, TG_SMEM>>>(ahb, alb, wbh + 1*Dd*Dd, wbl + 1*Dd*Dd,
                                         NPF, e1h, e1l, kp2h, kp2l, NPF, 0, NPF, nullptr);
        tgemm_k<3><<<GT, 256, TG_SMEM>>>(e1h, e1l, wbh + 3*Dd*Dd, wbl + 3*Dd*Dd,
                                         concat2_b, NPB, NPB, NPB, NPB,
                                         att + (size_t)i * Dd, Ss * Dd, rattn_w, s4);
        read_k<<<Bsz, 256>>>(s4, knowledge, readv);
        // z=0: memory' = [mcur, read]@write_w + write_b
        // z=1: mp'     = [mcur, read]@W2      + bias2
        sgemm_k<0><<<Gs(Bsz, Dd, 2), 256>>>(mcur, Dd, readv, Dd, Dd,
                                            Wcat, biascat,
                                            zbuf + (size_t)(p ^ 1) * 2 * BD,
                                            Bsz, 2 * Dd, Dd,
                                            0, (size_t)2*Dd*Dd, Dd, (size_t)BD);
        p ^= 1;
    }

    out_k<<<(BD + 255) / 256, 256>>>(zbuf + (size_t)p * 2 * BD, att, out, out_size);
}

// round 11
// speedup vs baseline: 2.9356x; 1.0011x over previous
#include <cuda_runtime.h>
#include <cuda_bf16.h>
#include <math.h>

// Problem constants
#define Bsz 640
#define Dd 512
#define Ss 4
#define Tt 10
#define TBsz 64
#define Ll 30
#define KBsz 196
#define MKB (Bsz*KBsz)   // 125440
#define TS 40            // T*S
#define BD (Bsz*Dd)

typedef __nv_bfloat16 bf16;

// ---------------- scratch (static device globals; no allocations) ----------
__device__ float g_q0[BD];
__device__ float g_qall[Ss*BD];
__device__ float g_ch[Bsz*Ss*Dd];
__device__ float g_chkey[Bsz*Ss*Dd];
__device__ float g_chval[Bsz*Ss*Dd];
__device__ float g_normed[Bsz*Ss*Dd];
__device__ float g_Amat[TBsz*TS*TS];
__device__ float g_att[Bsz*Ss*Dd];
__device__ bf16  g_kph[(size_t)MKB*Dd];
__device__ bf16  g_kpl[(size_t)MKB*Dd];
__device__ bf16  g_kp2h[(size_t)MKB*Dd];
__device__ bf16  g_kp2l[(size_t)MKB*Dd];
__device__ bf16  g_e1h[(size_t)MKB*Dd];
__device__ bf16  g_e1l[(size_t)MKB*Dd];
__device__ bf16  g_ah [(size_t)MKB*Dd];
__device__ bf16  g_al [(size_t)MKB*Dd];
__device__ bf16  g_knh[(size_t)MKB*Dd];
__device__ bf16  g_knl[(size_t)MKB*Dd];
__device__ bf16  g_wbh[4][Dd*Dd];
__device__ bf16  g_wbl[4][Dd*Dd];
__device__ float g_s4[4*(size_t)MKB];        // score partials per N-slice
__device__ float g_read[BD];
__device__ float g_Wcat[2][2*Dd*Dd];         // [0]=write_w copy, [1]=W2=write_w@mproj_w
__device__ float g_biascat[2][Dd];           // [0]=write_b copy, [1]=bias2
__device__ float g_zero[Dd];                 // stays zero (.bss)
__device__ float g_tmp512[Dd];
__device__ float g_zbuf[4*BD];               // [p][q][BD]: q=0 memory, q=1 mp

__device__ __forceinline__ float eluf(float x){ return x > 0.f ? x : expm1f(x); }

__device__ __forceinline__ void splitbf(float x, bf16& h, bf16& l){
    h = __float2bfloat16_rn(x);
    l = __float2bfloat16_rn(x - __bfloat162float(h));
}

__device__ __forceinline__ void mma_bf16(float* cc, const unsigned* a, const unsigned* b){
    asm("mma.sync.aligned.m16n8k16.row.col.f32.bf16.bf16.f32 "
        "{%0,%1,%2,%3}, {%4,%5,%6,%7}, {%8,%9}, {%0,%1,%2,%3};"
        : "+f"(cc[0]), "+f"(cc[1]), "+f"(cc[2]), "+f"(cc[3])
        : "r"(a[0]), "r"(a[1]), "r"(a[2]), "r"(a[3]), "r"(b[0]), "r"(b[1]));
}
__device__ __forceinline__ void ldm4(unsigned* r, const bf16* p){
    unsigned addr = (unsigned)__cvta_generic_to_shared(p);
    asm volatile("ldmatrix.sync.aligned.m8n8.x4.shared.b16 {%0,%1,%2,%3}, [%4];"
                 : "=r"(r[0]), "=r"(r[1]), "=r"(r[2]), "=r"(r[3]) : "r"(addr));
}
__device__ __forceinline__ void ldm4t(unsigned* r, const bf16* p){
    unsigned addr = (unsigned)__cvta_generic_to_shared(p);
    asm volatile("ldmatrix.sync.aligned.m8n8.x4.trans.shared.b16 {%0,%1,%2,%3}, [%4];"
                 : "=r"(r[0]), "=r"(r[1]), "=r"(r[2]), "=r"(r[3]) : "r"(addr));
}
__device__ __forceinline__ void cpa16(void* sdst, const void* gsrc){
    unsigned s = (unsigned)__cvta_generic_to_shared(sdst);
    asm volatile("cp.async.cg.shared.global [%0], [%1], 16;" :: "r"(s), "l"(gsrc));
}
__device__ __forceinline__ void cpa_commit(){ asm volatile("cp.async.commit_group;"); }

// =============  big tensor-core GEMM: split-bf16 3-pass, ldmatrix  ===========
// MODE 2: t = elu(acc + (addh+addl)); Chi/Clo = splitbf(t)
// MODE 3: svec[slice][m] = sum_n elu((acc+bias[n])*colmul[(m/KB)*cmStride+n])*rvec[n]
// MODE 4: v = acc + bias; Chi/Clo = splitbf(v)
#define TGK 512
#define TGN 512
#define TBK 32
#define NKIT (TGK/TBK)
#define NSTG 2
#define ALD 40
#define BLD 136
#define A_ST (128*ALD)
#define B_ST (TBK*BLD)

template<int MODE>
__global__ __launch_bounds__(256, 2)
void tgemm_k(const bf16* __restrict__ Ahg, const bf16* __restrict__ Alg,
             const bf16* __restrict__ Bhg, const bf16* __restrict__ Blg,
             const float* __restrict__ bias,
             bf16* __restrict__ Chi, bf16* __restrict__ Clo,
             const bf16* __restrict__ addh, const bf16* __restrict__ addl,
             const float* __restrict__ colmul, int cmStride,
             const float* __restrict__ rvec, float* __restrict__ svec)
{
    extern __shared__ bf16 smem[];
    bf16* Abase = smem;
    bf16* Bbase = smem + NSTG*2*A_ST;

    const int bm = blockIdx.y * 128;
    const int bn = blockIdx.x * 128;
    const int tid = threadIdx.x;
    const int wid = tid >> 5, lane = tid & 31;
    const int warp_m = wid & 1;
    const int warp_n = wid >> 1;
    const int r = lane >> 2, c = lane & 3;
    const int lrow = lane & 15, lcol = (lane >> 4) * 8;

    float acc[4][4][4];
    #pragma unroll
    for (int i = 0; i < 4; i++)
        #pragma unroll
        for (int j = 0; j < 4; j++)
            #pragma unroll
            for (int q = 0; q < 4; q++) acc[i][j][q] = 0.f;

    auto do_copy = [&](int k0, int st){
        const bf16* Ag[2] = { Ahg, Alg };
        const bf16* Bg[2] = { Bhg, Blg };
        #pragma unroll
        for (int h = 0; h < 2; h++) {
            bf16* As = Abase + (st*2 + h) * A_ST;
            bf16* Bs = Bbase + (st*2 + h) * B_ST;
            #pragma unroll
            for (int e2 = 0; e2 < 2; e2++) {
                int e   = tid * 2 + e2;
                int row = e >> 2;
                int seg = (e & 3) * 8;
                cpa16(As + row * ALD + seg,
                      Ag[h] + (size_t)(bm + row) * TGK + k0 * TBK + seg);
            }
            #pragma unroll
            for (int e2 = 0; e2 < 2; e2++) {
                int e   = tid * 2 + e2;
                int row = e >> 4;
                int seg = (e & 15) * 8;
                cpa16(Bs + row * BLD + seg,
                      Bg[h] + (size_t)(k0 * TBK + row) * TGN + bn + seg);
            }
        }
        cpa_commit();
    };

    do_copy(0, 0);

    for (int k0 = 0; k0 < NKIT; k0++) {
        int st = k0 & 1;
        if (k0 + 1 < NKIT) {
            do_copy(k0 + 1, st ^ 1);
            asm volatile("cp.async.wait_group 1;" ::: "memory");
        } else {
            asm volatile("cp.async.wait_group 0;" ::: "memory");
        }
        __syncthreads();

        const bf16* Ash = Abase + (st*2 + 0) * A_ST;
        const bf16* Asl = Abase + (st*2 + 1) * A_ST;
        const bf16* Bsh = Bbase + (st*2 + 0) * B_ST;
        const bf16* Bsl = Bbase + (st*2 + 1) * B_ST;

        #pragma unroll
        for (int ks = 0; ks < 2; ks++) {
            unsigned ah[4][4], al[4][4], bh[4][2], bl[4][2];
            #pragma unroll
            for (int mt = 0; mt < 4; mt++) {
                int row = warp_m * 64 + mt * 16 + lrow;
                ldm4(ah[mt], Ash + row * ALD + ks * 16 + lcol);
                ldm4(al[mt], Asl + row * ALD + ks * 16 + lcol);
            }
            #pragma unroll
            for (int p = 0; p < 2; p++) {
                unsigned t[4];
                int rr = ks * 16 + lrow;
                int ccol = warp_n * 32 + p * 16 + lcol;
                ldm4t(t, Bsh + rr * BLD + ccol);
                bh[2*p][0] = t[0]; bh[2*p][1] = t[1];
                bh[2*p+1][0] = t[2]; bh[2*p+1][1] = t[3];
                ldm4t(t, Bsl + rr * BLD + ccol);
                bl[2*p][0] = t[0]; bl[2*p][1] = t[1];
                bl[2*p+1][0] = t[2]; bl[2*p+1][1] = t[3];
            }
            #pragma unroll
            for (int mt = 0; mt < 4; mt++)
                #pragma unroll
                for (int nt = 0; nt < 4; nt++)
                    mma_bf16(acc[mt][nt], ah[mt], bh[nt]);
            #pragma unroll
            for (int mt = 0; mt < 4; mt++)
                #pragma unroll
                for (int nt = 0; nt < 4; nt++)
                    mma_bf16(acc[mt][nt], al[mt], bh[nt]);
            #pragma unroll
            for (int mt = 0; mt < 4; mt++)
                #pragma unroll
                for (int nt = 0; nt < 4; nt++)
                    mma_bf16(acc[mt][nt], ah[mt], bl[nt]);
        }
        __syncthreads();
    }

    if (MODE == 3) {
        __shared__ float sred[128];
        if (tid < 128) sred[tid] = 0.f;
        __syncthreads();
        #pragma unroll
        for (int mt = 0; mt < 4; mt++) {
            int mloc = warp_m*64 + mt*16 + r;
            int m0 = bm + mloc;
            int b0 = m0 / KBsz;
            int b1 = (m0 + 8) / KBsz;
            float p0 = 0.f, p1 = 0.f;
            #pragma unroll
            for (int nt = 0; nt < 4; nt++) {
                int n0 = bn + warp_n*32 + nt*8 + 2*c;
                float v;
                v = eluf((acc[mt][nt][0] + bias[n0  ]) * colmul[(size_t)b0*cmStride + n0  ]); p0 += v*rvec[n0];
                v = eluf((acc[mt][nt][1] + bias[n0+1]) * colmul[(size_t)b0*cmStride + n0+1]); p0 += v*rvec[n0+1];
                v = eluf((acc[mt][nt][2] + bias[n0  ]) * colmul[(size_t)b1*cmStride + n0  ]); p1 += v*rvec[n0];
                v = eluf((acc[mt][nt][3] + bias[n0+1]) * colmul[(size_t)b1*cmStride + n0+1]); p1 += v*rvec[n0+1];
            }
            p0 += __shfl_xor_sync(0xffffffffu, p0, 1);
            p0 += __shfl_xor_sync(0xffffffffu, p0, 2);
            p1 += __shfl_xor_sync(0xffffffffu, p1, 1);
            p1 += __shfl_xor_sync(0xffffffffu, p1, 2);
            if (c == 0) { atomicAdd(&sred[mloc], p0); atomicAdd(&sred[mloc + 8], p1); }
        }
        __syncthreads();
        if (tid < 128)
            svec[(size_t)blockIdx.x * MKB + bm + tid] = sred[tid];
        return;
    }

    #pragma unroll
    for (int mt = 0; mt < 4; mt++) {
        int m0 = bm + warp_m*64 + mt*16 + r;
        #pragma unroll
        for (int nt = 0; nt < 4; nt++) {
            int n0 = bn + warp_n*32 + nt*8 + 2*c;
            #pragma unroll
            for (int half = 0; half < 2; half++) {
                int mm = m0 + half*8;
                float vx = acc[mt][nt][2*half], vy = acc[mt][nt][2*half+1];
                size_t gm = (size_t)mm*TGN + n0;
                if (MODE == 2) {
                    __nv_bfloat162 adh = *(const __nv_bfloat162*)(addh + gm);
                    __nv_bfloat162 adl = *(const __nv_bfloat162*)(addl + gm);
                    vx = eluf(vx + __bfloat162float(adh.x) + __bfloat162float(adl.x));
                    vy = eluf(vy + __bfloat162float(adh.y) + __bfloat162float(adl.y));
                } else { // MODE 4
                    vx += bias[n0]; vy += bias[n0+1];
                }
                bf16 hx, lx, hy, ly;
                splitbf(vx, hx, lx); splitbf(vy, hy, ly);
                *(__nv_bfloat162*)(Chi + gm) = __nv_bfloat162(hx, hy);
                *(__nv_bfloat162*)(Clo + gm) = __nv_bfloat162(lx, ly);
            }
        }
    }
}

// ---------------- split / helper kernels -------------------------------------
__global__ void splitbf_k(const float* __restrict__ src,
                          bf16* __restrict__ hi, bf16* __restrict__ lo, size_t n)
{
    size_t i = ((size_t)blockIdx.x * blockDim.x + threadIdx.x) * 4;
    if (i >= n) return;
    float4 v = *(const float4*)(src + i);
    bf16 h0,l0,h1,l1,h2,l2,h3,l3;
    splitbf(v.x,h0,l0); splitbf(v.y,h1,l1); splitbf(v.z,h2,l2); splitbf(v.w,h3,l3);
    *(__nv_bfloat162*)(hi + i)     = __nv_bfloat162(h0, h1);
    *(__nv_bfloat162*)(hi + i + 2) = __nv_bfloat162(h2, h3);
    *(__nv_bfloat162*)(lo + i)     = __nv_bfloat162(l0, l1);
    *(__nv_bfloat162*)(lo + i + 2) = __nv_bfloat162(l2, l3);
}

__global__ void scale_split_k(const bf16* __restrict__ kph,
                              const bf16* __restrict__ kpl,
                              const float* __restrict__ mp,
                              bf16* __restrict__ hi, bf16* __restrict__ lo)
{
    size_t i = ((size_t)blockIdx.x * blockDim.x + threadIdx.x) * 4;
    if (i >= (size_t)MKB * Dd) return;
    int m = (int)(i >> 9);
    int d = (int)(i & 511);
    int b = m / KBsz;
    __nv_bfloat162 h01 = *(const __nv_bfloat162*)(kph + i);
    __nv_bfloat162 h23 = *(const __nv_bfloat162*)(kph + i + 2);
    __nv_bfloat162 l01 = *(const __nv_bfloat162*)(kpl + i);
    __nv_bfloat162 l23 = *(const __nv_bfloat162*)(kpl + i + 2);
    float4 s = *(const float4*)(mp + (size_t)b * Dd + d);
    float v0 = (__bfloat162float(h01.x) + __bfloat162float(l01.x)) * s.x;
    float v1 = (__bfloat162float(h01.y) + __bfloat162float(l01.y)) * s.y;
    float v2 = (__bfloat162float(h23.x) + __bfloat162float(l23.x)) * s.z;
    float v3 = (__bfloat162float(h23.y) + __bfloat162float(l23.y)) * s.w;
    bf16 h0,l0,h1,l1,h2,l2,h3,l3;
    splitbf(v0,h0,l0); splitbf(v1,h1,l1); splitbf(v2,h2,l2); splitbf(v3,h3,l3);
    *(__nv_bfloat162*)(hi + i)     = __nv_bfloat162(h0, h1);
    *(__nv_bfloat162*)(hi + i + 2) = __nv_bfloat162(h2, h3);
    *(__nv_bfloat162*)(lo + i)     = __nv_bfloat162(l0, l1);
    *(__nv_bfloat162*)(lo + i + 2) = __nv_bfloat162(l2, l3);
}

// r[n] = vec[k] dot W[k][n] + b[n]   (512x512 W, 512 vec)
__global__ void vecmat_k(const float* __restrict__ vec,
                         const float* __restrict__ W,
                         const float* __restrict__ b,
                         float* __restrict__ r)
{
    int n = blockIdx.x * blockDim.x + threadIdx.x;
    if (n >= Dd) return;
    float a = b[n];
    for (int k = 0; k < Dd; k++) a += vec[k] * W[(size_t)k * Dd + n];
    r[n] = a;
}

__global__ void copyf_k(const float* __restrict__ src, float* __restrict__ dst, int n)
{
    int i = (blockIdx.x * blockDim.x + threadIdx.x) * 4;
    if (i < n) *(float4*)(dst + i) = *(const float4*)(src + i);
}

// =====================  small FFMA2 GEMM (64x128 tile)  ======================
__device__ __forceinline__ unsigned long long pack2(float lo, float hi) {
    unsigned long long r;
    asm("mov.b64 %0, {%1, %2};" : "=l"(r) : "f"(lo), "f"(hi));
    return r;
}
__device__ __forceinline__ void unpack2(unsigned long long v, float& lo, float& hi) {
    asm("mov.b64 {%0, %1}, %2;" : "=f"(lo), "=f"(hi) : "l"(v));
}
__device__ __forceinline__ void fma2(unsigned long long& d,
                                     unsigned long long a, unsigned long long b) {
    asm("fma.rn.f32x2 %0, %1, %2, %0;" : "+l"(d) : "l"(a), "l"(b));
}

#define SBM 64
#define SBN 128
#define BKK 16

// z-batched; A'[m,k] = (k < splitK ? A[m,k] : A2[m,k-splitK])
template<int MODE>
__global__ __launch_bounds__(256)
void sgemm_k(const float* __restrict__ A, int lda,
             const float* __restrict__ A2, int lda2, int splitK,
             const float* __restrict__ W,
             const float* __restrict__ bias,
             float* __restrict__ C,
             int M, int K, int N,
             size_t strideA, size_t strideW, size_t strideBias, size_t strideC)
{
    A    += (size_t)blockIdx.z * strideA;
    A2   += (size_t)blockIdx.z * strideA;
    W    += (size_t)blockIdx.z * strideW;
    bias += (size_t)blockIdx.z * strideBias;
    C    += (size_t)blockIdx.z * strideC;

    __shared__ float As[BKK][SBM];
    __shared__ float Bs[BKK][SBN];

    const int bm = blockIdx.y * SBM;
    const int bn = blockIdx.x * SBN;
    const int tid = threadIdx.x;
    const int ty = tid >> 5;        // 0..7
    const int tx = tid & 31;        // 0..31

    unsigned long long acc2[8][2];
    #pragma unroll
    for (int i = 0; i < 8; i++) { acc2[i][0] = 0ull; acc2[i][1] = 0ull; }

    for (int k0 = 0; k0 < K; k0 += BKK) {
        {
            int e   = tid;              // 0..255
            int row = e >> 2;           // 0..63
            int kq  = (e & 3) * 4;
            int m   = bm + row;
            int k   = k0 + kq;
            const float* src = (k < splitK)
                ? (A  + (size_t)m * lda  + k)
                : (A2 + (size_t)m * lda2 + (k - splitK));
            float4 v = *(const float4*)src;
            As[kq + 0][row] = v.x; As[kq + 1][row] = v.y;
            As[kq + 2][row] = v.z; As[kq + 3][row] = v.w;
        }
        #pragma unroll
        for (int e2 = 0; e2 < 2; e2++) {
            int e   = tid * 2 + e2;
            int row = e >> 5;
            int cc  = (e & 31) * 4;
            float4 v = *(const float4*)(W + (size_t)(k0 + row) * N + bn + cc);
            *(float4*)&Bs[row][cc] = v;
        }
        __syncthreads();
        #pragma unroll
        for (int kk = 0; kk < BKK; kk++) {
            float a[8];
            unsigned long long b2[2];
            #pragma unroll
            for (int i = 0; i < 8; i++) a[i] = As[kk][ty * 8 + i];
            b2[0] = *(const unsigned long long*)&Bs[kk][tx * 4];
            b2[1] = *(const unsigned long long*)&Bs[kk][tx * 4 + 2];
            #pragma unroll
            for (int i = 0; i < 8; i++) {
                unsigned long long pa = pack2(a[i], a[i]);
                fma2(acc2[i][0], pa, b2[0]);
                fma2(acc2[i][1], pa, b2[1]);
            }
        }
        __syncthreads();
    }

    #pragma unroll
    for (int i = 0; i < 8; i++) {
        int m = bm + ty * 8 + i;
        int n = bn + tx * 4;
        float4 v;
        unpack2(acc2[i][0], v.x, v.y);
        unpack2(acc2[i][1], v.z, v.w);
        v.x += bias[n]; v.y += bias[n+1]; v.z += bias[n+2]; v.w += bias[n+3];
        if (MODE == 1) { v.x = tanhf(v.x); v.y = tanhf(v.y); v.z = tanhf(v.z); v.w = tanhf(v.w); }
        *(float4*)(C + (size_t)m * N + n) = v;
    }
}

// ---------------- attention / misc kernels (validated) -----------------------
__global__ void word_attn_k(const float* __restrict__ qall,
                            const float* __restrict__ qword,
                            const float* __restrict__ caw,
                            float* __restrict__ ch)
{
    int b = blockIdx.x, s = blockIdx.y;
    __shared__ float qs[Dd];
    __shared__ float lg[Ll];
    int tid = threadIdx.x;
    for (int d = tid; d < Dd; d += 256)
        qs[d] = qall[((size_t)s * Bsz + b) * Dd + d] * caw[d];
    __syncthreads();
    int wid = tid >> 5, lane = tid & 31;
    for (int l = wid; l < Ll; l += 8) {
        const float* qw = qword + ((size_t)b * Ll + l) * Dd;
        float a = 0.f;
        for (int d = lane; d < Dd; d += 32) a += qs[d] * qw[d];
        #pragma unroll
        for (int o = 16; o; o >>= 1) a += __shfl_xor_sync(0xffffffffu, a, o);
        if (lane == 0) lg[l] = a;
    }
    __syncthreads();
    if (tid == 0) {
        float mx = -INFINITY;
        for (int l = 0; l < Ll; l++) mx = fmaxf(mx, lg[l]);
        float sm = 0.f;
        for (int l = 0; l < Ll; l++) { float e = expf(lg[l] - mx); lg[l] = e; sm += e; }
        float inv = 1.f / sm;
        for (int l = 0; l < Ll; l++) lg[l] *= inv;
    }
    __syncthreads();
    for (int d = tid; d < Dd; d += 256) {
        float a = 0.f;
        for (int l = 0; l < Ll; l++) a += lg[l] * qword[((size_t)b * Ll + l) * Dd + d];
        ch[((size_t)b * Ss + s) * Dd + d] = a;
    }
}

__global__ void norm_k(const float* __restrict__ chkey, float* __restrict__ normed)
{
    int i = blockIdx.x * blockDim.x + threadIdx.x;
    if (i >= BD) return;
    int b = i >> 9, d = i & 511;
    size_t base = (size_t)b * Ss * Dd + d;
    float ss = 0.f;
    #pragma unroll
    for (int s = 0; s < Ss; s++) { float v = chkey[base + s * Dd]; ss += v * v; }
    float inv = 1.f / sqrtf(ss);
    #pragma unroll
    for (int s = 0; s < Ss; s++) normed[base + s * Dd] = chkey[base + s * Dd] * inv;
}

__global__ void gram_k(const float* __restrict__ normed, float* __restrict__ Amat)
{
    int tb = blockIdx.x, i = blockIdx.y;
    __shared__ float Ki[Dd];
    __shared__ float lg[TS];
    int tid = threadIdx.x;
    int ti = i / Ss, si = i % Ss;
    size_t rowi = ((size_t)(ti * TBsz + tb) * Ss + si) * Dd;
    for (int d = tid; d < Dd; d += 256) Ki[d] = normed[rowi + d];
    __syncthreads();
    int wid = tid >> 5, lane = tid & 31;
    for (int j = wid; j < TS; j += 8) {
        float a;
        if (j > i) a = -1e30f;
        else {
            int tj = j / Ss, sj = j % Ss;
            size_t rowj = ((size_t)(tj * TBsz + tb) * Ss + sj) * Dd;
            a = 0.f;
            for (int d = lane; d < Dd; d += 32) a += Ki[d] * normed[rowj + d];
            #pragma unroll
            for (int o = 16; o; o >>= 1) a += __shfl_xor_sync(0xffffffffu, a, o);
        }
        if (lane == 0) lg[j] = a;
    }
    __syncthreads();
    if (tid == 0) {
        float mx = -INFINITY;
        for (int j = 0; j < TS; j++) mx = fmaxf(mx, lg[j]);
        float sm = 0.f;
        for (int j = 0; j < TS; j++) { float e = expf(lg[j] - mx); lg[j] = e; sm += e; }
        float inv = 1.f / sm;
        for (int j = 0; j < TS; j++) lg[j] *= inv;
    }
    __syncthreads();
    if (tid < TS) Amat[((size_t)tb * TS + i) * TS + tid] = lg[tid];
}

__global__ void attv_k(const float* __restrict__ Amat,
                       const float* __restrict__ chval,
                       float* __restrict__ att)
{
    int tb = blockIdx.x, i = blockIdx.y;
    __shared__ float aw[TS];
    int tid = threadIdx.x;
    if (tid < TS) aw[tid] = Amat[((size_t)tb * TS + i) * TS + tid];
    __syncthreads();
    int ti = i / Ss, si = i % Ss;
    for (int d = tid; d < Dd; d += 256) {
        float a = 0.f;
        for (int j = 0; j <= i; j++) {
            int tj = j / Ss, sj = j % Ss;
            a += aw[j] * chval[((size_t)(tj * TBsz + tb) * Ss + sj) * Dd + d];
        }
        att[((size_t)(ti * TBsz + tb) * Ss + si) * Dd + d] = a;
    }
}

__global__ void bcast_k(const float* __restrict__ src, float* __restrict__ dst)
{
    int i = blockIdx.x * blockDim.x + threadIdx.x;
    if (i < BD) dst[i] = src[i & 511];
}

// softmax over KB (summing 4 N-slice partials, parallel reductions)
// + vectorized weighted read of knowledge
__global__ void read_k(const float* __restrict__ s4,
                       const float* __restrict__ knowledge,
                       float* __restrict__ readv)
{
    int b = blockIdx.x;
    int tid = threadIdx.x;              // 256
    int wid = tid >> 5, lane = tid & 31;
    __shared__ float sv[KBsz];
    __shared__ float wred[8];

    float x = -1e30f;
    if (tid < KBsz) {
        size_t base = (size_t)b * KBsz + tid;
        x = s4[base] + s4[(size_t)MKB + base]
          + s4[2*(size_t)MKB + base] + s4[3*(size_t)MKB + base];
    }
    // block max
    float m = x;
    #pragma unroll
    for (int o = 16; o; o >>= 1) m = fmaxf(m, __shfl_xor_sync(0xffffffffu, m, o));
    if (lane == 0) wred[wid] = m;
    __syncthreads();
    if (tid == 0) {
        float mm = wred[0];
        #pragma unroll
        for (int w = 1; w < 8; w++) mm = fmaxf(mm, wred[w]);
        wred[0] = mm;
    }
    __syncthreads();
    float mx = wred[0];
    float e = (tid < KBsz) ? expf(x - mx) : 0.f;
    // block sum
    float s = e;
    #pragma unroll
    for (int o = 16; o; o >>= 1) s += __shfl_xor_sync(0xffffffffu, s, o);
    __syncthreads();
    if (lane == 0) wred[wid] = s;
    __syncthreads();
    if (tid == 0) {
        float ss = 0.f;
        #pragma unroll
        for (int w = 0; w < 8; w++) ss += wred[w];
        wred[0] = 1.f / ss;
    }
    __syncthreads();
    if (tid < KBsz) sv[tid] = e * wred[0];
    __syncthreads();

    // gather: 128 threads, one float4 column each, k unrolled
    if (tid < 128) {
        const float4* kn = (const float4*)(knowledge + (size_t)b * KBsz * Dd);
        float4 acc = make_float4(0.f, 0.f, 0.f, 0.f);
        int k = 0;
        #pragma unroll 4
        for (; k + 4 <= KBsz; k += 4) {
            #pragma unroll
            for (int u = 0; u < 4; u++) {
                float w = sv[k + u];
                float4 t = kn[(size_t)(k + u) * 128 + tid];
                acc.x += w * t.x; acc.y += w * t.y;
                acc.z += w * t.z; acc.w += w * t.w;
            }
        }
        // KBsz = 196 = 49*4, loop covers all; safety tail:
        for (; k < KBsz; k++) {
            float w = sv[k];
            float4 t = kn[(size_t)k * 128 + tid];
            acc.x += w * t.x; acc.y += w * t.y;
            acc.z += w * t.z; acc.w += w * t.w;
        }
        ((float4*)(readv + (size_t)b * Dd))[tid] = acc;
    }
}

__global__ void out_k(const float* __restrict__ mem,
                      const float* __restrict__ att,
                      float* __restrict__ out, int out_size)
{
    int i = blockIdx.x * blockDim.x + threadIdx.x;
    if (i >= BD) return;
    if (i < out_size) out[i] = mem[i];
    if (out_size >= 2 * BD) {
        int b = i >> 9, d = i & 511;
        out[BD + i] = att[((size_t)b * Ss + (Ss - 1)) * Dd + d];
    }
}

// ---------------- launch -----------------------------------------------------
static float* symf(const void* s) { void* p = nullptr; cudaGetSymbolAddress(&p, s); return (float*)p; }
static bf16*  symb(const void* s) { void* p = nullptr; cudaGetSymbolAddress(&p, s); return (bf16*)p; }

#define TG_SMEM (int)((NSTG*2*A_ST + NSTG*2*B_ST) * sizeof(bf16))

extern "C" void kernel_launch(void* const* d_in, const int* in_sizes, int n_in,
                              void* d_out, int out_size)
{
    const float* qword     = (const float*)d_in[0];
    const float* qemb      = (const float*)d_in[1];
    const float* knowledge = (const float*)d_in[2];
    const float* ci_w     = (const float*)d_in[4];
    const float* ci_b     = (const float*)d_in[5];
    const float* ciu_w    = (const float*)d_in[6];
    const float* ciu_b    = (const float*)d_in[7];
    const float* ca_w     = (const float*)d_in[8];
    const float* kproj_w  = (const float*)d_in[10];
    const float* kproj_b  = (const float*)d_in[11];
    const float* mproj_w  = (const float*)d_in[12];
    const float* mproj_b  = (const float*)d_in[13];
    const float* concat_w = (const float*)d_in[14];
    const float* concat_b = (const float*)d_in[15];
    const float* concat2_w= (const float*)d_in[16];
    const float* concat2_b= (const float*)d_in[17];
    const float* rattn_w  = (const float*)d_in[18];
    const float* write_w  = (const float*)d_in[20];
    const float* write_b  = (const float*)d_in[21];
    const float* init_mem = (const float*)d_in[22];
    const float* kq_w     = (const float*)d_in[23];
    const float* kq_b     = (const float*)d_in[24];
    const float* val_w    = (const float*)d_in[25];
    const float* val_b    = (const float*)d_in[26];
    float* out = (float*)d_out;

    float* q0     = symf(g_q0);
    float* qall   = symf(g_qall);
    float* ch     = symf(g_ch);
    float* chkey  = symf(g_chkey);
    float* chval  = symf(g_chval);
    float* normed = symf(g_normed);
    float* Amat   = symf(g_Amat);
    float* att    = symf(g_att);
    bf16*  kph    = symb(g_kph);
    bf16*  kpl    = symb(g_kpl);
    bf16*  kp2h   = symb(g_kp2h);
    bf16*  kp2l   = symb(g_kp2l);
    bf16*  e1h    = symb(g_e1h);
    bf16*  e1l    = symb(g_e1l);
    bf16*  ahb    = symb(g_ah);
    bf16*  alb    = symb(g_al);
    bf16*  knh    = symb(g_knh);
    bf16*  knl    = symb(g_knl);
    bf16*  wbh    = symb(g_wbh);
    bf16*  wbl    = symb(g_wbl);
    float* s4     = symf(g_s4);
    float* readv  = symf(g_read);
    float* Wcat   = symf(g_Wcat);
    float* biascat= symf(g_biascat);
    float* zerov  = symf(g_zero);
    float* tmp512 = symf(g_tmp512);
    float* zbuf   = symf(g_zbuf);

    static bool init_done = false;
    static cudaStream_t s2 = nullptr;
    static cudaEvent_t evFork = nullptr, evJoin = nullptr;
    if (!init_done) {
        cudaFuncSetAttribute(tgemm_k<2>, cudaFuncAttributeMaxDynamicSharedMemorySize, TG_SMEM);
        cudaFuncSetAttribute(tgemm_k<3>, cudaFuncAttributeMaxDynamicSharedMemorySize, TG_SMEM);
        cudaFuncSetAttribute(tgemm_k<4>, cudaFuncAttributeMaxDynamicSharedMemorySize, TG_SMEM);
        cudaStreamCreateWithFlags(&s2, cudaStreamNonBlocking);
        cudaEventCreateWithFlags(&evFork, cudaEventDisableTiming);
        cudaEventCreateWithFlags(&evJoin, cudaEventDisableTiming);
        init_done = true;
    }

    auto Gs = [](int M, int N, int Z) { return dim3(N / SBN, M / SBM, Z); };
    const dim3 GT(Dd / 128, MKB / 128);
    const float* NPF = nullptr;
    bf16* NPB = nullptr;

    // ---- fork ----
    cudaEventRecord(evFork, 0);
    cudaStreamWaitEvent(s2, evFork, 0);

    {   // stream s2: splits + kp + kp2 + write/mproj fusion prep + init state
        size_t nk = (size_t)MKB * Dd;
        splitbf_k<<<(unsigned)((nk / 4 + 255) / 256), 256, 0, s2>>>(knowledge, knh, knl, nk);
        size_t nw = (size_t)Dd * Dd;
        splitbf_k<<<(unsigned)((nw / 4 + 255) / 256), 256, 0, s2>>>(kproj_w,  wbh + 0*Dd*Dd, wbl + 0*Dd*Dd, nw);
        // concat_w top+bot are contiguous in src AND dst -> one launch
        splitbf_k<<<(unsigned)((2*nw / 4 + 255) / 256), 256, 0, s2>>>(concat_w, wbh + 1*Dd*Dd, wbl + 1*Dd*Dd, 2*nw);
        splitbf_k<<<(unsigned)((nw / 4 + 255) / 256), 256, 0, s2>>>(concat2_w, wbh + 3*Dd*Dd, wbl + 3*Dd*Dd, nw);
        // kp / kp2 (split-only outputs)
        tgemm_k<4><<<GT, 256, TG_SMEM, s2>>>(knh, knl, wbh + 0*Dd*Dd, wbl + 0*Dd*Dd,
                                             kproj_b, kph, kpl, NPB, NPB, NPF, 0, NPF, nullptr);
        tgemm_k<4><<<GT, 256, TG_SMEM, s2>>>(kph, kpl, wbh + 2*Dd*Dd, wbl + 2*Dd*Dd,
                                             concat_b, kp2h, kp2l, NPB, NPB, NPF, 0, NPF, nullptr);
        // W2 = write_w @ mproj_w into Wcat[1]; Wcat[0] = write_w
        sgemm_k<0><<<Gs(2*Dd, Dd, 1), 256, 0, s2>>>(write_w, Dd, write_w, Dd, Dd,
                                                    mproj_w, zerov, Wcat + (size_t)2*Dd*Dd,
                                                    2*Dd, Dd, Dd, 0, 0, 0, 0);
        copyf_k<<<(2*Dd*Dd / 4 + 255) / 256, 256, 0, s2>>>(write_w, Wcat, 2*Dd*Dd);
        copyf_k<<<(Dd / 4 + 255) / 256, 256, 0, s2>>>(write_b, biascat, Dd);
        vecmat_k<<<2, 256, 0, s2>>>(write_b, mproj_w, mproj_b, biascat + Dd);   // bias2
        // init state in zbuf[p=0]: memory0 + mp0
        bcast_k<<<(BD + 255) / 256, 256, 0, s2>>>(init_mem, zbuf);              // memory0
        vecmat_k<<<2, 256, 0, s2>>>(init_mem, mproj_w, mproj_b, tmp512);        // mp0 row
        bcast_k<<<(BD + 255) / 256, 256, 0, s2>>>(tmp512, zbuf + BD);           // mp0
    }
    cudaEventRecord(evJoin, s2);

    // default stream: question path
    sgemm_k<1><<<Gs(Bsz, Dd, 1), 256>>>(qemb, Dd, qemb, Dd, Dd, ci_w, ci_b, q0,
                                        Bsz, Dd, Dd, 0, 0, 0, 0);
    sgemm_k<0><<<Gs(Bsz, Dd, Ss), 256>>>(q0, Dd, q0, Dd, Dd, ciu_w, ciu_b, qall,
                                         Bsz, Dd, Dd,
                                         0, (size_t)Dd * Dd, Dd, (size_t)BD);
    word_attn_k<<<dim3(Bsz, Ss), 256>>>(qall, qword, ca_w, ch);
    sgemm_k<0><<<Gs(Bsz * Ss, Dd, 1), 256>>>(ch, Dd, ch, Dd, Dd, kq_w, kq_b, chkey,
                                             Bsz * Ss, Dd, Dd, 0, 0, 0, 0);
    sgemm_k<0><<<Gs(Bsz * Ss, Dd, 1), 256>>>(ch, Dd, ch, Dd, Dd, val_w, val_b, chval,
                                             Bsz * Ss, Dd, Dd, 0, 0, 0, 0);
    norm_k<<<(BD + 255) / 256, 256>>>(chkey, normed);
    gram_k<<<dim3(TBsz, TS), 256>>>(normed, Amat);
    attv_k<<<dim3(TBsz, TS), 256>>>(Amat, chval, att);

    cudaStreamWaitEvent(0, evJoin, 0);

    int p = 0;
    for (int i = 0; i < Ss; i++) {
        float* mcur = zbuf + (size_t)p * 2 * BD;
        float* mpcur = mcur + BD;
        {
            size_t nk = (size_t)MKB * Dd;
            scale_split_k<<<(unsigned)((nk / 4 + 255) / 256), 256>>>(kph, kpl, mpcur, ahb, alb);
        }
        tgemm_k<2><<<GT, 256, TG_SMEM>>>(ahb, alb, wbh + 1*Dd*Dd, wbl + 1*Dd*Dd,
                                         NPF, e1h, e1l, kp2h, kp2l, NPF, 0, NPF, nullptr);
        tgemm_k<3><<<GT, 256, TG_SMEM>>>(e1h, e1l, wbh + 3*Dd*Dd, wbl + 3*Dd*Dd,
                                         concat2_b, NPB, NPB, NPB, NPB,
                                         att + (size_t)i * Dd, Ss * Dd, rattn_w, s4);
        read_k<<<Bsz, 256>>>(s4, knowledge, readv);
        // z=0: memory' = [mcur, read]@write_w + write_b
        // z=1: mp'     = [mcur, read]@W2      + bias2
        sgemm_k<0><<<Gs(Bsz, Dd, 2), 256>>>(mcur, Dd, readv, Dd, Dd,
                                            Wcat, biascat,
                                            zbuf + (size_t)(p ^ 1) * 2 * BD,
                                            Bsz, 2 * Dd, Dd,
                                            0, (size_t)2*Dd*Dd, Dd, (size_t)BD);
        p ^= 1;
    }

    out_k<<<(BD + 255) / 256, 256>>>(zbuf + (size_t)p * 2 * BD, att, out, out_size);
}

// round 12
// speedup vs baseline: 2.9426x; 1.0024x over previous
#include <cuda_runtime.h>
#include <cuda_bf16.h>
#include <math.h>

// Problem constants
#define Bsz 640
#define Dd 512
#define Ss 4
#define Tt 10
#define TBsz 64
#define Ll 30
#define KBsz 196
#define MKB (Bsz*KBsz)   // 125440
#define TS 40            // T*S
#define BD (Bsz*Dd)

typedef __nv_bfloat16 bf16;

// ---------------- scratch (static device globals; no allocations) ----------
__device__ float g_q0[BD];
__device__ float g_qall[Ss*BD];
__device__ float g_ch[Bsz*Ss*Dd];
__device__ float g_chkey[Bsz*Ss*Dd];
__device__ float g_chval[Bsz*Ss*Dd];
__device__ float g_normed[Bsz*Ss*Dd];
__device__ float g_Amat[TBsz*TS*TS];
__device__ float g_att[Bsz*Ss*Dd];
__device__ bf16  g_kph[(size_t)MKB*Dd];
__device__ bf16  g_kpl[(size_t)MKB*Dd];
__device__ bf16  g_kp2h[(size_t)MKB*Dd];
__device__ bf16  g_kp2l[(size_t)MKB*Dd];
__device__ bf16  g_e1h[(size_t)MKB*Dd];
__device__ bf16  g_e1l[(size_t)MKB*Dd];
__device__ bf16  g_ah [(size_t)MKB*Dd];
__device__ bf16  g_al [(size_t)MKB*Dd];
__device__ bf16  g_knh[(size_t)MKB*Dd];
__device__ bf16  g_knl[(size_t)MKB*Dd];
__device__ bf16  g_wbh[4][Dd*Dd];
__device__ bf16  g_wbl[4][Dd*Dd];
__device__ float g_s4[4*(size_t)MKB];        // score partials per N-slice
__device__ float g_read[BD];
__device__ float g_Wcat[2][2*Dd*Dd];         // [0]=write_w copy, [1]=W2=write_w@mproj_w
__device__ float g_biascat[2][Dd];           // [0]=write_b copy, [1]=bias2
__device__ float g_zero[Dd];                 // stays zero (.bss)
__device__ float g_tmp512[Dd];
__device__ float g_zbuf[4*BD];               // [p][q][BD]: q=0 memory, q=1 mp

__device__ __forceinline__ float eluf(float x){ return x > 0.f ? x : expm1f(x); }

__device__ __forceinline__ void splitbf(float x, bf16& h, bf16& l){
    h = __float2bfloat16_rn(x);
    l = __float2bfloat16_rn(x - __bfloat162float(h));
}

__device__ __forceinline__ void mma_bf16(float* cc, const unsigned* a, const unsigned* b){
    asm("mma.sync.aligned.m16n8k16.row.col.f32.bf16.bf16.f32 "
        "{%0,%1,%2,%3}, {%4,%5,%6,%7}, {%8,%9}, {%0,%1,%2,%3};"
        : "+f"(cc[0]), "+f"(cc[1]), "+f"(cc[2]), "+f"(cc[3])
        : "r"(a[0]), "r"(a[1]), "r"(a[2]), "r"(a[3]), "r"(b[0]), "r"(b[1]));
}
__device__ __forceinline__ void ldm4(unsigned* r, const bf16* p){
    unsigned addr = (unsigned)__cvta_generic_to_shared(p);
    asm volatile("ldmatrix.sync.aligned.m8n8.x4.shared.b16 {%0,%1,%2,%3}, [%4];"
                 : "=r"(r[0]), "=r"(r[1]), "=r"(r[2]), "=r"(r[3]) : "r"(addr));
}
__device__ __forceinline__ void ldm4t(unsigned* r, const bf16* p){
    unsigned addr = (unsigned)__cvta_generic_to_shared(p);
    asm volatile("ldmatrix.sync.aligned.m8n8.x4.trans.shared.b16 {%0,%1,%2,%3}, [%4];"
                 : "=r"(r[0]), "=r"(r[1]), "=r"(r[2]), "=r"(r[3]) : "r"(addr));
}
__device__ __forceinline__ void cpa16(void* sdst, const void* gsrc){
    unsigned s = (unsigned)__cvta_generic_to_shared(sdst);
    asm volatile("cp.async.cg.shared.global [%0], [%1], 16;" :: "r"(s), "l"(gsrc));
}
__device__ __forceinline__ void cpa_commit(){ asm volatile("cp.async.commit_group;"); }

// =============  big tensor-core GEMM: split-bf16 3-pass, ldmatrix  ===========
// MODE 2: t = elu(acc + (addh+addl)); Chi/Clo = splitbf(t)
// MODE 3: svec[slice][m] = sum_n elu((acc+bias[n])*colmul[(m/KB)*cmStride+n])*rvec[n]
// MODE 4: v = acc + bias; Chi/Clo = splitbf(v)
#define TGK 512
#define TGN 512
#define TBK 32
#define NKIT (TGK/TBK)
#define NSTG 2
#define ALD 40
#define BLD 136
#define A_ST (128*ALD)
#define B_ST (TBK*BLD)

template<int MODE>
__global__ __launch_bounds__(256, 2)
void tgemm_k(const bf16* __restrict__ Ahg, const bf16* __restrict__ Alg,
             const bf16* __restrict__ Bhg, const bf16* __restrict__ Blg,
             const float* __restrict__ bias,
             bf16* __restrict__ Chi, bf16* __restrict__ Clo,
             const bf16* __restrict__ addh, const bf16* __restrict__ addl,
             const float* __restrict__ colmul, int cmStride,
             const float* __restrict__ rvec, float* __restrict__ svec)
{
    extern __shared__ bf16 smem[];
    bf16* Abase = smem;
    bf16* Bbase = smem + NSTG*2*A_ST;

    const int bm = blockIdx.y * 128;
    const int bn = blockIdx.x * 128;
    const int tid = threadIdx.x;
    const int wid = tid >> 5, lane = tid & 31;
    const int warp_m = wid & 1;
    const int warp_n = wid >> 1;
    const int r = lane >> 2, c = lane & 3;
    const int lrow = lane & 15, lcol = (lane >> 4) * 8;

    float acc[4][4][4];
    #pragma unroll
    for (int i = 0; i < 4; i++)
        #pragma unroll
        for (int j = 0; j < 4; j++)
            #pragma unroll
            for (int q = 0; q < 4; q++) acc[i][j][q] = 0.f;

    auto do_copy = [&](int k0, int st){
        const bf16* Ag[2] = { Ahg, Alg };
        const bf16* Bg[2] = { Bhg, Blg };
        #pragma unroll
        for (int h = 0; h < 2; h++) {
            bf16* As = Abase + (st*2 + h) * A_ST;
            bf16* Bs = Bbase + (st*2 + h) * B_ST;
            #pragma unroll
            for (int e2 = 0; e2 < 2; e2++) {
                int e   = tid * 2 + e2;
                int row = e >> 2;
                int seg = (e & 3) * 8;
                cpa16(As + row * ALD + seg,
                      Ag[h] + (size_t)(bm + row) * TGK + k0 * TBK + seg);
            }
            #pragma unroll
            for (int e2 = 0; e2 < 2; e2++) {
                int e   = tid * 2 + e2;
                int row = e >> 4;
                int seg = (e & 15) * 8;
                cpa16(Bs + row * BLD + seg,
                      Bg[h] + (size_t)(k0 * TBK + row) * TGN + bn + seg);
            }
        }
        cpa_commit();
    };

    do_copy(0, 0);

    for (int k0 = 0; k0 < NKIT; k0++) {
        int st = k0 & 1;
        // stage st's copy is the most recent committed group -> drain all
        asm volatile("cp.async.wait_group 0;" ::: "memory");
        __syncthreads();
        // issue next copy AFTER the sync: stage st^1's readers (iter k0-1)
        // have all passed the barrier, so overwrite is safe.
        if (k0 + 1 < NKIT) do_copy(k0 + 1, st ^ 1);

        const bf16* Ash = Abase + (st*2 + 0) * A_ST;
        const bf16* Asl = Abase + (st*2 + 1) * A_ST;
        const bf16* Bsh = Bbase + (st*2 + 0) * B_ST;
        const bf16* Bsl = Bbase + (st*2 + 1) * B_ST;

        #pragma unroll
        for (int ks = 0; ks < 2; ks++) {
            unsigned ah[4][4], al[4][4], bh[4][2], bl[4][2];
            int rr = ks * 16 + lrow;
            int cbase = warp_n * 32 + lcol;
            // --- fragments for hi*hi first ---
            #pragma unroll
            for (int mt = 0; mt < 4; mt++) {
                int row = warp_m * 64 + mt * 16 + lrow;
                ldm4(ah[mt], Ash + row * ALD + ks * 16 + lcol);
            }
            #pragma unroll
            for (int p = 0; p < 2; p++) {
                unsigned t[4];
                ldm4t(t, Bsh + rr * BLD + cbase + p * 16);
                bh[2*p][0] = t[0]; bh[2*p][1] = t[1];
                bh[2*p+1][0] = t[2]; bh[2*p+1][1] = t[3];
            }
            #pragma unroll
            for (int mt = 0; mt < 4; mt++)
                #pragma unroll
                for (int nt = 0; nt < 4; nt++)
                    mma_bf16(acc[mt][nt], ah[mt], bh[nt]);   // hi*hi
            // --- al loads hide under hi*hi issue ---
            #pragma unroll
            for (int mt = 0; mt < 4; mt++) {
                int row = warp_m * 64 + mt * 16 + lrow;
                ldm4(al[mt], Asl + row * ALD + ks * 16 + lcol);
            }
            #pragma unroll
            for (int mt = 0; mt < 4; mt++)
                #pragma unroll
                for (int nt = 0; nt < 4; nt++)
                    mma_bf16(acc[mt][nt], al[mt], bh[nt]);   // lo*hi
            // --- bl loads hide under lo*hi issue ---
            #pragma unroll
            for (int p = 0; p < 2; p++) {
                unsigned t[4];
                ldm4t(t, Bsl + rr * BLD + cbase + p * 16);
                bl[2*p][0] = t[0]; bl[2*p][1] = t[1];
                bl[2*p+1][0] = t[2]; bl[2*p+1][1] = t[3];
            }
            #pragma unroll
            for (int mt = 0; mt < 4; mt++)
                #pragma unroll
                for (int nt = 0; nt < 4; nt++)
                    mma_bf16(acc[mt][nt], ah[mt], bl[nt]);   // hi*lo
        }
    }
    __syncthreads();   // final: all warps done before epilogue smem reuse

    if (MODE == 3) {
        __shared__ float sred[128];
        if (tid < 128) sred[tid] = 0.f;
        __syncthreads();
        #pragma unroll
        for (int mt = 0; mt < 4; mt++) {
            int mloc = warp_m*64 + mt*16 + r;
            int m0 = bm + mloc;
            int b0 = m0 / KBsz;
            int b1 = (m0 + 8) / KBsz;
            float p0 = 0.f, p1 = 0.f;
            #pragma unroll
            for (int nt = 0; nt < 4; nt++) {
                int n0 = bn + warp_n*32 + nt*8 + 2*c;
                float v;
                v = eluf((acc[mt][nt][0] + bias[n0  ]) * colmul[(size_t)b0*cmStride + n0  ]); p0 += v*rvec[n0];
                v = eluf((acc[mt][nt][1] + bias[n0+1]) * colmul[(size_t)b0*cmStride + n0+1]); p0 += v*rvec[n0+1];
                v = eluf((acc[mt][nt][2] + bias[n0  ]) * colmul[(size_t)b1*cmStride + n0  ]); p1 += v*rvec[n0];
                v = eluf((acc[mt][nt][3] + bias[n0+1]) * colmul[(size_t)b1*cmStride + n0+1]); p1 += v*rvec[n0+1];
            }
            p0 += __shfl_xor_sync(0xffffffffu, p0, 1);
            p0 += __shfl_xor_sync(0xffffffffu, p0, 2);
            p1 += __shfl_xor_sync(0xffffffffu, p1, 1);
            p1 += __shfl_xor_sync(0xffffffffu, p1, 2);
            if (c == 0) { atomicAdd(&sred[mloc], p0); atomicAdd(&sred[mloc + 8], p1); }
        }
        __syncthreads();
        if (tid < 128)
            svec[(size_t)blockIdx.x * MKB + bm + tid] = sred[tid];
        return;
    }

    #pragma unroll
    for (int mt = 0; mt < 4; mt++) {
        int m0 = bm + warp_m*64 + mt*16 + r;
        #pragma unroll
        for (int nt = 0; nt < 4; nt++) {
            int n0 = bn + warp_n*32 + nt*8 + 2*c;
            #pragma unroll
            for (int half = 0; half < 2; half++) {
                int mm = m0 + half*8;
                float vx = acc[mt][nt][2*half], vy = acc[mt][nt][2*half+1];
                size_t gm = (size_t)mm*TGN + n0;
                if (MODE == 2) {
                    __nv_bfloat162 adh = *(const __nv_bfloat162*)(addh + gm);
                    __nv_bfloat162 adl = *(const __nv_bfloat162*)(addl + gm);
                    vx = eluf(vx + __bfloat162float(adh.x) + __bfloat162float(adl.x));
                    vy = eluf(vy + __bfloat162float(adh.y) + __bfloat162float(adl.y));
                } else { // MODE 4
                    vx += bias[n0]; vy += bias[n0+1];
                }
                bf16 hx, lx, hy, ly;
                splitbf(vx, hx, lx); splitbf(vy, hy, ly);
                *(__nv_bfloat162*)(Chi + gm) = __nv_bfloat162(hx, hy);
                *(__nv_bfloat162*)(Clo + gm) = __nv_bfloat162(lx, ly);
            }
        }
    }
}

// ---------------- split / helper kernels -------------------------------------
__global__ void splitbf_k(const float* __restrict__ src,
                          bf16* __restrict__ hi, bf16* __restrict__ lo, size_t n)
{
    size_t i = ((size_t)blockIdx.x * blockDim.x + threadIdx.x) * 4;
    if (i >= n) return;
    float4 v = *(const float4*)(src + i);
    bf16 h0,l0,h1,l1,h2,l2,h3,l3;
    splitbf(v.x,h0,l0); splitbf(v.y,h1,l1); splitbf(v.z,h2,l2); splitbf(v.w,h3,l3);
    *(__nv_bfloat162*)(hi + i)     = __nv_bfloat162(h0, h1);
    *(__nv_bfloat162*)(hi + i + 2) = __nv_bfloat162(h2, h3);
    *(__nv_bfloat162*)(lo + i)     = __nv_bfloat162(l0, l1);
    *(__nv_bfloat162*)(lo + i + 2) = __nv_bfloat162(l2, l3);
}

__global__ void scale_split_k(const bf16* __restrict__ kph,
                              const bf16* __restrict__ kpl,
                              const float* __restrict__ mp,
                              bf16* __restrict__ hi, bf16* __restrict__ lo)
{
    size_t i = ((size_t)blockIdx.x * blockDim.x + threadIdx.x) * 4;
    if (i >= (size_t)MKB * Dd) return;
    int m = (int)(i >> 9);
    int d = (int)(i & 511);
    int b = m / KBsz;
    __nv_bfloat162 h01 = *(const __nv_bfloat162*)(kph + i);
    __nv_bfloat162 h23 = *(const __nv_bfloat162*)(kph + i + 2);
    __nv_bfloat162 l01 = *(const __nv_bfloat162*)(kpl + i);
    __nv_bfloat162 l23 = *(const __nv_bfloat162*)(kpl + i + 2);
    float4 s = *(const float4*)(mp + (size_t)b * Dd + d);
    float v0 = (__bfloat162float(h01.x) + __bfloat162float(l01.x)) * s.x;
    float v1 = (__bfloat162float(h01.y) + __bfloat162float(l01.y)) * s.y;
    float v2 = (__bfloat162float(h23.x) + __bfloat162float(l23.x)) * s.z;
    float v3 = (__bfloat162float(h23.y) + __bfloat162float(l23.y)) * s.w;
    bf16 h0,l0,h1,l1,h2,l2,h3,l3;
    splitbf(v0,h0,l0); splitbf(v1,h1,l1); splitbf(v2,h2,l2); splitbf(v3,h3,l3);
    *(__nv_bfloat162*)(hi + i)     = __nv_bfloat162(h0, h1);
    *(__nv_bfloat162*)(hi + i + 2) = __nv_bfloat162(h2, h3);
    *(__nv_bfloat162*)(lo + i)     = __nv_bfloat162(l0, l1);
    *(__nv_bfloat162*)(lo + i + 2) = __nv_bfloat162(l2, l3);
}

// r[n] = vec[k] dot W[k][n] + b[n]   (512x512 W, 512 vec)
__global__ void vecmat_k(const float* __restrict__ vec,
                         const float* __restrict__ W,
                         const float* __restrict__ b,
                         float* __restrict__ r)
{
    int n = blockIdx.x * blockDim.x + threadIdx.x;
    if (n >= Dd) return;
    float a = b[n];
    for (int k = 0; k < Dd; k++) a += vec[k] * W[(size_t)k * Dd + n];
    r[n] = a;
}

__global__ void copyf_k(const float* __restrict__ src, float* __restrict__ dst, int n)
{
    int i = (blockIdx.x * blockDim.x + threadIdx.x) * 4;
    if (i < n) *(float4*)(dst + i) = *(const float4*)(src + i);
}

// =====================  small FFMA2 GEMM (64x128 tile)  ======================
__device__ __forceinline__ unsigned long long pack2(float lo, float hi) {
    unsigned long long r;
    asm("mov.b64 %0, {%1, %2};" : "=l"(r) : "f"(lo), "f"(hi));
    return r;
}
__device__ __forceinline__ void unpack2(unsigned long long v, float& lo, float& hi) {
    asm("mov.b64 {%0, %1}, %2;" : "=f"(lo), "=f"(hi) : "l"(v));
}
__device__ __forceinline__ void fma2(unsigned long long& d,
                                     unsigned long long a, unsigned long long b) {
    asm("fma.rn.f32x2 %0, %1, %2, %0;" : "+l"(d) : "l"(a), "l"(b));
}

#define SBM 64
#define SBN 128
#define BKK 16

// z-batched; A'[m,k] = (k < splitK ? A[m,k] : A2[m,k-splitK])
template<int MODE>
__global__ __launch_bounds__(256)
void sgemm_k(const float* __restrict__ A, int lda,
             const float* __restrict__ A2, int lda2, int splitK,
             const float* __restrict__ W,
             const float* __restrict__ bias,
             float* __restrict__ C,
             int M, int K, int N,
             size_t strideA, size_t strideW, size_t strideBias, size_t strideC)
{
    A    += (size_t)blockIdx.z * strideA;
    A2   += (size_t)blockIdx.z * strideA;
    W    += (size_t)blockIdx.z * strideW;
    bias += (size_t)blockIdx.z * strideBias;
    C    += (size_t)blockIdx.z * strideC;

    __shared__ float As[BKK][SBM];
    __shared__ float Bs[BKK][SBN];

    const int bm = blockIdx.y * SBM;
    const int bn = blockIdx.x * SBN;
    const int tid = threadIdx.x;
    const int ty = tid >> 5;        // 0..7
    const int tx = tid & 31;        // 0..31

    unsigned long long acc2[8][2];
    #pragma unroll
    for (int i = 0; i < 8; i++) { acc2[i][0] = 0ull; acc2[i][1] = 0ull; }

    for (int k0 = 0; k0 < K; k0 += BKK) {
        {
            int e   = tid;              // 0..255
            int row = e >> 2;           // 0..63
            int kq  = (e & 3) * 4;
            int m   = bm + row;
            int k   = k0 + kq;
            const float* src = (k < splitK)
                ? (A  + (size_t)m * lda  + k)
                : (A2 + (size_t)m * lda2 + (k - splitK));
            float4 v = *(const float4*)src;
            As[kq + 0][row] = v.x; As[kq + 1][row] = v.y;
            As[kq + 2][row] = v.z; As[kq + 3][row] = v.w;
        }
        #pragma unroll
        for (int e2 = 0; e2 < 2; e2++) {
            int e   = tid * 2 + e2;
            int row = e >> 5;
            int cc  = (e & 31) * 4;
            float4 v = *(const float4*)(W + (size_t)(k0 + row) * N + bn + cc);
            *(float4*)&Bs[row][cc] = v;
        }
        __syncthreads();
        #pragma unroll
        for (int kk = 0; kk < BKK; kk++) {
            float a[8];
            unsigned long long b2[2];
            #pragma unroll
            for (int i = 0; i < 8; i++) a[i] = As[kk][ty * 8 + i];
            b2[0] = *(const unsigned long long*)&Bs[kk][tx * 4];
            b2[1] = *(const unsigned long long*)&Bs[kk][tx * 4 + 2];
            #pragma unroll
            for (int i = 0; i < 8; i++) {
                unsigned long long pa = pack2(a[i], a[i]);
                fma2(acc2[i][0], pa, b2[0]);
                fma2(acc2[i][1], pa, b2[1]);
            }
        }
        __syncthreads();
    }

    #pragma unroll
    for (int i = 0; i < 8; i++) {
        int m = bm + ty * 8 + i;
        int n = bn + tx * 4;
        float4 v;
        unpack2(acc2[i][0], v.x, v.y);
        unpack2(acc2[i][1], v.z, v.w);
        v.x += bias[n]; v.y += bias[n+1]; v.z += bias[n+2]; v.w += bias[n+3];
        if (MODE == 1) { v.x = tanhf(v.x); v.y = tanhf(v.y); v.z = tanhf(v.z); v.w = tanhf(v.w); }
        *(float4*)(C + (size_t)m * N + n) = v;
    }
}

// ---------------- attention / misc kernels (validated) -----------------------
__global__ void word_attn_k(const float* __restrict__ qall,
                            const float* __restrict__ qword,
                            const float* __restrict__ caw,
                            float* __restrict__ ch)
{
    int b = blockIdx.x, s = blockIdx.y;
    __shared__ float qs[Dd];
    __shared__ float lg[Ll];
    int tid = threadIdx.x;
    for (int d = tid; d < Dd; d += 256)
        qs[d] = qall[((size_t)s * Bsz + b) * Dd + d] * caw[d];
    __syncthreads();
    int wid = tid >> 5, lane = tid & 31;
    for (int l = wid; l < Ll; l += 8) {
        const float* qw = qword + ((size_t)b * Ll + l) * Dd;
        float a = 0.f;
        for (int d = lane; d < Dd; d += 32) a += qs[d] * qw[d];
        #pragma unroll
        for (int o = 16; o; o >>= 1) a += __shfl_xor_sync(0xffffffffu, a, o);
        if (lane == 0) lg[l] = a;
    }
    __syncthreads();
    if (tid == 0) {
        float mx = -INFINITY;
        for (int l = 0; l < Ll; l++) mx = fmaxf(mx, lg[l]);
        float sm = 0.f;
        for (int l = 0; l < Ll; l++) { float e = expf(lg[l] - mx); lg[l] = e; sm += e; }
        float inv = 1.f / sm;
        for (int l = 0; l < Ll; l++) lg[l] *= inv;
    }
    __syncthreads();
    for (int d = tid; d < Dd; d += 256) {
        float a = 0.f;
        for (int l = 0; l < Ll; l++) a += lg[l] * qword[((size_t)b * Ll + l) * Dd + d];
        ch[((size_t)b * Ss + s) * Dd + d] = a;
    }
}

__global__ void norm_k(const float* __restrict__ chkey, float* __restrict__ normed)
{
    int i = blockIdx.x * blockDim.x + threadIdx.x;
    if (i >= BD) return;
    int b = i >> 9, d = i & 511;
    size_t base = (size_t)b * Ss * Dd + d;
    float ss = 0.f;
    #pragma unroll
    for (int s = 0; s < Ss; s++) { float v = chkey[base + s * Dd]; ss += v * v; }
    float inv = 1.f / sqrtf(ss);
    #pragma unroll
    for (int s = 0; s < Ss; s++) normed[base + s * Dd] = chkey[base + s * Dd] * inv;
}

__global__ void gram_k(const float* __restrict__ normed, float* __restrict__ Amat)
{
    int tb = blockIdx.x, i = blockIdx.y;
    __shared__ float Ki[Dd];
    __shared__ float lg[TS];
    int tid = threadIdx.x;
    int ti = i / Ss, si = i % Ss;
    size_t rowi = ((size_t)(ti * TBsz + tb) * Ss + si) * Dd;
    for (int d = tid; d < Dd; d += 256) Ki[d] = normed[rowi + d];
    __syncthreads();
    int wid = tid >> 5, lane = tid & 31;
    for (int j = wid; j < TS; j += 8) {
        float a;
        if (j > i) a = -1e30f;
        else {
            int tj = j / Ss, sj = j % Ss;
            size_t rowj = ((size_t)(tj * TBsz + tb) * Ss + sj) * Dd;
            a = 0.f;
            for (int d = lane; d < Dd; d += 32) a += Ki[d] * normed[rowj + d];
            #pragma unroll
            for (int o = 16; o; o >>= 1) a += __shfl_xor_sync(0xffffffffu, a, o);
        }
        if (lane == 0) lg[j] = a;
    }
    __syncthreads();
    if (tid == 0) {
        float mx = -INFINITY;
        for (int j = 0; j < TS; j++) mx = fmaxf(mx, lg[j]);
        float sm = 0.f;
        for (int j = 0; j < TS; j++) { float e = expf(lg[j] - mx); lg[j] = e; sm += e; }
        float inv = 1.f / sm;
        for (int j = 0; j < TS; j++) lg[j] *= inv;
    }
    __syncthreads();
    if (tid < TS) Amat[((size_t)tb * TS + i) * TS + tid] = lg[tid];
}

__global__ void attv_k(const float* __restrict__ Amat,
                       const float* __restrict__ chval,
                       float* __restrict__ att)
{
    int tb = blockIdx.x, i = blockIdx.y;
    __shared__ float aw[TS];
    int tid = threadIdx.x;
    if (tid < TS) aw[tid] = Amat[((size_t)tb * TS + i) * TS + tid];
    __syncthreads();
    int ti = i / Ss, si = i % Ss;
    for (int d = tid; d < Dd; d += 256) {
        float a = 0.f;
        for (int j = 0; j <= i; j++) {
            int tj = j / Ss, sj = j % Ss;
            a += aw[j] * chval[((size_t)(tj * TBsz + tb) * Ss + sj) * Dd + d];
        }
        att[((size_t)(ti * TBsz + tb) * Ss + si) * Dd + d] = a;
    }
}

__global__ void bcast_k(const float* __restrict__ src, float* __restrict__ dst)
{
    int i = blockIdx.x * blockDim.x + threadIdx.x;
    if (i < BD) dst[i] = src[i & 511];
}

// softmax over KB (summing 4 N-slice partials, parallel reductions)
// + vectorized weighted read of knowledge
__global__ void read_k(const float* __restrict__ s4,
                       const float* __restrict__ knowledge,
                       float* __restrict__ readv)
{
    int b = blockIdx.x;
    int tid = threadIdx.x;              // 256
    int wid = tid >> 5, lane = tid & 31;
    __shared__ float sv[KBsz];
    __shared__ float wred[8];

    float x = -1e30f;
    if (tid < KBsz) {
        size_t base = (size_t)b * KBsz + tid;
        x = s4[base] + s4[(size_t)MKB + base]
          + s4[2*(size_t)MKB + base] + s4[3*(size_t)MKB + base];
    }
    // block max
    float m = x;
    #pragma unroll
    for (int o = 16; o; o >>= 1) m = fmaxf(m, __shfl_xor_sync(0xffffffffu, m, o));
    if (lane == 0) wred[wid] = m;
    __syncthreads();
    if (tid == 0) {
        float mm = wred[0];
        #pragma unroll
        for (int w = 1; w < 8; w++) mm = fmaxf(mm, wred[w]);
        wred[0] = mm;
    }
    __syncthreads();
    float mx = wred[0];
    float e = (tid < KBsz) ? expf(x - mx) : 0.f;
    // block sum
    float s = e;
    #pragma unroll
    for (int o = 16; o; o >>= 1) s += __shfl_xor_sync(0xffffffffu, s, o);
    __syncthreads();
    if (lane == 0) wred[wid] = s;
    __syncthreads();
    if (tid == 0) {
        float ss = 0.f;
        #pragma unroll
        for (int w = 0; w < 8; w++) ss += wred[w];
        wred[0] = 1.f / ss;
    }
    __syncthreads();
    if (tid < KBsz) sv[tid] = e * wred[0];
    __syncthreads();

    // gather: 128 threads, one float4 column each, k unrolled
    if (tid < 128) {
        const float4* kn = (const float4*)(knowledge + (size_t)b * KBsz * Dd);
        float4 acc = make_float4(0.f, 0.f, 0.f, 0.f);
        int k = 0;
        #pragma unroll 4
        for (; k + 4 <= KBsz; k += 4) {
            #pragma unroll
            for (int u = 0; u < 4; u++) {
                float w = sv[k + u];
                float4 t = kn[(size_t)(k + u) * 128 + tid];
                acc.x += w * t.x; acc.y += w * t.y;
                acc.z += w * t.z; acc.w += w * t.w;
            }
        }
        for (; k < KBsz; k++) {
            float w = sv[k];
            float4 t = kn[(size_t)k * 128 + tid];
            acc.x += w * t.x; acc.y += w * t.y;
            acc.z += w * t.z; acc.w += w * t.w;
        }
        ((float4*)(readv + (size_t)b * Dd))[tid] = acc;
    }
}

__global__ void out_k(const float* __restrict__ mem,
                      const float* __restrict__ att,
                      float* __restrict__ out, int out_size)
{
    int i = blockIdx.x * blockDim.x + threadIdx.x;
    if (i >= BD) return;
    if (i < out_size) out[i] = mem[i];
    if (out_size >= 2 * BD) {
        int b = i >> 9, d = i & 511;
        out[BD + i] = att[((size_t)b * Ss + (Ss - 1)) * Dd + d];
    }
}

// ---------------- launch -----------------------------------------------------
static float* symf(const void* s) { void* p = nullptr; cudaGetSymbolAddress(&p, s); return (float*)p; }
static bf16*  symb(const void* s) { void* p = nullptr; cudaGetSymbolAddress(&p, s); return (bf16*)p; }

#define TG_SMEM (int)((NSTG*2*A_ST + NSTG*2*B_ST) * sizeof(bf16))

extern "C" void kernel_launch(void* const* d_in, const int* in_sizes, int n_in,
                              void* d_out, int out_size)
{
    const float* qword     = (const float*)d_in[0];
    const float* qemb      = (const float*)d_in[1];
    const float* knowledge = (const float*)d_in[2];
    const float* ci_w     = (const float*)d_in[4];
    const float* ci_b     = (const float*)d_in[5];
    const float* ciu_w    = (const float*)d_in[6];
    const float* ciu_b    = (const float*)d_in[7];
    const float* ca_w     = (const float*)d_in[8];
    const float* kproj_w  = (const float*)d_in[10];
    const float* kproj_b  = (const float*)d_in[11];
    const float* mproj_w  = (const float*)d_in[12];
    const float* mproj_b  = (const float*)d_in[13];
    const float* concat_w = (const float*)d_in[14];
    const float* concat_b = (const float*)d_in[15];
    const float* concat2_w= (const float*)d_in[16];
    const float* concat2_b= (const float*)d_in[17];
    const float* rattn_w  = (const float*)d_in[18];
    const float* write_w  = (const float*)d_in[20];
    const float* write_b  = (const float*)d_in[21];
    const float* init_mem = (const float*)d_in[22];
    const float* kq_w     = (const float*)d_in[23];
    const float* kq_b     = (const float*)d_in[24];
    const float* val_w    = (const float*)d_in[25];
    const float* val_b    = (const float*)d_in[26];
    float* out = (float*)d_out;

    float* q0     = symf(g_q0);
    float* qall   = symf(g_qall);
    float* ch     = symf(g_ch);
    float* chkey  = symf(g_chkey);
    float* chval  = symf(g_chval);
    float* normed = symf(g_normed);
    float* Amat   = symf(g_Amat);
    float* att    = symf(g_att);
    bf16*  kph    = symb(g_kph);
    bf16*  kpl    = symb(g_kpl);
    bf16*  kp2h   = symb(g_kp2h);
    bf16*  kp2l   = symb(g_kp2l);
    bf16*  e1h    = symb(g_e1h);
    bf16*  e1l    = symb(g_e1l);
    bf16*  ahb    = symb(g_ah);
    bf16*  alb    = symb(g_al);
    bf16*  knh    = symb(g_knh);
    bf16*  knl    = symb(g_knl);
    bf16*  wbh    = symb(g_wbh);
    bf16*  wbl    = symb(g_wbl);
    float* s4     = symf(g_s4);
    float* readv  = symf(g_read);
    float* Wcat   = symf(g_Wcat);
    float* biascat= symf(g_biascat);
    float* zerov  = symf(g_zero);
    float* tmp512 = symf(g_tmp512);
    float* zbuf   = symf(g_zbuf);

    static bool init_done = false;
    static cudaStream_t s2 = nullptr;
    static cudaEvent_t evFork = nullptr, evJoin = nullptr;
    if (!init_done) {
        cudaFuncSetAttribute(tgemm_k<2>, cudaFuncAttributeMaxDynamicSharedMemorySize, TG_SMEM);
        cudaFuncSetAttribute(tgemm_k<3>, cudaFuncAttributeMaxDynamicSharedMemorySize, TG_SMEM);
        cudaFuncSetAttribute(tgemm_k<4>, cudaFuncAttributeMaxDynamicSharedMemorySize, TG_SMEM);
        cudaStreamCreateWithFlags(&s2, cudaStreamNonBlocking);
        cudaEventCreateWithFlags(&evFork, cudaEventDisableTiming);
        cudaEventCreateWithFlags(&evJoin, cudaEventDisableTiming);
        init_done = true;
    }

    auto Gs = [](int M, int N, int Z) { return dim3(N / SBN, M / SBM, Z); };
    const dim3 GT(Dd / 128, MKB / 128);
    const float* NPF = nullptr;
    bf16* NPB = nullptr;

    // ---- fork ----
    cudaEventRecord(evFork, 0);
    cudaStreamWaitEvent(s2, evFork, 0);

    {   // stream s2: splits + kp + kp2 + write/mproj fusion prep + init state
        size_t nk = (size_t)MKB * Dd;
        splitbf_k<<<(unsigned)((nk / 4 + 255) / 256), 256, 0, s2>>>(knowledge, knh, knl, nk);
        size_t nw = (size_t)Dd * Dd;
        splitbf_k<<<(unsigned)((nw / 4 + 255) / 256), 256, 0, s2>>>(kproj_w,  wbh + 0*Dd*Dd, wbl + 0*Dd*Dd, nw);
        splitbf_k<<<(unsigned)((2*nw / 4 + 255) / 256), 256, 0, s2>>>(concat_w, wbh + 1*Dd*Dd, wbl + 1*Dd*Dd, 2*nw);
        splitbf_k<<<(unsigned)((nw / 4 + 255) / 256), 256, 0, s2>>>(concat2_w, wbh + 3*Dd*Dd, wbl + 3*Dd*Dd, nw);
        // kp / kp2 (split-only outputs)
        tgemm_k<4><<<GT, 256, TG_SMEM, s2>>>(knh, knl, wbh + 0*Dd*Dd, wbl + 0*Dd*Dd,
                                             kproj_b, kph, kpl, NPB, NPB, NPF, 0, NPF, nullptr);
        tgemm_k<4><<<GT, 256, TG_SMEM, s2>>>(kph, kpl, wbh + 2*Dd*Dd, wbl + 2*Dd*Dd,
                                             concat_b, kp2h, kp2l, NPB, NPB, NPF, 0, NPF, nullptr);
        // W2 = write_w @ mproj_w into Wcat[1]; Wcat[0] = write_w
        sgemm_k<0><<<Gs(2*Dd, Dd, 1), 256, 0, s2>>>(write_w, Dd, write_w, Dd, Dd,
                                                    mproj_w, zerov, Wcat + (size_t)2*Dd*Dd,
                                                    2*Dd, Dd, Dd, 0, 0, 0, 0);
        copyf_k<<<(2*Dd*Dd / 4 + 255) / 256, 256, 0, s2>>>(write_w, Wcat, 2*Dd*Dd);
        copyf_k<<<(Dd / 4 + 255) / 256, 256, 0, s2>>>(write_b, biascat, Dd);
        vecmat_k<<<2, 256, 0, s2>>>(write_b, mproj_w, mproj_b, biascat + Dd);   // bias2
        // init state in zbuf[p=0]: memory0 + mp0
        bcast_k<<<(BD + 255) / 256, 256, 0, s2>>>(init_mem, zbuf);              // memory0
        vecmat_k<<<2, 256, 0, s2>>>(init_mem, mproj_w, mproj_b, tmp512);        // mp0 row
        bcast_k<<<(BD + 255) / 256, 256, 0, s2>>>(tmp512, zbuf + BD);           // mp0
    }
    cudaEventRecord(evJoin, s2);

    // default stream: question path
    sgemm_k<1><<<Gs(Bsz, Dd, 1), 256>>>(qemb, Dd, qemb, Dd, Dd, ci_w, ci_b, q0,
                                        Bsz, Dd, Dd, 0, 0, 0, 0);
    sgemm_k<0><<<Gs(Bsz, Dd, Ss), 256>>>(q0, Dd, q0, Dd, Dd, ciu_w, ciu_b, qall,
                                         Bsz, Dd, Dd,
                                         0, (size_t)Dd * Dd, Dd, (size_t)BD);
    word_attn_k<<<dim3(Bsz, Ss), 256>>>(qall, qword, ca_w, ch);
    sgemm_k<0><<<Gs(Bsz * Ss, Dd, 1), 256>>>(ch, Dd, ch, Dd, Dd, kq_w, kq_b, chkey,
                                             Bsz * Ss, Dd, Dd, 0, 0, 0, 0);
    sgemm_k<0><<<Gs(Bsz * Ss, Dd, 1), 256>>>(ch, Dd, ch, Dd, Dd, val_w, val_b, chval,
                                             Bsz * Ss, Dd, Dd, 0, 0, 0, 0);
    norm_k<<<(BD + 255) / 256, 256>>>(chkey, normed);
    gram_k<<<dim3(TBsz, TS), 256>>>(normed, Amat);
    attv_k<<<dim3(TBsz, TS), 256>>>(Amat, chval, att);

    cudaStreamWaitEvent(0, evJoin, 0);

    int p = 0;
    for (int i = 0; i < Ss; i++) {
        float* mcur = zbuf + (size_t)p * 2 * BD;
        float* mpcur = mcur + BD;
        {
            size_t nk = (size_t)MKB * Dd;
            scale_split_k<<<(unsigned)((nk / 4 + 255) / 256), 256>>>(kph, kpl, mpcur, ahb, alb);
        }
        tgemm_k<2><<<GT, 256, TG_SMEM>>>(ahb, alb, wbh + 1*Dd*Dd, wbl + 1*Dd*Dd,
                                         NPF, e1h, e1l, kp2h, kp2l, NPF, 0, NPF, nullptr);
        tgemm_k<3><<<GT, 256, TG_SMEM>>>(e1h, e1l, wbh + 3*Dd*Dd, wbl + 3*Dd*Dd,
                                         concat2_b, NPB, NPB, NPB, NPB,
                                         att + (size_t)i * Dd, Ss * Dd, rattn_w, s4);
        read_k<<<Bsz, 256>>>(s4, knowledge, readv);
        // z=0: memory' = [mcur, read]@write_w + write_b
        // z=1: mp'     = [mcur, read]@W2      + bias2
        sgemm_k<0><<<Gs(Bsz, Dd, 2), 256>>>(mcur, Dd, readv, Dd, Dd,
                                            Wcat, biascat,
                                            zbuf + (size_t)(p ^ 1) * 2 * BD,
                                            Bsz, 2 * Dd, Dd,
                                            0, (size_t)2*Dd*Dd, Dd, (size_t)BD);
        p ^= 1;
    }

    out_k<<<(BD + 255) / 256, 256>>>(zbuf + (size_t)p * 2 * BD, att, out, out_size);
}

// round 13
// speedup vs baseline: 3.6802x; 1.2507x over previous
#include <cuda_runtime.h>
#include <cuda_fp16.h>
#include <math.h>

// Problem constants
#define Bsz 640
#define Dd 512
#define Ss 4
#define Tt 10
#define TBsz 64
#define Ll 30
#define KBsz 196
#define MKB (Bsz*KBsz)   // 125440
#define TS 40            // T*S
#define BD (Bsz*Dd)

typedef __half hf;

// ---------------- scratch (static device globals; no allocations) ----------
__device__ float g_q0[BD];
__device__ float g_qall[Ss*BD];
__device__ float g_ch[Bsz*Ss*Dd];
__device__ float g_chkey[Bsz*Ss*Dd];
__device__ float g_chval[Bsz*Ss*Dd];
__device__ float g_normed[Bsz*Ss*Dd];
__device__ float g_Amat[TBsz*TS*TS];
__device__ float g_att[Bsz*Ss*Dd];
__device__ hf    g_kph[(size_t)MKB*Dd];
__device__ hf    g_kpl[(size_t)MKB*Dd];
__device__ hf    g_kp2h[(size_t)MKB*Dd];
__device__ hf    g_kp2l[(size_t)MKB*Dd];
__device__ hf    g_e1h[(size_t)MKB*Dd];
__device__ hf    g_e1l[(size_t)MKB*Dd];
__device__ hf    g_ah [(size_t)MKB*Dd];
__device__ hf    g_al [(size_t)MKB*Dd];
__device__ hf    g_knh[(size_t)MKB*Dd];
__device__ hf    g_knl[(size_t)MKB*Dd];
__device__ hf    g_wb[4][Dd*Dd];             // weights, single fp16
__device__ float g_s4[4*(size_t)MKB];        // score partials per N-slice
__device__ float g_read[BD];
__device__ float g_Wcat[2][2*Dd*Dd];         // [0]=write_w copy, [1]=W2=write_w@mproj_w
__device__ float g_biascat[2][Dd];           // [0]=write_b copy, [1]=bias2
__device__ float g_zero[Dd];                 // stays zero (.bss)
__device__ float g_tmp512[Dd];
__device__ float g_zbuf[4*BD];               // [p][q][BD]: q=0 memory, q=1 mp

__device__ __forceinline__ float eluf(float x){ return x > 0.f ? x : expm1f(x); }

__device__ __forceinline__ void splith(float x, hf& h, hf& l){
    h = __float2half_rn(x);
    l = __float2half_rn(x - __half2float(h));
}

__device__ __forceinline__ void mma_f16(float* cc, const unsigned* a, const unsigned* b){
    asm("mma.sync.aligned.m16n8k16.row.col.f32.f16.f16.f32 "
        "{%0,%1,%2,%3}, {%4,%5,%6,%7}, {%8,%9}, {%0,%1,%2,%3};"
        : "+f"(cc[0]), "+f"(cc[1]), "+f"(cc[2]), "+f"(cc[3])
        : "r"(a[0]), "r"(a[1]), "r"(a[2]), "r"(a[3]), "r"(b[0]), "r"(b[1]));
}
__device__ __forceinline__ void ldm4(unsigned* r, const hf* p){
    unsigned addr = (unsigned)__cvta_generic_to_shared(p);
    asm volatile("ldmatrix.sync.aligned.m8n8.x4.shared.b16 {%0,%1,%2,%3}, [%4];"
                 : "=r"(r[0]), "=r"(r[1]), "=r"(r[2]), "=r"(r[3]) : "r"(addr));
}
__device__ __forceinline__ void ldm4t(unsigned* r, const hf* p){
    unsigned addr = (unsigned)__cvta_generic_to_shared(p);
    asm volatile("ldmatrix.sync.aligned.m8n8.x4.trans.shared.b16 {%0,%1,%2,%3}, [%4];"
                 : "=r"(r[0]), "=r"(r[1]), "=r"(r[2]), "=r"(r[3]) : "r"(addr));
}
__device__ __forceinline__ void cpa16(void* sdst, const void* gsrc){
    unsigned s = (unsigned)__cvta_generic_to_shared(sdst);
    asm volatile("cp.async.cg.shared.global [%0], [%1], 16;" :: "r"(s), "l"(gsrc));
}
__device__ __forceinline__ void cpa_commit(){ asm volatile("cp.async.commit_group;"); }

// =============  big tensor-core GEMM: fp16 2-pass (A hi/lo, B single)  =======
// MODE 2: t = elu(acc + (addh+addl)); Chi/Clo = splith(t)
// MODE 3: svec[slice][m] = sum_n elu((acc+bias[n])*colmul[(m/KB)*cmStride+n])*rvec[n]
// MODE 4: v = acc + bias; Chi/Clo = splith(v)
#define TGK 512
#define TGN 512
#define TBK 32
#define NKIT (TGK/TBK)
#define NSTG 2
#define ALD 40
#define BLD 136
#define A_ST (128*ALD)
#define B_ST (TBK*BLD)

template<int MODE>
__global__ __launch_bounds__(256, 2)
void tgemm_k(const hf* __restrict__ Ahg, const hf* __restrict__ Alg,
             const hf* __restrict__ Bg,
             const float* __restrict__ bias,
             hf* __restrict__ Chi, hf* __restrict__ Clo,
             const hf* __restrict__ addh, const hf* __restrict__ addl,
             const float* __restrict__ colmul, int cmStride,
             const float* __restrict__ rvec, float* __restrict__ svec)
{
    extern __shared__ hf smem[];
    hf* Abase = smem;                        // [NSTG][2][128][ALD]
    hf* Bbase = smem + NSTG*2*A_ST;          // [NSTG][TBK][BLD]

    const int bm = blockIdx.y * 128;
    const int bn = blockIdx.x * 128;
    const int tid = threadIdx.x;
    const int wid = tid >> 5, lane = tid & 31;
    const int warp_m = wid & 1;
    const int warp_n = wid >> 1;
    const int r = lane >> 2, c = lane & 3;
    const int lrow = lane & 15, lcol = (lane >> 4) * 8;

    float acc[4][4][4];
    #pragma unroll
    for (int i = 0; i < 4; i++)
        #pragma unroll
        for (int j = 0; j < 4; j++)
            #pragma unroll
            for (int q = 0; q < 4; q++) acc[i][j][q] = 0.f;

    auto do_copy = [&](int k0, int st){
        const hf* Ag[2] = { Ahg, Alg };
        #pragma unroll
        for (int h = 0; h < 2; h++) {
            hf* As = Abase + (st*2 + h) * A_ST;
            #pragma unroll
            for (int e2 = 0; e2 < 2; e2++) {
                int e   = tid * 2 + e2;
                int row = e >> 2;
                int seg = (e & 3) * 8;
                cpa16(As + row * ALD + seg,
                      Ag[h] + (size_t)(bm + row) * TGK + k0 * TBK + seg);
            }
        }
        {
            hf* Bs = Bbase + st * B_ST;
            #pragma unroll
            for (int e2 = 0; e2 < 2; e2++) {
                int e   = tid * 2 + e2;
                int row = e >> 4;
                int seg = (e & 15) * 8;
                cpa16(Bs + row * BLD + seg,
                      Bg + (size_t)(k0 * TBK + row) * TGN + bn + seg);
            }
        }
        cpa_commit();
    };

    do_copy(0, 0);

    for (int k0 = 0; k0 < NKIT; k0++) {
        int st = k0 & 1;
        asm volatile("cp.async.wait_group 0;" ::: "memory");
        __syncthreads();
        if (k0 + 1 < NKIT) do_copy(k0 + 1, st ^ 1);

        const hf* Ash = Abase + (st*2 + 0) * A_ST;
        const hf* Asl = Abase + (st*2 + 1) * A_ST;
        const hf* Bsh = Bbase + st * B_ST;

        #pragma unroll
        for (int ks = 0; ks < 2; ks++) {
            unsigned ah[4][4], al[4][4], bh[4][2];
            int rr = ks * 16 + lrow;
            int cbase = warp_n * 32 + lcol;
            #pragma unroll
            for (int mt = 0; mt < 4; mt++) {
                int row = warp_m * 64 + mt * 16 + lrow;
                ldm4(ah[mt], Ash + row * ALD + ks * 16 + lcol);
            }
            #pragma unroll
            for (int p = 0; p < 2; p++) {
                unsigned t[4];
                ldm4t(t, Bsh + rr * BLD + cbase + p * 16);
                bh[2*p][0] = t[0]; bh[2*p][1] = t[1];
                bh[2*p+1][0] = t[2]; bh[2*p+1][1] = t[3];
            }
            #pragma unroll
            for (int mt = 0; mt < 4; mt++)
                #pragma unroll
                for (int nt = 0; nt < 4; nt++)
                    mma_f16(acc[mt][nt], ah[mt], bh[nt]);    // hi * B
            #pragma unroll
            for (int mt = 0; mt < 4; mt++) {
                int row = warp_m * 64 + mt * 16 + lrow;
                ldm4(al[mt], Asl + row * ALD + ks * 16 + lcol);
            }
            #pragma unroll
            for (int mt = 0; mt < 4; mt++)
                #pragma unroll
                for (int nt = 0; nt < 4; nt++)
                    mma_f16(acc[mt][nt], al[mt], bh[nt]);    // lo * B
        }
    }
    __syncthreads();

    if (MODE == 3) {
        __shared__ float sred[128];
        if (tid < 128) sred[tid] = 0.f;
        __syncthreads();
        #pragma unroll
        for (int mt = 0; mt < 4; mt++) {
            int mloc = warp_m*64 + mt*16 + r;
            int m0 = bm + mloc;
            int b0 = m0 / KBsz;
            int b1 = (m0 + 8) / KBsz;
            float p0 = 0.f, p1 = 0.f;
            #pragma unroll
            for (int nt = 0; nt < 4; nt++) {
                int n0 = bn + warp_n*32 + nt*8 + 2*c;
                float v;
                v = eluf((acc[mt][nt][0] + bias[n0  ]) * colmul[(size_t)b0*cmStride + n0  ]); p0 += v*rvec[n0];
                v = eluf((acc[mt][nt][1] + bias[n0+1]) * colmul[(size_t)b0*cmStride + n0+1]); p0 += v*rvec[n0+1];
                v = eluf((acc[mt][nt][2] + bias[n0  ]) * colmul[(size_t)b1*cmStride + n0  ]); p1 += v*rvec[n0];
                v = eluf((acc[mt][nt][3] + bias[n0+1]) * colmul[(size_t)b1*cmStride + n0+1]); p1 += v*rvec[n0+1];
            }
            p0 += __shfl_xor_sync(0xffffffffu, p0, 1);
            p0 += __shfl_xor_sync(0xffffffffu, p0, 2);
            p1 += __shfl_xor_sync(0xffffffffu, p1, 1);
            p1 += __shfl_xor_sync(0xffffffffu, p1, 2);
            if (c == 0) { atomicAdd(&sred[mloc], p0); atomicAdd(&sred[mloc + 8], p1); }
        }
        __syncthreads();
        if (tid < 128)
            svec[(size_t)blockIdx.x * MKB + bm + tid] = sred[tid];
        return;
    }

    #pragma unroll
    for (int mt = 0; mt < 4; mt++) {
        int m0 = bm + warp_m*64 + mt*16 + r;
        #pragma unroll
        for (int nt = 0; nt < 4; nt++) {
            int n0 = bn + warp_n*32 + nt*8 + 2*c;
            #pragma unroll
            for (int half = 0; half < 2; half++) {
                int mm = m0 + half*8;
                float vx = acc[mt][nt][2*half], vy = acc[mt][nt][2*half+1];
                size_t gm = (size_t)mm*TGN + n0;
                if (MODE == 2) {
                    __half2 adh = *(const __half2*)(addh + gm);
                    __half2 adl = *(const __half2*)(addl + gm);
                    vx = eluf(vx + __half2float(__low2half(adh)) + __half2float(__low2half(adl)));
                    vy = eluf(vy + __half2float(__high2half(adh)) + __half2float(__high2half(adl)));
                } else { // MODE 4
                    vx += bias[n0]; vy += bias[n0+1];
                }
                hf hx, lx, hy, ly;
                splith(vx, hx, lx); splith(vy, hy, ly);
                *(__half2*)(Chi + gm) = __halves2half2(hx, hy);
                *(__half2*)(Clo + gm) = __halves2half2(lx, ly);
            }
        }
    }
}

// ---------------- split / helper kernels -------------------------------------
__global__ void splith_k(const float* __restrict__ src,
                         hf* __restrict__ hi, hf* __restrict__ lo, size_t n)
{
    size_t i = ((size_t)blockIdx.x * blockDim.x + threadIdx.x) * 4;
    if (i >= n) return;
    float4 v = *(const float4*)(src + i);
    hf h0,l0,h1,l1,h2,l2,h3,l3;
    splith(v.x,h0,l0); splith(v.y,h1,l1); splith(v.z,h2,l2); splith(v.w,h3,l3);
    *(__half2*)(hi + i)     = __halves2half2(h0, h1);
    *(__half2*)(hi + i + 2) = __halves2half2(h2, h3);
    *(__half2*)(lo + i)     = __halves2half2(l0, l1);
    *(__half2*)(lo + i + 2) = __halves2half2(l2, l3);
}

__global__ void cvt16_k(const float* __restrict__ src, hf* __restrict__ dst, size_t n)
{
    size_t i = ((size_t)blockIdx.x * blockDim.x + threadIdx.x) * 4;
    if (i >= n) return;
    float4 v = *(const float4*)(src + i);
    *(__half2*)(dst + i)     = __halves2half2(__float2half_rn(v.x), __float2half_rn(v.y));
    *(__half2*)(dst + i + 2) = __halves2half2(__float2half_rn(v.z), __float2half_rn(v.w));
}

__global__ void scale_split_k(const hf* __restrict__ kph,
                              const hf* __restrict__ kpl,
                              const float* __restrict__ mp,
                              hf* __restrict__ hi, hf* __restrict__ lo)
{
    size_t i = ((size_t)blockIdx.x * blockDim.x + threadIdx.x) * 4;
    if (i >= (size_t)MKB * Dd) return;
    int m = (int)(i >> 9);
    int d = (int)(i & 511);
    int b = m / KBsz;
    __half2 h01 = *(const __half2*)(kph + i);
    __half2 h23 = *(const __half2*)(kph + i + 2);
    __half2 l01 = *(const __half2*)(kpl + i);
    __half2 l23 = *(const __half2*)(kpl + i + 2);
    float4 s = *(const float4*)(mp + (size_t)b * Dd + d);
    float v0 = (__half2float(__low2half(h01)) + __half2float(__low2half(l01))) * s.x;
    float v1 = (__half2float(__high2half(h01)) + __half2float(__high2half(l01))) * s.y;
    float v2 = (__half2float(__low2half(h23)) + __half2float(__low2half(l23))) * s.z;
    float v3 = (__half2float(__high2half(h23)) + __half2float(__high2half(l23))) * s.w;
    hf h0,l0,h1,l1,h2,l2,h3,l3;
    splith(v0,h0,l0); splith(v1,h1,l1); splith(v2,h2,l2); splith(v3,h3,l3);
    *(__half2*)(hi + i)     = __halves2half2(h0, h1);
    *(__half2*)(hi + i + 2) = __halves2half2(h2, h3);
    *(__half2*)(lo + i)     = __halves2half2(l0, l1);
    *(__half2*)(lo + i + 2) = __halves2half2(l2, l3);
}

// r[n] = vec[k] dot W[k][n] + b[n]   (512x512 W, 512 vec)
__global__ void vecmat_k(const float* __restrict__ vec,
                         const float* __restrict__ W,
                         const float* __restrict__ b,
                         float* __restrict__ r)
{
    int n = blockIdx.x * blockDim.x + threadIdx.x;
    if (n >= Dd) return;
    float a = b[n];
    for (int k = 0; k < Dd; k++) a += vec[k] * W[(size_t)k * Dd + n];
    r[n] = a;
}

__global__ void copyf_k(const float* __restrict__ src, float* __restrict__ dst, int n)
{
    int i = (blockIdx.x * blockDim.x + threadIdx.x) * 4;
    if (i < n) *(float4*)(dst + i) = *(const float4*)(src + i);
}

// =====================  small FFMA2 GEMM (64x128 tile)  ======================
__device__ __forceinline__ unsigned long long pack2(float lo, float hi) {
    unsigned long long r;
    asm("mov.b64 %0, {%1, %2};" : "=l"(r) : "f"(lo), "f"(hi));
    return r;
}
__device__ __forceinline__ void unpack2(unsigned long long v, float& lo, float& hi) {
    asm("mov.b64 {%0, %1}, %2;" : "=f"(lo), "=f"(hi) : "l"(v));
}
__device__ __forceinline__ void fma2(unsigned long long& d,
                                     unsigned long long a, unsigned long long b) {
    asm("fma.rn.f32x2 %0, %1, %2, %0;" : "+l"(d) : "l"(a), "l"(b));
}

#define SBM 64
#define SBN 128
#define BKK 16

template<int MODE>
__global__ __launch_bounds__(256)
void sgemm_k(const float* __restrict__ A, int lda,
             const float* __restrict__ A2, int lda2, int splitK,
             const float* __restrict__ W,
             const float* __restrict__ bias,
             float* __restrict__ C,
             int M, int K, int N,
             size_t strideA, size_t strideW, size_t strideBias, size_t strideC)
{
    A    += (size_t)blockIdx.z * strideA;
    A2   += (size_t)blockIdx.z * strideA;
    W    += (size_t)blockIdx.z * strideW;
    bias += (size_t)blockIdx.z * strideBias;
    C    += (size_t)blockIdx.z * strideC;

    __shared__ float As[BKK][SBM];
    __shared__ float Bs[BKK][SBN];

    const int bm = blockIdx.y * SBM;
    const int bn = blockIdx.x * SBN;
    const int tid = threadIdx.x;
    const int ty = tid >> 5;
    const int tx = tid & 31;

    unsigned long long acc2[8][2];
    #pragma unroll
    for (int i = 0; i < 8; i++) { acc2[i][0] = 0ull; acc2[i][1] = 0ull; }

    for (int k0 = 0; k0 < K; k0 += BKK) {
        {
            int e   = tid;
            int row = e >> 2;
            int kq  = (e & 3) * 4;
            int m   = bm + row;
            int k   = k0 + kq;
            const float* src = (k < splitK)
                ? (A  + (size_t)m * lda  + k)
                : (A2 + (size_t)m * lda2 + (k - splitK));
            float4 v = *(const float4*)src;
            As[kq + 0][row] = v.x; As[kq + 1][row] = v.y;
            As[kq + 2][row] = v.z; As[kq + 3][row] = v.w;
        }
        #pragma unroll
        for (int e2 = 0; e2 < 2; e2++) {
            int e   = tid * 2 + e2;
            int row = e >> 5;
            int cc  = (e & 31) * 4;
            float4 v = *(const float4*)(W + (size_t)(k0 + row) * N + bn + cc);
            *(float4*)&Bs[row][cc] = v;
        }
        __syncthreads();
        #pragma unroll
        for (int kk = 0; kk < BKK; kk++) {
            float a[8];
            unsigned long long b2[2];
            #pragma unroll
            for (int i = 0; i < 8; i++) a[i] = As[kk][ty * 8 + i];
            b2[0] = *(const unsigned long long*)&Bs[kk][tx * 4];
            b2[1] = *(const unsigned long long*)&Bs[kk][tx * 4 + 2];
            #pragma unroll
            for (int i = 0; i < 8; i++) {
                unsigned long long pa = pack2(a[i], a[i]);
                fma2(acc2[i][0], pa, b2[0]);
                fma2(acc2[i][1], pa, b2[1]);
            }
        }
        __syncthreads();
    }

    #pragma unroll
    for (int i = 0; i < 8; i++) {
        int m = bm + ty * 8 + i;
        int n = bn + tx * 4;
        float4 v;
        unpack2(acc2[i][0], v.x, v.y);
        unpack2(acc2[i][1], v.z, v.w);
        v.x += bias[n]; v.y += bias[n+1]; v.z += bias[n+2]; v.w += bias[n+3];
        if (MODE == 1) { v.x = tanhf(v.x); v.y = tanhf(v.y); v.z = tanhf(v.z); v.w = tanhf(v.w); }
        *(float4*)(C + (size_t)m * N + n) = v;
    }
}

// ---------------- attention / misc kernels (validated) -----------------------
__global__ void word_attn_k(const float* __restrict__ qall,
                            const float* __restrict__ qword,
                            const float* __restrict__ caw,
                            float* __restrict__ ch)
{
    int b = blockIdx.x, s = blockIdx.y;
    __shared__ float qs[Dd];
    __shared__ float lg[Ll];
    int tid = threadIdx.x;
    for (int d = tid; d < Dd; d += 256)
        qs[d] = qall[((size_t)s * Bsz + b) * Dd + d] * caw[d];
    __syncthreads();
    int wid = tid >> 5, lane = tid & 31;
    for (int l = wid; l < Ll; l += 8) {
        const float* qw = qword + ((size_t)b * Ll + l) * Dd;
        float a = 0.f;
        for (int d = lane; d < Dd; d += 32) a += qs[d] * qw[d];
        #pragma unroll
        for (int o = 16; o; o >>= 1) a += __shfl_xor_sync(0xffffffffu, a, o);
        if (lane == 0) lg[l] = a;
    }
    __syncthreads();
    if (tid == 0) {
        float mx = -INFINITY;
        for (int l = 0; l < Ll; l++) mx = fmaxf(mx, lg[l]);
        float sm = 0.f;
        for (int l = 0; l < Ll; l++) { float e = expf(lg[l] - mx); lg[l] = e; sm += e; }
        float inv = 1.f / sm;
        for (int l = 0; l < Ll; l++) lg[l] *= inv;
    }
    __syncthreads();
    for (int d = tid; d < Dd; d += 256) {
        float a = 0.f;
        for (int l = 0; l < Ll; l++) a += lg[l] * qword[((size_t)b * Ll + l) * Dd + d];
        ch[((size_t)b * Ss + s) * Dd + d] = a;
    }
}

__global__ void norm_k(const float* __restrict__ chkey, float* __restrict__ normed)
{
    int i = blockIdx.x * blockDim.x + threadIdx.x;
    if (i >= BD) return;
    int b = i >> 9, d = i & 511;
    size_t base = (size_t)b * Ss * Dd + d;
    float ss = 0.f;
    #pragma unroll
    for (int s = 0; s < Ss; s++) { float v = chkey[base + s * Dd]; ss += v * v; }
    float inv = 1.f / sqrtf(ss);
    #pragma unroll
    for (int s = 0; s < Ss; s++) normed[base + s * Dd] = chkey[base + s * Dd] * inv;
}

__global__ void gram_k(const float* __restrict__ normed, float* __restrict__ Amat)
{
    int tb = blockIdx.x, i = blockIdx.y;
    __shared__ float Ki[Dd];
    __shared__ float lg[TS];
    int tid = threadIdx.x;
    int ti = i / Ss, si = i % Ss;
    size_t rowi = ((size_t)(ti * TBsz + tb) * Ss + si) * Dd;
    for (int d = tid; d < Dd; d += 256) Ki[d] = normed[rowi + d];
    __syncthreads();
    int wid = tid >> 5, lane = tid & 31;
    for (int j = wid; j < TS; j += 8) {
        float a;
        if (j > i) a = -1e30f;
        else {
            int tj = j / Ss, sj = j % Ss;
            size_t rowj = ((size_t)(tj * TBsz + tb) * Ss + sj) * Dd;
            a = 0.f;
            for (int d = lane; d < Dd; d += 32) a += Ki[d] * normed[rowj + d];
            #pragma unroll
            for (int o = 16; o; o >>= 1) a += __shfl_xor_sync(0xffffffffu, a, o);
        }
        if (lane == 0) lg[j] = a;
    }
    __syncthreads();
    if (tid == 0) {
        float mx = -INFINITY;
        for (int j = 0; j < TS; j++) mx = fmaxf(mx, lg[j]);
        float sm = 0.f;
        for (int j = 0; j < TS; j++) { float e = expf(lg[j] - mx); lg[j] = e; sm += e; }
        float inv = 1.f / sm;
        for (int j = 0; j < TS; j++) lg[j] *= inv;
    }
    __syncthreads();
    if (tid < TS) Amat[((size_t)tb * TS + i) * TS + tid] = lg[tid];
}

__global__ void attv_k(const float* __restrict__ Amat,
                       const float* __restrict__ chval,
                       float* __restrict__ att)
{
    int tb = blockIdx.x, i = blockIdx.y;
    __shared__ float aw[TS];
    int tid = threadIdx.x;
    if (tid < TS) aw[tid] = Amat[((size_t)tb * TS + i) * TS + tid];
    __syncthreads();
    int ti = i / Ss, si = i % Ss;
    for (int d = tid; d < Dd; d += 256) {
        float a = 0.f;
        for (int j = 0; j <= i; j++) {
            int tj = j / Ss, sj = j % Ss;
            a += aw[j] * chval[((size_t)(tj * TBsz + tb) * Ss + sj) * Dd + d];
        }
        att[((size_t)(ti * TBsz + tb) * Ss + si) * Dd + d] = a;
    }
}

__global__ void bcast_k(const float* __restrict__ src, float* __restrict__ dst)
{
    int i = blockIdx.x * blockDim.x + threadIdx.x;
    if (i < BD) dst[i] = src[i & 511];
}

// softmax over KB (summing 4 N-slice partials, parallel reductions)
// + vectorized weighted read of knowledge
__global__ void read_k(const float* __restrict__ s4,
                       const float* __restrict__ knowledge,
                       float* __restrict__ readv)
{
    int b = blockIdx.x;
    int tid = threadIdx.x;              // 256
    int wid = tid >> 5, lane = tid & 31;
    __shared__ float sv[KBsz];
    __shared__ float wred[8];

    float x = -1e30f;
    if (tid < KBsz) {
        size_t base = (size_t)b * KBsz + tid;
        x = s4[base] + s4[(size_t)MKB + base]
          + s4[2*(size_t)MKB + base] + s4[3*(size_t)MKB + base];
    }
    float m = x;
    #pragma unroll
    for (int o = 16; o; o >>= 1) m = fmaxf(m, __shfl_xor_sync(0xffffffffu, m, o));
    if (lane == 0) wred[wid] = m;
    __syncthreads();
    if (tid == 0) {
        float mm = wred[0];
        #pragma unroll
        for (int w = 1; w < 8; w++) mm = fmaxf(mm, wred[w]);
        wred[0] = mm;
    }
    __syncthreads();
    float mx = wred[0];
    float e = (tid < KBsz) ? expf(x - mx) : 0.f;
    float s = e;
    #pragma unroll
    for (int o = 16; o; o >>= 1) s += __shfl_xor_sync(0xffffffffu, s, o);
    __syncthreads();
    if (lane == 0) wred[wid] = s;
    __syncthreads();
    if (tid == 0) {
        float ss = 0.f;
        #pragma unroll
        for (int w = 0; w < 8; w++) ss += wred[w];
        wred[0] = 1.f / ss;
    }
    __syncthreads();
    if (tid < KBsz) sv[tid] = e * wred[0];
    __syncthreads();

    if (tid < 128) {
        const float4* kn = (const float4*)(knowledge + (size_t)b * KBsz * Dd);
        float4 acc = make_float4(0.f, 0.f, 0.f, 0.f);
        int k = 0;
        #pragma unroll 4
        for (; k + 4 <= KBsz; k += 4) {
            #pragma unroll
            for (int u = 0; u < 4; u++) {
                float w = sv[k + u];
                float4 t = kn[(size_t)(k + u) * 128 + tid];
                acc.x += w * t.x; acc.y += w * t.y;
                acc.z += w * t.z; acc.w += w * t.w;
            }
        }
        for (; k < KBsz; k++) {
            float w = sv[k];
            float4 t = kn[(size_t)k * 128 + tid];
            acc.x += w * t.x; acc.y += w * t.y;
            acc.z += w * t.z; acc.w += w * t.w;
        }
        ((float4*)(readv + (size_t)b * Dd))[tid] = acc;
    }
}

__global__ void out_k(const float* __restrict__ mem,
                      const float* __restrict__ att,
                      float* __restrict__ out, int out_size)
{
    int i = blockIdx.x * blockDim.x + threadIdx.x;
    if (i >= BD) return;
    if (i < out_size) out[i] = mem[i];
    if (out_size >= 2 * BD) {
        int b = i >> 9, d = i & 511;
        out[BD + i] = att[((size_t)b * Ss + (Ss - 1)) * Dd + d];
    }
}

// ---------------- launch -----------------------------------------------------
static float* symf(const void* s) { void* p = nullptr; cudaGetSymbolAddress(&p, s); return (float*)p; }
static hf*    symh(const void* s) { void* p = nullptr; cudaGetSymbolAddress(&p, s); return (hf*)p; }

#define TG_SMEM (int)((NSTG*2*A_ST + NSTG*B_ST) * sizeof(hf))

extern "C" void kernel_launch(void* const* d_in, const int* in_sizes, int n_in,
                              void* d_out, int out_size)
{
    const float* qword     = (const float*)d_in[0];
    const float* qemb      = (const float*)d_in[1];
    const float* knowledge = (const float*)d_in[2];
    const float* ci_w     = (const float*)d_in[4];
    const float* ci_b     = (const float*)d_in[5];
    const float* ciu_w    = (const float*)d_in[6];
    const float* ciu_b    = (const float*)d_in[7];
    const float* ca_w     = (const float*)d_in[8];
    const float* kproj_w  = (const float*)d_in[10];
    const float* kproj_b  = (const float*)d_in[11];
    const float* mproj_w  = (const float*)d_in[12];
    const float* mproj_b  = (const float*)d_in[13];
    const float* concat_w = (const float*)d_in[14];
    const float* concat_b = (const float*)d_in[15];
    const float* concat2_w= (const float*)d_in[16];
    const float* concat2_b= (const float*)d_in[17];
    const float* rattn_w  = (const float*)d_in[18];
    const float* write_w  = (const float*)d_in[20];
    const float* write_b  = (const float*)d_in[21];
    const float* init_mem = (const float*)d_in[22];
    const float* kq_w     = (const float*)d_in[23];
    const float* kq_b     = (const float*)d_in[24];
    const float* val_w    = (const float*)d_in[25];
    const float* val_b    = (const float*)d_in[26];
    float* out = (float*)d_out;

    float* q0     = symf(g_q0);
    float* qall   = symf(g_qall);
    float* ch     = symf(g_ch);
    float* chkey  = symf(g_chkey);
    float* chval  = symf(g_chval);
    float* normed = symf(g_normed);
    float* Amat   = symf(g_Amat);
    float* att    = symf(g_att);
    hf*    kph    = symh(g_kph);
    hf*    kpl    = symh(g_kpl);
    hf*    kp2h   = symh(g_kp2h);
    hf*    kp2l   = symh(g_kp2l);
    hf*    e1h    = symh(g_e1h);
    hf*    e1l    = symh(g_e1l);
    hf*    ahb    = symh(g_ah);
    hf*    alb    = symh(g_al);
    hf*    knh    = symh(g_knh);
    hf*    knl    = symh(g_knl);
    hf*    wb     = symh(g_wb);
    float* s4     = symf(g_s4);
    float* readv  = symf(g_read);
    float* Wcat   = symf(g_Wcat);
    float* biascat= symf(g_biascat);
    float* zerov  = symf(g_zero);
    float* tmp512 = symf(g_tmp512);
    float* zbuf   = symf(g_zbuf);

    static bool init_done = false;
    static cudaStream_t s2 = nullptr;
    static cudaEvent_t evFork = nullptr, evJoin = nullptr;
    if (!init_done) {
        cudaFuncSetAttribute(tgemm_k<2>, cudaFuncAttributeMaxDynamicSharedMemorySize, TG_SMEM);
        cudaFuncSetAttribute(tgemm_k<3>, cudaFuncAttributeMaxDynamicSharedMemorySize, TG_SMEM);
        cudaFuncSetAttribute(tgemm_k<4>, cudaFuncAttributeMaxDynamicSharedMemorySize, TG_SMEM);
        cudaStreamCreateWithFlags(&s2, cudaStreamNonBlocking);
        cudaEventCreateWithFlags(&evFork, cudaEventDisableTiming);
        cudaEventCreateWithFlags(&evJoin, cudaEventDisableTiming);
        init_done = true;
    }

    auto Gs = [](int M, int N, int Z) { return dim3(N / SBN, M / SBM, Z); };
    const dim3 GT(Dd / 128, MKB / 128);
    const float* NPF = nullptr;
    hf* NPH = nullptr;

    // ---- fork ----
    cudaEventRecord(evFork, 0);
    cudaStreamWaitEvent(s2, evFork, 0);

    {   // stream s2: splits + kp + kp2 + write/mproj fusion prep + init state
        size_t nk = (size_t)MKB * Dd;
        splith_k<<<(unsigned)((nk / 4 + 255) / 256), 256, 0, s2>>>(knowledge, knh, knl, nk);
        size_t nw = (size_t)Dd * Dd;
        cvt16_k<<<(unsigned)((nw / 4 + 255) / 256), 256, 0, s2>>>(kproj_w,  wb + 0*Dd*Dd, nw);
        cvt16_k<<<(unsigned)((2*nw / 4 + 255) / 256), 256, 0, s2>>>(concat_w, wb + 1*Dd*Dd, 2*nw);
        cvt16_k<<<(unsigned)((nw / 4 + 255) / 256), 256, 0, s2>>>(concat2_w, wb + 3*Dd*Dd, nw);
        // kp / kp2 (split-only outputs)
        tgemm_k<4><<<GT, 256, TG_SMEM, s2>>>(knh, knl, wb + 0*Dd*Dd,
                                             kproj_b, kph, kpl, NPH, NPH, NPF, 0, NPF, nullptr);
        tgemm_k<4><<<GT, 256, TG_SMEM, s2>>>(kph, kpl, wb + 2*Dd*Dd,
                                             concat_b, kp2h, kp2l, NPH, NPH, NPF, 0, NPF, nullptr);
        // W2 = write_w @ mproj_w into Wcat[1]; Wcat[0] = write_w
        sgemm_k<0><<<Gs(2*Dd, Dd, 1), 256, 0, s2>>>(write_w, Dd, write_w, Dd, Dd,
                                                    mproj_w, zerov, Wcat + (size_t)2*Dd*Dd,
                                                    2*Dd, Dd, Dd, 0, 0, 0, 0);
        copyf_k<<<(2*Dd*Dd / 4 + 255) / 256, 256, 0, s2>>>(write_w, Wcat, 2*Dd*Dd);
        copyf_k<<<(Dd / 4 + 255) / 256, 256, 0, s2>>>(write_b, biascat, Dd);
        vecmat_k<<<2, 256, 0, s2>>>(write_b, mproj_w, mproj_b, biascat + Dd);   // bias2
        bcast_k<<<(BD + 255) / 256, 256, 0, s2>>>(init_mem, zbuf);              // memory0
        vecmat_k<<<2, 256, 0, s2>>>(init_mem, mproj_w, mproj_b, tmp512);        // mp0 row
        bcast_k<<<(BD + 255) / 256, 256, 0, s2>>>(tmp512, zbuf + BD);           // mp0
    }
    cudaEventRecord(evJoin, s2);

    // default stream: question path
    sgemm_k<1><<<Gs(Bsz, Dd, 1), 256>>>(qemb, Dd, qemb, Dd, Dd, ci_w, ci_b, q0,
                                        Bsz, Dd, Dd, 0, 0, 0, 0);
    sgemm_k<0><<<Gs(Bsz, Dd, Ss), 256>>>(q0, Dd, q0, Dd, Dd, ciu_w, ciu_b, qall,
                                         Bsz, Dd, Dd,
                                         0, (size_t)Dd * Dd, Dd, (size_t)BD);
    word_attn_k<<<dim3(Bsz, Ss), 256>>>(qall, qword, ca_w, ch);
    sgemm_k<0><<<Gs(Bsz * Ss, Dd, 1), 256>>>(ch, Dd, ch, Dd, Dd, kq_w, kq_b, chkey,
                                             Bsz * Ss, Dd, Dd, 0, 0, 0, 0);
    sgemm_k<0><<<Gs(Bsz * Ss, Dd, 1), 256>>>(ch, Dd, ch, Dd, Dd, val_w, val_b, chval,
                                             Bsz * Ss, Dd, Dd, 0, 0, 0, 0);
    norm_k<<<(BD + 255) / 256, 256>>>(chkey, normed);
    gram_k<<<dim3(TBsz, TS), 256>>>(normed, Amat);
    attv_k<<<dim3(TBsz, TS), 256>>>(Amat, chval, att);

    cudaStreamWaitEvent(0, evJoin, 0);

    int p = 0;
    for (int i = 0; i < Ss; i++) {
        float* mcur = zbuf + (size_t)p * 2 * BD;
        float* mpcur = mcur + BD;
        {
            size_t nk = (size_t)MKB * Dd;
            scale_split_k<<<(unsigned)((nk / 4 + 255) / 256), 256>>>(kph, kpl, mpcur, ahb, alb);
        }
        tgemm_k<2><<<GT, 256, TG_SMEM>>>(ahb, alb, wb + 1*Dd*Dd,
                                         NPF, e1h, e1l, kp2h, kp2l, NPF, 0, NPF, nullptr);
        tgemm_k<3><<<GT, 256, TG_SMEM>>>(e1h, e1l, wb + 3*Dd*Dd,
                                         concat2_b, NPH, NPH, NPH, NPH,
                                         att + (size_t)i * Dd, Ss * Dd, rattn_w, s4);
        read_k<<<Bsz, 256>>>(s4, knowledge, readv);
        sgemm_k<0><<<Gs(Bsz, Dd, 2), 256>>>(mcur, Dd, readv, Dd, Dd,
                                            Wcat, biascat,
                                            zbuf + (size_t)(p ^ 1) * 2 * BD,
                                            Bsz, 2 * Dd, Dd,
                                            0, (size_t)2*Dd*Dd, Dd, (size_t)BD);
        p ^= 1;
    }

    out_k<<<(BD + 255) / 256, 256>>>(zbuf + (size_t)p * 2 * BD, att, out, out_size);
}

// round 14
// speedup vs baseline: 5.4758x; 1.4879x over previous
#include <cuda_runtime.h>
#include <cuda_fp16.h>
#include <math.h>

// Problem constants
#define Bsz 640
#define Dd 512
#define Ss 4
#define Tt 10
#define TBsz 64
#define Ll 30
#define KBsz 196
#define MKB (Bsz*KBsz)   // 125440
#define TS 40            // T*S
#define BD (Bsz*Dd)

typedef __half hf;

// ---------------- scratch (static device globals; no allocations) ----------
__device__ float g_q0[BD];
__device__ float g_qall[Ss*BD];
__device__ float g_ch[Bsz*Ss*Dd];
__device__ float g_chkey[Bsz*Ss*Dd];
__device__ float g_chval[Bsz*Ss*Dd];
__device__ float g_normed[Bsz*Ss*Dd];
__device__ float g_Amat[TBsz*TS*TS];
__device__ float g_att[Bsz*Ss*Dd];
__device__ hf    g_kp [(size_t)MKB*Dd];      // know_proj, fp16
__device__ hf    g_kp2[(size_t)MKB*Dd];      // kp2, fp16
__device__ hf    g_e1 [(size_t)MKB*Dd];      // e1, fp16
__device__ hf    g_a  [(size_t)MKB*Dd];      // kp*mp, fp16
__device__ hf    g_kn [(size_t)MKB*Dd];      // knowledge, fp16
__device__ hf    g_wb[4][Dd*Dd];             // weights, fp16
__device__ float g_s4[4*(size_t)MKB];        // score partials per N-slice
__device__ float g_read[BD];
__device__ float g_Wcat[2][2*Dd*Dd];         // [0]=write_w copy, [1]=W2=write_w@mproj_w
__device__ float g_biascat[2][Dd];           // [0]=write_b copy, [1]=bias2
__device__ float g_zero[Dd];                 // stays zero (.bss)
__device__ float g_tmp512[Dd];
__device__ float g_zbuf[4*BD];               // [p][q][BD]: q=0 memory, q=1 mp

__device__ __forceinline__ float eluf(float x){ return x > 0.f ? x : expm1f(x); }

__device__ __forceinline__ void mma_f16(float* cc, const unsigned* a, const unsigned* b){
    asm("mma.sync.aligned.m16n8k16.row.col.f32.f16.f16.f32 "
        "{%0,%1,%2,%3}, {%4,%5,%6,%7}, {%8,%9}, {%0,%1,%2,%3};"
        : "+f"(cc[0]), "+f"(cc[1]), "+f"(cc[2]), "+f"(cc[3])
        : "r"(a[0]), "r"(a[1]), "r"(a[2]), "r"(a[3]), "r"(b[0]), "r"(b[1]));
}
__device__ __forceinline__ void ldm4(unsigned* r, const hf* p){
    unsigned addr = (unsigned)__cvta_generic_to_shared(p);
    asm volatile("ldmatrix.sync.aligned.m8n8.x4.shared.b16 {%0,%1,%2,%3}, [%4];"
                 : "=r"(r[0]), "=r"(r[1]), "=r"(r[2]), "=r"(r[3]) : "r"(addr));
}
__device__ __forceinline__ void ldm4t(unsigned* r, const hf* p){
    unsigned addr = (unsigned)__cvta_generic_to_shared(p);
    asm volatile("ldmatrix.sync.aligned.m8n8.x4.trans.shared.b16 {%0,%1,%2,%3}, [%4];"
                 : "=r"(r[0]), "=r"(r[1]), "=r"(r[2]), "=r"(r[3]) : "r"(addr));
}
__device__ __forceinline__ void cpa16(void* sdst, const void* gsrc){
    unsigned s = (unsigned)__cvta_generic_to_shared(sdst);
    asm volatile("cp.async.cg.shared.global [%0], [%1], 16;" :: "r"(s), "l"(gsrc));
}
__device__ __forceinline__ void cpa_commit(){ asm volatile("cp.async.commit_group;"); }

// =============  big tensor-core GEMM: fp16 single-pass  ======================
// MODE 2: t = elu(acc + add); C = fp16(t)
// MODE 3: svec[slice][m] = sum_n elu((acc+bias[n])*colmul[(m/KB)*cmStride+n])*rvec[n]
// MODE 4: C = fp16(acc + bias)
#define TGK 512
#define TGN 512
#define TBK 32
#define NKIT (TGK/TBK)
#define NSTG 2
#define ALD 40
#define BLD 136
#define A_ST (128*ALD)
#define B_ST (TBK*BLD)

template<int MODE>
__global__ __launch_bounds__(256, 2)
void tgemm_k(const hf* __restrict__ Ag, const hf* __restrict__ Bg,
             const float* __restrict__ bias,
             hf* __restrict__ C,
             const hf* __restrict__ addmat,
             const float* __restrict__ colmul, int cmStride,
             const float* __restrict__ rvec, float* __restrict__ svec)
{
    extern __shared__ hf smem[];
    hf* Abase = smem;                        // [NSTG][128][ALD]
    hf* Bbase = smem + NSTG*A_ST;            // [NSTG][TBK][BLD]

    const int bm = blockIdx.y * 128;
    const int bn = blockIdx.x * 128;
    const int tid = threadIdx.x;
    const int wid = tid >> 5, lane = tid & 31;
    const int warp_m = wid & 1;
    const int warp_n = wid >> 1;
    const int r = lane >> 2, c = lane & 3;
    const int lrow = lane & 15, lcol = (lane >> 4) * 8;

    float acc[4][4][4];
    #pragma unroll
    for (int i = 0; i < 4; i++)
        #pragma unroll
        for (int j = 0; j < 4; j++)
            #pragma unroll
            for (int q = 0; q < 4; q++) acc[i][j][q] = 0.f;

    auto do_copy = [&](int k0, int st){
        hf* As = Abase + st * A_ST;
        hf* Bs = Bbase + st * B_ST;
        #pragma unroll
        for (int e2 = 0; e2 < 2; e2++) {
            int e   = tid * 2 + e2;          // 0..511
            int row = e >> 2;                // 0..127
            int seg = (e & 3) * 8;           // 0,8,16,24
            cpa16(As + row * ALD + seg,
                  Ag + (size_t)(bm + row) * TGK + k0 * TBK + seg);
        }
        #pragma unroll
        for (int e2 = 0; e2 < 2; e2++) {
            int e   = tid * 2 + e2;          // 0..511
            int row = e >> 4;                // 0..31
            int seg = (e & 15) * 8;          // 0..120
            cpa16(Bs + row * BLD + seg,
                  Bg + (size_t)(k0 * TBK + row) * TGN + bn + seg);
        }
        cpa_commit();
    };

    do_copy(0, 0);

    for (int k0 = 0; k0 < NKIT; k0++) {
        int st = k0 & 1;
        asm volatile("cp.async.wait_group 0;" ::: "memory");
        __syncthreads();
        if (k0 + 1 < NKIT) do_copy(k0 + 1, st ^ 1);

        const hf* Ash = Abase + st * A_ST;
        const hf* Bsh = Bbase + st * B_ST;

        #pragma unroll
        for (int ks = 0; ks < 2; ks++) {
            unsigned ah[4][4], bh[4][2];
            int rr = ks * 16 + lrow;
            int cbase = warp_n * 32 + lcol;
            #pragma unroll
            for (int mt = 0; mt < 4; mt++) {
                int row = warp_m * 64 + mt * 16 + lrow;
                ldm4(ah[mt], Ash + row * ALD + ks * 16 + lcol);
            }
            #pragma unroll
            for (int p = 0; p < 2; p++) {
                unsigned t[4];
                ldm4t(t, Bsh + rr * BLD + cbase + p * 16);
                bh[2*p][0] = t[0]; bh[2*p][1] = t[1];
                bh[2*p+1][0] = t[2]; bh[2*p+1][1] = t[3];
            }
            #pragma unroll
            for (int mt = 0; mt < 4; mt++)
                #pragma unroll
                for (int nt = 0; nt < 4; nt++)
                    mma_f16(acc[mt][nt], ah[mt], bh[nt]);
        }
    }
    __syncthreads();

    if (MODE == 3) {
        __shared__ float sred[128];
        if (tid < 128) sred[tid] = 0.f;
        __syncthreads();
        #pragma unroll
        for (int mt = 0; mt < 4; mt++) {
            int mloc = warp_m*64 + mt*16 + r;
            int m0 = bm + mloc;
            int b0 = m0 / KBsz;
            int b1 = (m0 + 8) / KBsz;
            float p0 = 0.f, p1 = 0.f;
            #pragma unroll
            for (int nt = 0; nt < 4; nt++) {
                int n0 = bn + warp_n*32 + nt*8 + 2*c;
                float v;
                v = eluf((acc[mt][nt][0] + bias[n0  ]) * colmul[(size_t)b0*cmStride + n0  ]); p0 += v*rvec[n0];
                v = eluf((acc[mt][nt][1] + bias[n0+1]) * colmul[(size_t)b0*cmStride + n0+1]); p0 += v*rvec[n0+1];
                v = eluf((acc[mt][nt][2] + bias[n0  ]) * colmul[(size_t)b1*cmStride + n0  ]); p1 += v*rvec[n0];
                v = eluf((acc[mt][nt][3] + bias[n0+1]) * colmul[(size_t)b1*cmStride + n0+1]); p1 += v*rvec[n0+1];
            }
            p0 += __shfl_xor_sync(0xffffffffu, p0, 1);
            p0 += __shfl_xor_sync(0xffffffffu, p0, 2);
            p1 += __shfl_xor_sync(0xffffffffu, p1, 1);
            p1 += __shfl_xor_sync(0xffffffffu, p1, 2);
            if (c == 0) { atomicAdd(&sred[mloc], p0); atomicAdd(&sred[mloc + 8], p1); }
        }
        __syncthreads();
        if (tid < 128)
            svec[(size_t)blockIdx.x * MKB + bm + tid] = sred[tid];
        return;
    }

    #pragma unroll
    for (int mt = 0; mt < 4; mt++) {
        int m0 = bm + warp_m*64 + mt*16 + r;
        #pragma unroll
        for (int nt = 0; nt < 4; nt++) {
            int n0 = bn + warp_n*32 + nt*8 + 2*c;
            #pragma unroll
            for (int half = 0; half < 2; half++) {
                int mm = m0 + half*8;
                float vx = acc[mt][nt][2*half], vy = acc[mt][nt][2*half+1];
                size_t gm = (size_t)mm*TGN + n0;
                if (MODE == 2) {
                    __half2 ad = *(const __half2*)(addmat + gm);
                    vx = eluf(vx + __half2float(__low2half(ad)));
                    vy = eluf(vy + __half2float(__high2half(ad)));
                } else { // MODE 4
                    vx += bias[n0]; vy += bias[n0+1];
                }
                *(__half2*)(C + gm) =
                    __halves2half2(__float2half_rn(vx), __float2half_rn(vy));
            }
        }
    }
}

// ---------------- split / helper kernels -------------------------------------
__global__ void cvt16_k(const float* __restrict__ src, hf* __restrict__ dst, size_t n)
{
    size_t i = ((size_t)blockIdx.x * blockDim.x + threadIdx.x) * 4;
    if (i >= n) return;
    float4 v = *(const float4*)(src + i);
    *(__half2*)(dst + i)     = __halves2half2(__float2half_rn(v.x), __float2half_rn(v.y));
    *(__half2*)(dst + i + 2) = __halves2half2(__float2half_rn(v.z), __float2half_rn(v.w));
}

__global__ void scale_k(const hf* __restrict__ kp,
                        const float* __restrict__ mp,
                        hf* __restrict__ outa)
{
    size_t i = ((size_t)blockIdx.x * blockDim.x + threadIdx.x) * 4;
    if (i >= (size_t)MKB * Dd) return;
    int m = (int)(i >> 9);
    int d = (int)(i & 511);
    int b = m / KBsz;
    __half2 k01 = *(const __half2*)(kp + i);
    __half2 k23 = *(const __half2*)(kp + i + 2);
    float4 s = *(const float4*)(mp + (size_t)b * Dd + d);
    float v0 = __half2float(__low2half(k01)) * s.x;
    float v1 = __half2float(__high2half(k01)) * s.y;
    float v2 = __half2float(__low2half(k23)) * s.z;
    float v3 = __half2float(__high2half(k23)) * s.w;
    *(__half2*)(outa + i)     = __halves2half2(__float2half_rn(v0), __float2half_rn(v1));
    *(__half2*)(outa + i + 2) = __halves2half2(__float2half_rn(v2), __float2half_rn(v3));
}

// r[n] = vec[k] dot W[k][n] + b[n]
__global__ void vecmat_k(const float* __restrict__ vec,
                         const float* __restrict__ W,
                         const float* __restrict__ b,
                         float* __restrict__ r)
{
    int n = blockIdx.x * blockDim.x + threadIdx.x;
    if (n >= Dd) return;
    float a = b[n];
    for (int k = 0; k < Dd; k++) a += vec[k] * W[(size_t)k * Dd + n];
    r[n] = a;
}

__global__ void copyf_k(const float* __restrict__ src, float* __restrict__ dst, int n)
{
    int i = (blockIdx.x * blockDim.x + threadIdx.x) * 4;
    if (i < n) *(float4*)(dst + i) = *(const float4*)(src + i);
}

// =====================  small FFMA2 GEMM (64x128 tile)  ======================
__device__ __forceinline__ unsigned long long pack2(float lo, float hi) {
    unsigned long long r;
    asm("mov.b64 %0, {%1, %2};" : "=l"(r) : "f"(lo), "f"(hi));
    return r;
}
__device__ __forceinline__ void unpack2(unsigned long long v, float& lo, float& hi) {
    asm("mov.b64 {%0, %1}, %2;" : "=f"(lo), "=f"(hi) : "l"(v));
}
__device__ __forceinline__ void fma2(unsigned long long& d,
                                     unsigned long long a, unsigned long long b) {
    asm("fma.rn.f32x2 %0, %1, %2, %0;" : "+l"(d) : "l"(a), "l"(b));
}

#define SBM 64
#define SBN 128
#define BKK 16

template<int MODE>
__global__ __launch_bounds__(256)
void sgemm_k(const float* __restrict__ A, int lda,
             const float* __restrict__ A2, int lda2, int splitK,
             const float* __restrict__ W,
             const float* __restrict__ bias,
             float* __restrict__ C,
             int M, int K, int N,
             size_t strideA, size_t strideW, size_t strideBias, size_t strideC)
{
    A    += (size_t)blockIdx.z * strideA;
    A2   += (size_t)blockIdx.z * strideA;
    W    += (size_t)blockIdx.z * strideW;
    bias += (size_t)blockIdx.z * strideBias;
    C    += (size_t)blockIdx.z * strideC;

    __shared__ float As[BKK][SBM];
    __shared__ float Bs[BKK][SBN];

    const int bm = blockIdx.y * SBM;
    const int bn = blockIdx.x * SBN;
    const int tid = threadIdx.x;
    const int ty = tid >> 5;
    const int tx = tid & 31;

    unsigned long long acc2[8][2];
    #pragma unroll
    for (int i = 0; i < 8; i++) { acc2[i][0] = 0ull; acc2[i][1] = 0ull; }

    for (int k0 = 0; k0 < K; k0 += BKK) {
        {
            int e   = tid;
            int row = e >> 2;
            int kq  = (e & 3) * 4;
            int m   = bm + row;
            int k   = k0 + kq;
            const float* src = (k < splitK)
                ? (A  + (size_t)m * lda  + k)
                : (A2 + (size_t)m * lda2 + (k - splitK));
            float4 v = *(const float4*)src;
            As[kq + 0][row] = v.x; As[kq + 1][row] = v.y;
            As[kq + 2][row] = v.z; As[kq + 3][row] = v.w;
        }
        #pragma unroll
        for (int e2 = 0; e2 < 2; e2++) {
            int e   = tid * 2 + e2;
            int row = e >> 5;
            int cc  = (e & 31) * 4;
            float4 v = *(const float4*)(W + (size_t)(k0 + row) * N + bn + cc);
            *(float4*)&Bs[row][cc] = v;
        }
        __syncthreads();
        #pragma unroll
        for (int kk = 0; kk < BKK; kk++) {
            float a[8];
            unsigned long long b2[2];
            #pragma unroll
            for (int i = 0; i < 8; i++) a[i] = As[kk][ty * 8 + i];
            b2[0] = *(const unsigned long long*)&Bs[kk][tx * 4];
            b2[1] = *(const unsigned long long*)&Bs[kk][tx * 4 + 2];
            #pragma unroll
            for (int i = 0; i < 8; i++) {
                unsigned long long pa = pack2(a[i], a[i]);
                fma2(acc2[i][0], pa, b2[0]);
                fma2(acc2[i][1], pa, b2[1]);
            }
        }
        __syncthreads();
    }

    #pragma unroll
    for (int i = 0; i < 8; i++) {
        int m = bm + ty * 8 + i;
        int n = bn + tx * 4;
        float4 v;
        unpack2(acc2[i][0], v.x, v.y);
        unpack2(acc2[i][1], v.z, v.w);
        v.x += bias[n]; v.y += bias[n+1]; v.z += bias[n+2]; v.w += bias[n+3];
        if (MODE == 1) { v.x = tanhf(v.x); v.y = tanhf(v.y); v.z = tanhf(v.z); v.w = tanhf(v.w); }
        *(float4*)(C + (size_t)m * N + n) = v;
    }
}

// ---------------- attention / misc kernels (validated) -----------------------
__global__ void word_attn_k(const float* __restrict__ qall,
                            const float* __restrict__ qword,
                            const float* __restrict__ caw,
                            float* __restrict__ ch)
{
    int b = blockIdx.x, s = blockIdx.y;
    __shared__ float qs[Dd];
    __shared__ float lg[Ll];
    int tid = threadIdx.x;
    for (int d = tid; d < Dd; d += 256)
        qs[d] = qall[((size_t)s * Bsz + b) * Dd + d] * caw[d];
    __syncthreads();
    int wid = tid >> 5, lane = tid & 31;
    for (int l = wid; l < Ll; l += 8) {
        const float* qw = qword + ((size_t)b * Ll + l) * Dd;
        float a = 0.f;
        for (int d = lane; d < Dd; d += 32) a += qs[d] * qw[d];
        #pragma unroll
        for (int o = 16; o; o >>= 1) a += __shfl_xor_sync(0xffffffffu, a, o);
        if (lane == 0) lg[l] = a;
    }
    __syncthreads();
    if (tid == 0) {
        float mx = -INFINITY;
        for (int l = 0; l < Ll; l++) mx = fmaxf(mx, lg[l]);
        float sm = 0.f;
        for (int l = 0; l < Ll; l++) { float e = expf(lg[l] - mx); lg[l] = e; sm += e; }
        float inv = 1.f / sm;
        for (int l = 0; l < Ll; l++) lg[l] *= inv;
    }
    __syncthreads();
    for (int d = tid; d < Dd; d += 256) {
        float a = 0.f;
        for (int l = 0; l < Ll; l++) a += lg[l] * qword[((size_t)b * Ll + l) * Dd + d];
        ch[((size_t)b * Ss + s) * Dd + d] = a;
    }
}

__global__ void norm_k(const float* __restrict__ chkey, float* __restrict__ normed)
{
    int i = blockIdx.x * blockDim.x + threadIdx.x;
    if (i >= BD) return;
    int b = i >> 9, d = i & 511;
    size_t base = (size_t)b * Ss * Dd + d;
    float ss = 0.f;
    #pragma unroll
    for (int s = 0; s < Ss; s++) { float v = chkey[base + s * Dd]; ss += v * v; }
    float inv = 1.f / sqrtf(ss);
    #pragma unroll
    for (int s = 0; s < Ss; s++) normed[base + s * Dd] = chkey[base + s * Dd] * inv;
}

__global__ void gram_k(const float* __restrict__ normed, float* __restrict__ Amat)
{
    int tb = blockIdx.x, i = blockIdx.y;
    __shared__ float Ki[Dd];
    __shared__ float lg[TS];
    int tid = threadIdx.x;
    int ti = i / Ss, si = i % Ss;
    size_t rowi = ((size_t)(ti * TBsz + tb) * Ss + si) * Dd;
    for (int d = tid; d < Dd; d += 256) Ki[d] = normed[rowi + d];
    __syncthreads();
    int wid = tid >> 5, lane = tid & 31;
    for (int j = wid; j < TS; j += 8) {
        float a;
        if (j > i) a = -1e30f;
        else {
            int tj = j / Ss, sj = j % Ss;
            size_t rowj = ((size_t)(tj * TBsz + tb) * Ss + sj) * Dd;
            a = 0.f;
            for (int d = lane; d < Dd; d += 32) a += Ki[d] * normed[rowj + d];
            #pragma unroll
            for (int o = 16; o; o >>= 1) a += __shfl_xor_sync(0xffffffffu, a, o);
        }
        if (lane == 0) lg[j] = a;
    }
    __syncthreads();
    if (tid == 0) {
        float mx = -INFINITY;
        for (int j = 0; j < TS; j++) mx = fmaxf(mx, lg[j]);
        float sm = 0.f;
        for (int j = 0; j < TS; j++) { float e = expf(lg[j] - mx); lg[j] = e; sm += e; }
        float inv = 1.f / sm;
        for (int j = 0; j < TS; j++) lg[j] *= inv;
    }
    __syncthreads();
    if (tid < TS) Amat[((size_t)tb * TS + i) * TS + tid] = lg[tid];
}

__global__ void attv_k(const float* __restrict__ Amat,
                       const float* __restrict__ chval,
                       float* __restrict__ att)
{
    int tb = blockIdx.x, i = blockIdx.y;
    __shared__ float aw[TS];
    int tid = threadIdx.x;
    if (tid < TS) aw[tid] = Amat[((size_t)tb * TS + i) * TS + tid];
    __syncthreads();
    int ti = i / Ss, si = i % Ss;
    for (int d = tid; d < Dd; d += 256) {
        float a = 0.f;
        for (int j = 0; j <= i; j++) {
            int tj = j / Ss, sj = j % Ss;
            a += aw[j] * chval[((size_t)(tj * TBsz + tb) * Ss + sj) * Dd + d];
        }
        att[((size_t)(ti * TBsz + tb) * Ss + si) * Dd + d] = a;
    }
}

__global__ void bcast_k(const float* __restrict__ src, float* __restrict__ dst)
{
    int i = blockIdx.x * blockDim.x + threadIdx.x;
    if (i < BD) dst[i] = src[i & 511];
}

// softmax over KB (summing 4 N-slice partials, parallel reductions)
// + vectorized weighted read of knowledge
__global__ void read_k(const float* __restrict__ s4,
                       const float* __restrict__ knowledge,
                       float* __restrict__ readv)
{
    int b = blockIdx.x;
    int tid = threadIdx.x;              // 256
    int wid = tid >> 5, lane = tid & 31;
    __shared__ float sv[KBsz];
    __shared__ float wred[8];

    float x = -1e30f;
    if (tid < KBsz) {
        size_t base = (size_t)b * KBsz + tid;
        x = s4[base] + s4[(size_t)MKB + base]
          + s4[2*(size_t)MKB + base] + s4[3*(size_t)MKB + base];
    }
    float m = x;
    #pragma unroll
    for (int o = 16; o; o >>= 1) m = fmaxf(m, __shfl_xor_sync(0xffffffffu, m, o));
    if (lane == 0) wred[wid] = m;
    __syncthreads();
    if (tid == 0) {
        float mm = wred[0];
        #pragma unroll
        for (int w = 1; w < 8; w++) mm = fmaxf(mm, wred[w]);
        wred[0] = mm;
    }
    __syncthreads();
    float mx = wred[0];
    float e = (tid < KBsz) ? expf(x - mx) : 0.f;
    float s = e;
    #pragma unroll
    for (int o = 16; o; o >>= 1) s += __shfl_xor_sync(0xffffffffu, s, o);
    __syncthreads();
    if (lane == 0) wred[wid] = s;
    __syncthreads();
    if (tid == 0) {
        float ss = 0.f;
        #pragma unroll
        for (int w = 0; w < 8; w++) ss += wred[w];
        wred[0] = 1.f / ss;
    }
    __syncthreads();
    if (tid < KBsz) sv[tid] = e * wred[0];
    __syncthreads();

    if (tid < 128) {
        const float4* kn = (const float4*)(knowledge + (size_t)b * KBsz * Dd);
        float4 acc = make_float4(0.f, 0.f, 0.f, 0.f);
        int k = 0;
        #pragma unroll 4
        for (; k + 4 <= KBsz; k += 4) {
            #pragma unroll
            for (int u = 0; u < 4; u++) {
                float w = sv[k + u];
                float4 t = kn[(size_t)(k + u) * 128 + tid];
                acc.x += w * t.x; acc.y += w * t.y;
                acc.z += w * t.z; acc.w += w * t.w;
            }
        }
        for (; k < KBsz; k++) {
            float w = sv[k];
            float4 t = kn[(size_t)k * 128 + tid];
            acc.x += w * t.x; acc.y += w * t.y;
            acc.z += w * t.z; acc.w += w * t.w;
        }
        ((float4*)(readv + (size_t)b * Dd))[tid] = acc;
    }
}

__global__ void out_k(const float* __restrict__ mem,
                      const float* __restrict__ att,
                      float* __restrict__ out, int out_size)
{
    int i = blockIdx.x * blockDim.x + threadIdx.x;
    if (i >= BD) return;
    if (i < out_size) out[i] = mem[i];
    if (out_size >= 2 * BD) {
        int b = i >> 9, d = i & 511;
        out[BD + i] = att[((size_t)b * Ss + (Ss - 1)) * Dd + d];
    }
}

// ---------------- launch -----------------------------------------------------
static float* symf(const void* s) { void* p = nullptr; cudaGetSymbolAddress(&p, s); return (float*)p; }
static hf*    symh(const void* s) { void* p = nullptr; cudaGetSymbolAddress(&p, s); return (hf*)p; }

#define TG_SMEM (int)((NSTG*A_ST + NSTG*B_ST) * sizeof(hf))

extern "C" void kernel_launch(void* const* d_in, const int* in_sizes, int n_in,
                              void* d_out, int out_size)
{
    const float* qword     = (const float*)d_in[0];
    const float* qemb      = (const float*)d_in[1];
    const float* knowledge = (const float*)d_in[2];
    const float* ci_w     = (const float*)d_in[4];
    const float* ci_b     = (const float*)d_in[5];
    const float* ciu_w    = (const float*)d_in[6];
    const float* ciu_b    = (const float*)d_in[7];
    const float* ca_w     = (const float*)d_in[8];
    const float* kproj_w  = (const float*)d_in[10];
    const float* kproj_b  = (const float*)d_in[11];
    const float* mproj_w  = (const float*)d_in[12];
    const float* mproj_b  = (const float*)d_in[13];
    const float* concat_w = (const float*)d_in[14];
    const float* concat_b = (const float*)d_in[15];
    const float* concat2_w= (const float*)d_in[16];
    const float* concat2_b= (const float*)d_in[17];
    const float* rattn_w  = (const float*)d_in[18];
    const float* write_w  = (const float*)d_in[20];
    const float* write_b  = (const float*)d_in[21];
    const float* init_mem = (const float*)d_in[22];
    const float* kq_w     = (const float*)d_in[23];
    const float* kq_b     = (const float*)d_in[24];
    const float* val_w    = (const float*)d_in[25];
    const float* val_b    = (const float*)d_in[26];
    float* out = (float*)d_out;

    float* q0     = symf(g_q0);
    float* qall   = symf(g_qall);
    float* ch     = symf(g_ch);
    float* chkey  = symf(g_chkey);
    float* chval  = symf(g_chval);
    float* normed = symf(g_normed);
    float* Amat   = symf(g_Amat);
    float* att    = symf(g_att);
    hf*    kp     = symh(g_kp);
    hf*    kp2    = symh(g_kp2);
    hf*    e1     = symh(g_e1);
    hf*    ab     = symh(g_a);
    hf*    kn     = symh(g_kn);
    hf*    wb     = symh(g_wb);
    float* s4     = symf(g_s4);
    float* readv  = symf(g_read);
    float* Wcat   = symf(g_Wcat);
    float* biascat= symf(g_biascat);
    float* zerov  = symf(g_zero);
    float* tmp512 = symf(g_tmp512);
    float* zbuf   = symf(g_zbuf);

    static bool init_done = false;
    static cudaStream_t s2 = nullptr;
    static cudaEvent_t evFork = nullptr, evJoin = nullptr;
    if (!init_done) {
        cudaFuncSetAttribute(tgemm_k<2>, cudaFuncAttributeMaxDynamicSharedMemorySize, TG_SMEM);
        cudaFuncSetAttribute(tgemm_k<3>, cudaFuncAttributeMaxDynamicSharedMemorySize, TG_SMEM);
        cudaFuncSetAttribute(tgemm_k<4>, cudaFuncAttributeMaxDynamicSharedMemorySize, TG_SMEM);
        cudaStreamCreateWithFlags(&s2, cudaStreamNonBlocking);
        cudaEventCreateWithFlags(&evFork, cudaEventDisableTiming);
        cudaEventCreateWithFlags(&evJoin, cudaEventDisableTiming);
        init_done = true;
    }

    auto Gs = [](int M, int N, int Z) { return dim3(N / SBN, M / SBM, Z); };
    const dim3 GT(Dd / 128, MKB / 128);
    const float* NPF = nullptr;
    hf* NPH = nullptr;

    // ---- fork ----
    cudaEventRecord(evFork, 0);
    cudaStreamWaitEvent(s2, evFork, 0);

    {   // stream s2: conversions + kp + kp2 + write/mproj fusion prep + init state
        size_t nk = (size_t)MKB * Dd;
        cvt16_k<<<(unsigned)((nk / 4 + 255) / 256), 256, 0, s2>>>(knowledge, kn, nk);
        size_t nw = (size_t)Dd * Dd;
        cvt16_k<<<(unsigned)((nw / 4 + 255) / 256), 256, 0, s2>>>(kproj_w,  wb + 0*Dd*Dd, nw);
        cvt16_k<<<(unsigned)((2*nw / 4 + 255) / 256), 256, 0, s2>>>(concat_w, wb + 1*Dd*Dd, 2*nw);
        cvt16_k<<<(unsigned)((nw / 4 + 255) / 256), 256, 0, s2>>>(concat2_w, wb + 3*Dd*Dd, nw);
        // kp / kp2 (fp16 outputs)
        tgemm_k<4><<<GT, 256, TG_SMEM, s2>>>(kn, wb + 0*Dd*Dd,
                                             kproj_b, kp, NPH, NPF, 0, NPF, nullptr);
        tgemm_k<4><<<GT, 256, TG_SMEM, s2>>>(kp, wb + 2*Dd*Dd,
                                             concat_b, kp2, NPH, NPF, 0, NPF, nullptr);
        // W2 = write_w @ mproj_w into Wcat[1]; Wcat[0] = write_w
        sgemm_k<0><<<Gs(2*Dd, Dd, 1), 256, 0, s2>>>(write_w, Dd, write_w, Dd, Dd,
                                                    mproj_w, zerov, Wcat + (size_t)2*Dd*Dd,
                                                    2*Dd, Dd, Dd, 0, 0, 0, 0);
        copyf_k<<<(2*Dd*Dd / 4 + 255) / 256, 256, 0, s2>>>(write_w, Wcat, 2*Dd*Dd);
        copyf_k<<<(Dd / 4 + 255) / 256, 256, 0, s2>>>(write_b, biascat, Dd);
        vecmat_k<<<2, 256, 0, s2>>>(write_b, mproj_w, mproj_b, biascat + Dd);   // bias2
        bcast_k<<<(BD + 255) / 256, 256, 0, s2>>>(init_mem, zbuf);              // memory0
        vecmat_k<<<2, 256, 0, s2>>>(init_mem, mproj_w, mproj_b, tmp512);        // mp0 row
        bcast_k<<<(BD + 255) / 256, 256, 0, s2>>>(tmp512, zbuf + BD);           // mp0
    }
    cudaEventRecord(evJoin, s2);

    // default stream: question path
    sgemm_k<1><<<Gs(Bsz, Dd, 1), 256>>>(qemb, Dd, qemb, Dd, Dd, ci_w, ci_b, q0,
                                        Bsz, Dd, Dd, 0, 0, 0, 0);
    sgemm_k<0><<<Gs(Bsz, Dd, Ss), 256>>>(q0, Dd, q0, Dd, Dd, ciu_w, ciu_b, qall,
                                         Bsz, Dd, Dd,
                                         0, (size_t)Dd * Dd, Dd, (size_t)BD);
    word_attn_k<<<dim3(Bsz, Ss), 256>>>(qall, qword, ca_w, ch);
    sgemm_k<0><<<Gs(Bsz * Ss, Dd, 1), 256>>>(ch, Dd, ch, Dd, Dd, kq_w, kq_b, chkey,
                                             Bsz * Ss, Dd, Dd, 0, 0, 0, 0);
    sgemm_k<0><<<Gs(Bsz * Ss, Dd, 1), 256>>>(ch, Dd, ch, Dd, Dd, val_w, val_b, chval,
                                             Bsz * Ss, Dd, Dd, 0, 0, 0, 0);
    norm_k<<<(BD + 255) / 256, 256>>>(chkey, normed);
    gram_k<<<dim3(TBsz, TS), 256>>>(normed, Amat);
    attv_k<<<dim3(TBsz, TS), 256>>>(Amat, chval, att);

    cudaStreamWaitEvent(0, evJoin, 0);

    int p = 0;
    for (int i = 0; i < Ss; i++) {
        float* mcur = zbuf + (size_t)p * 2 * BD;
        float* mpcur = mcur + BD;
        {
            size_t nk = (size_t)MKB * Dd;
            scale_k<<<(unsigned)((nk / 4 + 255) / 256), 256>>>(kp, mpcur, ab);
        }
        tgemm_k<2><<<GT, 256, TG_SMEM>>>(ab, wb + 1*Dd*Dd,
                                         NPF, e1, kp2, NPF, 0, NPF, nullptr);
        tgemm_k<3><<<GT, 256, TG_SMEM>>>(e1, wb + 3*Dd*Dd,
                                         concat2_b, NPH, NPH,
                                         att + (size_t)i * Dd, Ss * Dd, rattn_w, s4);
        read_k<<<Bsz, 256>>>(s4, knowledge, readv);
        sgemm_k<0><<<Gs(Bsz, Dd, 2), 256>>>(mcur, Dd, readv, Dd, Dd,
                                            Wcat, biascat,
                                            zbuf + (size_t)(p ^ 1) * 2 * BD,
                                            Bsz, 2 * Dd, Dd,
                                            0, (size_t)2*Dd*Dd, Dd, (size_t)BD);
        p ^= 1;
    }

    out_k<<<(BD + 255) / 256, 256>>>(zbuf + (size_t)p * 2 * BD, att, out, out_size);
}

// round 15
// speedup vs baseline: 5.7033x; 1.0415x over previous
#include <cuda_runtime.h>
#include <cuda_fp16.h>
#include <math.h>

// Problem constants
#define Bsz 640
#define Dd 512
#define Ss 4
#define Tt 10
#define TBsz 64
#define Ll 30
#define KBsz 196
#define MKB (Bsz*KBsz)   // 125440
#define TS 40            // T*S
#define BD (Bsz*Dd)

typedef __half hf;

// ---------------- scratch (static device globals; no allocations) ----------
__device__ float g_q0[BD];
__device__ float g_qall[Ss*BD];
__device__ float g_ch[Bsz*Ss*Dd];
__device__ float g_chkv[2][Bsz*Ss*Dd];       // [0]=chkey [1]=chval
__device__ float g_normed[Bsz*Ss*Dd];
__device__ float g_Amat[TBsz*TS*TS];
__device__ float g_att[Bsz*Ss*Dd];
__device__ hf    g_kp [(size_t)MKB*Dd];      // know_proj, fp16
__device__ hf    g_kp2[(size_t)MKB*Dd];      // kp2, fp16
__device__ hf    g_e1 [(size_t)MKB*Dd];      // e1, fp16
__device__ hf    g_kn [(size_t)MKB*Dd];      // knowledge, fp16
__device__ hf    g_wb[4][Dd*Dd];             // weights, fp16
__device__ hf    g_mp16[BD];                 // mp in fp16 (per-iter)
__device__ float g_s4[4*(size_t)MKB];        // score partials per N-slice
__device__ float g_read[BD];
__device__ float g_Wcat[2][2*Dd*Dd];         // [0]=write_w copy, [1]=W2=write_w@mproj_w
__device__ float g_biascat[2][Dd];           // [0]=write_b copy, [1]=bias2
__device__ float g_Wkv[2][Dd*Dd];            // [0]=kq_w [1]=val_w (contiguous)
__device__ float g_bkv[2][Dd];
__device__ float g_zero[Dd];                 // stays zero (.bss)
__device__ float g_tmp512[Dd];
__device__ float g_zbuf[4*BD];               // [p][q][BD]: q=0 memory, q=1 mp

__device__ __forceinline__ float eluf(float x){ return x > 0.f ? x : expm1f(x); }

__device__ __forceinline__ void mma_f16(float* cc, const unsigned* a, const unsigned* b){
    asm("mma.sync.aligned.m16n8k16.row.col.f32.f16.f16.f32 "
        "{%0,%1,%2,%3}, {%4,%5,%6,%7}, {%8,%9}, {%0,%1,%2,%3};"
        : "+f"(cc[0]), "+f"(cc[1]), "+f"(cc[2]), "+f"(cc[3])
        : "r"(a[0]), "r"(a[1]), "r"(a[2]), "r"(a[3]), "r"(b[0]), "r"(b[1]));
}
__device__ __forceinline__ void ldm4(unsigned* r, const hf* p){
    unsigned addr = (unsigned)__cvta_generic_to_shared(p);
    asm volatile("ldmatrix.sync.aligned.m8n8.x4.shared.b16 {%0,%1,%2,%3}, [%4];"
                 : "=r"(r[0]), "=r"(r[1]), "=r"(r[2]), "=r"(r[3]) : "r"(addr));
}
__device__ __forceinline__ void ldm4t(unsigned* r, const hf* p){
    unsigned addr = (unsigned)__cvta_generic_to_shared(p);
    asm volatile("ldmatrix.sync.aligned.m8n8.x4.trans.shared.b16 {%0,%1,%2,%3}, [%4];"
                 : "=r"(r[0]), "=r"(r[1]), "=r"(r[2]), "=r"(r[3]) : "r"(addr));
}
__device__ __forceinline__ void cpa16(void* sdst, const void* gsrc){
    unsigned s = (unsigned)__cvta_generic_to_shared(sdst);
    asm volatile("cp.async.cg.shared.global [%0], [%1], 16;" :: "r"(s), "l"(gsrc));
}
__device__ __forceinline__ void cpa_commit(){ asm volatile("cp.async.commit_group;"); }

// =============  big tensor-core GEMM: fp16 single-pass  ======================
// MODE 2: A = Ag * rsv[b] (fused scale, LDG+STS pipeline);
//         t = elu(acc + add); C = fp16(t)
// MODE 3: svec[slice][m] = sum_n elu((acc+bias[n])*colmul[(m/KB)*cmStride+n])*rvec[n]
// MODE 4: C = fp16(acc + bias)
#define TGK 512
#define TGN 512
#define TBK 32
#define NKIT (TGK/TBK)
#define NSTG 2
#define ALD 40
#define BLD 136
#define A_ST (128*ALD)
#define B_ST (TBK*BLD)

template<int MODE>
__global__ __launch_bounds__(256, 2)
void tgemm_k(const hf* __restrict__ Ag, const hf* __restrict__ Bg,
             const float* __restrict__ bias,
             hf* __restrict__ C,
             const hf* __restrict__ addmat,
             const hf* __restrict__ rsv,
             const float* __restrict__ colmul, int cmStride,
             const float* __restrict__ rvec, float* __restrict__ svec)
{
    extern __shared__ hf smem[];
    hf* Abase = smem;                        // [NSTG][128][ALD]
    hf* Bbase = smem + NSTG*A_ST;            // [NSTG][TBK][BLD]

    const int bm = blockIdx.y * 128;
    const int bn = blockIdx.x * 128;
    const int tid = threadIdx.x;
    const int wid = tid >> 5, lane = tid & 31;
    const int warp_m = wid & 1;
    const int warp_n = wid >> 1;
    const int r = lane >> 2, c = lane & 3;
    const int lrow = lane & 15, lcol = (lane >> 4) * 8;

    float acc[4][4][4];
    #pragma unroll
    for (int i = 0; i < 4; i++)
        #pragma unroll
        for (int j = 0; j < 4; j++)
            #pragma unroll
            for (int q = 0; q < 4; q++) acc[i][j][q] = 0.f;

    // ---- copy helpers ----
    auto cpA = [&](int k0, int st){          // plain cp.async A (MODE 3/4)
        hf* As = Abase + st * A_ST;
        #pragma unroll
        for (int e2 = 0; e2 < 2; e2++) {
            int e   = tid * 2 + e2;
            int row = e >> 2;
            int seg = (e & 3) * 8;
            cpa16(As + row * ALD + seg,
                  Ag + (size_t)(bm + row) * TGK + k0 * TBK + seg);
        }
    };
    auto cpB = [&](int k0, int st){
        hf* Bs = Bbase + st * B_ST;
        #pragma unroll
        for (int e2 = 0; e2 < 2; e2++) {
            int e   = tid * 2 + e2;
            int row = e >> 4;
            int seg = (e & 15) * 8;
            cpa16(Bs + row * BLD + seg,
                  Bg + (size_t)(k0 * TBK + row) * TGN + bn + seg);
        }
        cpa_commit();
    };

    // MODE2 fused-scale A pipeline: registers prefetched one tile ahead
    uint4 ka[2], ra[2];
    auto ldgA = [&](int kt){
        #pragma unroll
        for (int e2 = 0; e2 < 2; e2++) {
            int e   = tid * 2 + e2;
            int row = e >> 2;
            int seg = (e & 3) * 8;
            int m   = bm + row;
            int b   = m / KBsz;
            ka[e2] = *(const uint4*)(Ag  + (size_t)m * TGK + kt * TBK + seg);
            ra[e2] = *(const uint4*)(rsv + (size_t)b * TGK + kt * TBK + seg);
        }
    };
    auto stsA = [&](int st){
        hf* As = Abase + st * A_ST;
        #pragma unroll
        for (int e2 = 0; e2 < 2; e2++) {
            int e   = tid * 2 + e2;
            int row = e >> 2;
            int seg = (e & 3) * 8;
            const __half2* kk = (const __half2*)&ka[e2];
            const __half2* rr2 = (const __half2*)&ra[e2];
            uint4 outv;
            __half2* po = (__half2*)&outv;
            #pragma unroll
            for (int q = 0; q < 4; q++) po[q] = __hmul2(kk[q], rr2[q]);
            *(uint4*)(As + row * ALD + seg) = outv;
        }
    };

    // ---- prologue ----
    if (MODE == 2) {
        ldgA(0);
        stsA(0);
        cpB(0, 0);
        ldgA(1);
    } else {
        cpA(0, 0);
        cpB(0, 0);
    }

    for (int k0 = 0; k0 < NKIT; k0++) {
        int st = k0 & 1;
        asm volatile("cp.async.wait_group 0;" ::: "memory");
        __syncthreads();
        if (MODE == 2) {
            if (k0 + 1 < NKIT) { stsA(st ^ 1); cpB(k0 + 1, st ^ 1); }
            if (k0 + 2 < NKIT) ldgA(k0 + 2);
        } else {
            if (k0 + 1 < NKIT) { cpA(k0 + 1, st ^ 1); cpB(k0 + 1, st ^ 1); }
        }

        const hf* Ash = Abase + st * A_ST;
        const hf* Bsh = Bbase + st * B_ST;

        #pragma unroll
        for (int ks = 0; ks < 2; ks++) {
            unsigned ah[4][4], bh[4][2];
            int rr = ks * 16 + lrow;
            int cbase = warp_n * 32 + lcol;
            #pragma unroll
            for (int mt = 0; mt < 4; mt++) {
                int row = warp_m * 64 + mt * 16 + lrow;
                ldm4(ah[mt], Ash + row * ALD + ks * 16 + lcol);
            }
            #pragma unroll
            for (int p = 0; p < 2; p++) {
                unsigned t[4];
                ldm4t(t, Bsh + rr * BLD + cbase + p * 16);
                bh[2*p][0] = t[0]; bh[2*p][1] = t[1];
                bh[2*p+1][0] = t[2]; bh[2*p+1][1] = t[3];
            }
            #pragma unroll
            for (int mt = 0; mt < 4; mt++)
                #pragma unroll
                for (int nt = 0; nt < 4; nt++)
                    mma_f16(acc[mt][nt], ah[mt], bh[nt]);
        }
    }
    __syncthreads();

    if (MODE == 3) {
        __shared__ float sred[128];
        if (tid < 128) sred[tid] = 0.f;
        __syncthreads();
        #pragma unroll
        for (int mt = 0; mt < 4; mt++) {
            int mloc = warp_m*64 + mt*16 + r;
            int m0 = bm + mloc;
            int b0 = m0 / KBsz;
            int b1 = (m0 + 8) / KBsz;
            float p0 = 0.f, p1 = 0.f;
            #pragma unroll
            for (int nt = 0; nt < 4; nt++) {
                int n0 = bn + warp_n*32 + nt*8 + 2*c;
                float v;
                v = eluf((acc[mt][nt][0] + bias[n0  ]) * colmul[(size_t)b0*cmStride + n0  ]); p0 += v*rvec[n0];
                v = eluf((acc[mt][nt][1] + bias[n0+1]) * colmul[(size_t)b0*cmStride + n0+1]); p0 += v*rvec[n0+1];
                v = eluf((acc[mt][nt][2] + bias[n0  ]) * colmul[(size_t)b1*cmStride + n0  ]); p1 += v*rvec[n0];
                v = eluf((acc[mt][nt][3] + bias[n0+1]) * colmul[(size_t)b1*cmStride + n0+1]); p1 += v*rvec[n0+1];
            }
            p0 += __shfl_xor_sync(0xffffffffu, p0, 1);
            p0 += __shfl_xor_sync(0xffffffffu, p0, 2);
            p1 += __shfl_xor_sync(0xffffffffu, p1, 1);
            p1 += __shfl_xor_sync(0xffffffffu, p1, 2);
            if (c == 0) { atomicAdd(&sred[mloc], p0); atomicAdd(&sred[mloc + 8], p1); }
        }
        __syncthreads();
        if (tid < 128)
            svec[(size_t)blockIdx.x * MKB + bm + tid] = sred[tid];
        return;
    }

    #pragma unroll
    for (int mt = 0; mt < 4; mt++) {
        int m0 = bm + warp_m*64 + mt*16 + r;
        #pragma unroll
        for (int nt = 0; nt < 4; nt++) {
            int n0 = bn + warp_n*32 + nt*8 + 2*c;
            #pragma unroll
            for (int half = 0; half < 2; half++) {
                int mm = m0 + half*8;
                float vx = acc[mt][nt][2*half], vy = acc[mt][nt][2*half+1];
                size_t gm = (size_t)mm*TGN + n0;
                if (MODE == 2) {
                    __half2 ad = *(const __half2*)(addmat + gm);
                    vx = eluf(vx + __half2float(__low2half(ad)));
                    vy = eluf(vy + __half2float(__high2half(ad)));
                } else { // MODE 4
                    vx += bias[n0]; vy += bias[n0+1];
                }
                *(__half2*)(C + gm) =
                    __halves2half2(__float2half_rn(vx), __float2half_rn(vy));
            }
        }
    }
}

// ---------------- split / helper kernels -------------------------------------
__global__ void cvt16_k(const float* __restrict__ src, hf* __restrict__ dst, size_t n)
{
    size_t i = ((size_t)blockIdx.x * blockDim.x + threadIdx.x) * 4;
    if (i >= n) return;
    float4 v = *(const float4*)(src + i);
    *(__half2*)(dst + i)     = __halves2half2(__float2half_rn(v.x), __float2half_rn(v.y));
    *(__half2*)(dst + i + 2) = __halves2half2(__float2half_rn(v.z), __float2half_rn(v.w));
}

// r[n] = vec[k] dot W[k][n] + b[n]
__global__ void vecmat_k(const float* __restrict__ vec,
                         const float* __restrict__ W,
                         const float* __restrict__ b,
                         float* __restrict__ r)
{
    int n = blockIdx.x * blockDim.x + threadIdx.x;
    if (n >= Dd) return;
    float a = b[n];
    for (int k = 0; k < Dd; k++) a += vec[k] * W[(size_t)k * Dd + n];
    r[n] = a;
}

__global__ void copyf_k(const float* __restrict__ src, float* __restrict__ dst, int n)
{
    int i = (blockIdx.x * blockDim.x + threadIdx.x) * 4;
    if (i < n) *(float4*)(dst + i) = *(const float4*)(src + i);
}

// =====================  small FFMA2 GEMM (64x128 tile)  ======================
__device__ __forceinline__ unsigned long long pack2(float lo, float hi) {
    unsigned long long r;
    asm("mov.b64 %0, {%1, %2};" : "=l"(r) : "f"(lo), "f"(hi));
    return r;
}
__device__ __forceinline__ void unpack2(unsigned long long v, float& lo, float& hi) {
    asm("mov.b64 {%0, %1}, %2;" : "=f"(lo), "=f"(hi) : "l"(v));
}
__device__ __forceinline__ void fma2(unsigned long long& d,
                                     unsigned long long a, unsigned long long b) {
    asm("fma.rn.f32x2 %0, %1, %2, %0;" : "+l"(d) : "l"(a), "l"(b));
}

#define SBM 64
#define SBN 128
#define BKK 16

template<int MODE>
__global__ __launch_bounds__(256)
void sgemm_k(const float* __restrict__ A, int lda,
             const float* __restrict__ A2, int lda2, int splitK,
             const float* __restrict__ W,
             const float* __restrict__ bias,
             float* __restrict__ C,
             int M, int K, int N,
             size_t strideA, size_t strideW, size_t strideBias, size_t strideC)
{
    A    += (size_t)blockIdx.z * strideA;
    A2   += (size_t)blockIdx.z * strideA;
    W    += (size_t)blockIdx.z * strideW;
    bias += (size_t)blockIdx.z * strideBias;
    C    += (size_t)blockIdx.z * strideC;

    __shared__ float As[BKK][SBM];
    __shared__ float Bs[BKK][SBN];

    const int bm = blockIdx.y * SBM;
    const int bn = blockIdx.x * SBN;
    const int tid = threadIdx.x;
    const int ty = tid >> 5;
    const int tx = tid & 31;

    unsigned long long acc2[8][2];
    #pragma unroll
    for (int i = 0; i < 8; i++) { acc2[i][0] = 0ull; acc2[i][1] = 0ull; }

    for (int k0 = 0; k0 < K; k0 += BKK) {
        {
            int e   = tid;
            int row = e >> 2;
            int kq  = (e & 3) * 4;
            int m   = bm + row;
            int k   = k0 + kq;
            const float* src = (k < splitK)
                ? (A  + (size_t)m * lda  + k)
                : (A2 + (size_t)m * lda2 + (k - splitK));
            float4 v = *(const float4*)src;
            As[kq + 0][row] = v.x; As[kq + 1][row] = v.y;
            As[kq + 2][row] = v.z; As[kq + 3][row] = v.w;
        }
        #pragma unroll
        for (int e2 = 0; e2 < 2; e2++) {
            int e   = tid * 2 + e2;
            int row = e >> 5;
            int cc  = (e & 31) * 4;
            float4 v = *(const float4*)(W + (size_t)(k0 + row) * N + bn + cc);
            *(float4*)&Bs[row][cc] = v;
        }
        __syncthreads();
        #pragma unroll
        for (int kk = 0; kk < BKK; kk++) {
            float a[8];
            unsigned long long b2[2];
            #pragma unroll
            for (int i = 0; i < 8; i++) a[i] = As[kk][ty * 8 + i];
            b2[0] = *(const unsigned long long*)&Bs[kk][tx * 4];
            b2[1] = *(const unsigned long long*)&Bs[kk][tx * 4 + 2];
            #pragma unroll
            for (int i = 0; i < 8; i++) {
                unsigned long long pa = pack2(a[i], a[i]);
                fma2(acc2[i][0], pa, b2[0]);
                fma2(acc2[i][1], pa, b2[1]);
            }
        }
        __syncthreads();
    }

    #pragma unroll
    for (int i = 0; i < 8; i++) {
        int m = bm + ty * 8 + i;
        int n = bn + tx * 4;
        float4 v;
        unpack2(acc2[i][0], v.x, v.y);
        unpack2(acc2[i][1], v.z, v.w);
        v.x += bias[n]; v.y += bias[n+1]; v.z += bias[n+2]; v.w += bias[n+3];
        if (MODE == 1) { v.x = tanhf(v.x); v.y = tanhf(v.y); v.z = tanhf(v.z); v.w = tanhf(v.w); }
        *(float4*)(C + (size_t)m * N + n) = v;
    }
}

// ---------------- attention / misc kernels (validated) -----------------------
__global__ void word_attn_k(const float* __restrict__ qall,
                            const float* __restrict__ qword,
                            const float* __restrict__ caw,
                            float* __restrict__ ch)
{
    int b = blockIdx.x, s = blockIdx.y;
    __shared__ float qs[Dd];
    __shared__ float lg[Ll];
    int tid = threadIdx.x;
    for (int d = tid; d < Dd; d += 256)
        qs[d] = qall[((size_t)s * Bsz + b) * Dd + d] * caw[d];
    __syncthreads();
    int wid = tid >> 5, lane = tid & 31;
    for (int l = wid; l < Ll; l += 8) {
        const float* qw = qword + ((size_t)b * Ll + l) * Dd;
        float a = 0.f;
        for (int d = lane; d < Dd; d += 32) a += qs[d] * qw[d];
        #pragma unroll
        for (int o = 16; o; o >>= 1) a += __shfl_xor_sync(0xffffffffu, a, o);
        if (lane == 0) lg[l] = a;
    }
    __syncthreads();
    if (tid == 0) {
        float mx = -INFINITY;
        for (int l = 0; l < Ll; l++) mx = fmaxf(mx, lg[l]);
        float sm = 0.f;
        for (int l = 0; l < Ll; l++) { float e = expf(lg[l] - mx); lg[l] = e; sm += e; }
        float inv = 1.f / sm;
        for (int l = 0; l < Ll; l++) lg[l] *= inv;
    }
    __syncthreads();
    for (int d = tid; d < Dd; d += 256) {
        float a = 0.f;
        for (int l = 0; l < Ll; l++) a += lg[l] * qword[((size_t)b * Ll + l) * Dd + d];
        ch[((size_t)b * Ss + s) * Dd + d] = a;
    }
}

__global__ void norm_k(const float* __restrict__ chkey, float* __restrict__ normed)
{
    int i = blockIdx.x * blockDim.x + threadIdx.x;
    if (i >= BD) return;
    int b = i >> 9, d = i & 511;
    size_t base = (size_t)b * Ss * Dd + d;
    float ss = 0.f;
    #pragma unroll
    for (int s = 0; s < Ss; s++) { float v = chkey[base + s * Dd]; ss += v * v; }
    float inv = 1.f / sqrtf(ss);
    #pragma unroll
    for (int s = 0; s < Ss; s++) normed[base + s * Dd] = chkey[base + s * Dd] * inv;
}

__global__ void gram_k(const float* __restrict__ normed, float* __restrict__ Amat)
{
    int tb = blockIdx.x, i = blockIdx.y;
    __shared__ float Ki[Dd];
    __shared__ float lg[TS];
    int tid = threadIdx.x;
    int ti = i / Ss, si = i % Ss;
    size_t rowi = ((size_t)(ti * TBsz + tb) * Ss + si) * Dd;
    for (int d = tid; d < Dd; d += 256) Ki[d] = normed[rowi + d];
    __syncthreads();
    int wid = tid >> 5, lane = tid & 31;
    for (int j = wid; j < TS; j += 8) {
        float a;
        if (j > i) a = -1e30f;
        else {
            int tj = j / Ss, sj = j % Ss;
            size_t rowj = ((size_t)(tj * TBsz + tb) * Ss + sj) * Dd;
            a = 0.f;
            for (int d = lane; d < Dd; d += 32) a += Ki[d] * normed[rowj + d];
            #pragma unroll
            for (int o = 16; o; o >>= 1) a += __shfl_xor_sync(0xffffffffu, a, o);
        }
        if (lane == 0) lg[j] = a;
    }
    __syncthreads();
    if (tid == 0) {
        float mx = -INFINITY;
        for (int j = 0; j < TS; j++) mx = fmaxf(mx, lg[j]);
        float sm = 0.f;
        for (int j = 0; j < TS; j++) { float e = expf(lg[j] - mx); lg[j] = e; sm += e; }
        float inv = 1.f / sm;
        for (int j = 0; j < TS; j++) lg[j] *= inv;
    }
    __syncthreads();
    if (tid < TS) Amat[((size_t)tb * TS + i) * TS + tid] = lg[tid];
}

__global__ void attv_k(const float* __restrict__ Amat,
                       const float* __restrict__ chval,
                       float* __restrict__ att)
{
    int tb = blockIdx.x, i = blockIdx.y;
    __shared__ float aw[TS];
    int tid = threadIdx.x;
    if (tid < TS) aw[tid] = Amat[((size_t)tb * TS + i) * TS + tid];
    __syncthreads();
    int ti = i / Ss, si = i % Ss;
    for (int d = tid; d < Dd; d += 256) {
        float a = 0.f;
        for (int j = 0; j <= i; j++) {
            int tj = j / Ss, sj = j % Ss;
            a += aw[j] * chval[((size_t)(tj * TBsz + tb) * Ss + sj) * Dd + d];
        }
        att[((size_t)(ti * TBsz + tb) * Ss + si) * Dd + d] = a;
    }
}

__global__ void bcast_k(const float* __restrict__ src, float* __restrict__ dst)
{
    int i = blockIdx.x * blockDim.x + threadIdx.x;
    if (i < BD) dst[i] = src[i & 511];
}

// softmax over KB (summing 4 N-slice partials, parallel reductions)
// + vectorized weighted read of knowledge
__global__ void read_k(const float* __restrict__ s4,
                       const float* __restrict__ knowledge,
                       float* __restrict__ readv)
{
    int b = blockIdx.x;
    int tid = threadIdx.x;              // 256
    int wid = tid >> 5, lane = tid & 31;
    __shared__ float sv[KBsz];
    __shared__ float wred[8];

    float x = -1e30f;
    if (tid < KBsz) {
        size_t base = (size_t)b * KBsz + tid;
        x = s4[base] + s4[(size_t)MKB + base]
          + s4[2*(size_t)MKB + base] + s4[3*(size_t)MKB + base];
    }
    float m = x;
    #pragma unroll
    for (int o = 16; o; o >>= 1) m = fmaxf(m, __shfl_xor_sync(0xffffffffu, m, o));
    if (lane == 0) wred[wid] = m;
    __syncthreads();
    if (tid == 0) {
        float mm = wred[0];
        #pragma unroll
        for (int w = 1; w < 8; w++) mm = fmaxf(mm, wred[w]);
        wred[0] = mm;
    }
    __syncthreads();
    float mx = wred[0];
    float e = (tid < KBsz) ? expf(x - mx) : 0.f;
    float s = e;
    #pragma unroll
    for (int o = 16; o; o >>= 1) s += __shfl_xor_sync(0xffffffffu, s, o);
    __syncthreads();
    if (lane == 0) wred[wid] = s;
    __syncthreads();
    if (tid == 0) {
        float ss = 0.f;
        #pragma unroll
        for (int w = 0; w < 8; w++) ss += wred[w];
        wred[0] = 1.f / ss;
    }
    __syncthreads();
    if (tid < KBsz) sv[tid] = e * wred[0];
    __syncthreads();

    if (tid < 128) {
        const float4* kn = (const float4*)(knowledge + (size_t)b * KBsz * Dd);
        float4 acc = make_float4(0.f, 0.f, 0.f, 0.f);
        int k = 0;
        #pragma unroll 4
        for (; k + 4 <= KBsz; k += 4) {
            #pragma unroll
            for (int u = 0; u < 4; u++) {
                float w = sv[k + u];
                float4 t = kn[(size_t)(k + u) * 128 + tid];
                acc.x += w * t.x; acc.y += w * t.y;
                acc.z += w * t.z; acc.w += w * t.w;
            }
        }
        for (; k < KBsz; k++) {
            float w = sv[k];
            float4 t = kn[(size_t)k * 128 + tid];
            acc.x += w * t.x; acc.y += w * t.y;
            acc.z += w * t.z; acc.w += w * t.w;
        }
        ((float4*)(readv + (size_t)b * Dd))[tid] = acc;
    }
}

__global__ void out_k(const float* __restrict__ mem,
                      const float* __restrict__ att,
                      float* __restrict__ out, int out_size)
{
    int i = blockIdx.x * blockDim.x + threadIdx.x;
    if (i >= BD) return;
    if (i < out_size) out[i] = mem[i];
    if (out_size >= 2 * BD) {
        int b = i >> 9, d = i & 511;
        out[BD + i] = att[((size_t)b * Ss + (Ss - 1)) * Dd + d];
    }
}

// ---------------- launch -----------------------------------------------------
static float* symf(const void* s) { void* p = nullptr; cudaGetSymbolAddress(&p, s); return (float*)p; }
static hf*    symh(const void* s) { void* p = nullptr; cudaGetSymbolAddress(&p, s); return (hf*)p; }

#define TG_SMEM (int)((NSTG*A_ST + NSTG*B_ST) * sizeof(hf))

extern "C" void kernel_launch(void* const* d_in, const int* in_sizes, int n_in,
                              void* d_out, int out_size)
{
    const float* qword     = (const float*)d_in[0];
    const float* qemb      = (const float*)d_in[1];
    const float* knowledge = (const float*)d_in[2];
    const float* ci_w     = (const float*)d_in[4];
    const float* ci_b     = (const float*)d_in[5];
    const float* ciu_w    = (const float*)d_in[6];
    const float* ciu_b    = (const float*)d_in[7];
    const float* ca_w     = (const float*)d_in[8];
    const float* kproj_w  = (const float*)d_in[10];
    const float* kproj_b  = (const float*)d_in[11];
    const float* mproj_w  = (const float*)d_in[12];
    const float* mproj_b  = (const float*)d_in[13];
    const float* concat_w = (const float*)d_in[14];
    const float* concat_b = (const float*)d_in[15];
    const float* concat2_w= (const float*)d_in[16];
    const float* concat2_b= (const float*)d_in[17];
    const float* rattn_w  = (const float*)d_in[18];
    const float* write_w  = (const float*)d_in[20];
    const float* write_b  = (const float*)d_in[21];
    const float* init_mem = (const float*)d_in[22];
    const float* kq_w     = (const float*)d_in[23];
    const float* kq_b     = (const float*)d_in[24];
    const float* val_w    = (const float*)d_in[25];
    const float* val_b    = (const float*)d_in[26];
    float* out = (float*)d_out;

    float* q0     = symf(g_q0);
    float* qall   = symf(g_qall);
    float* ch     = symf(g_ch);
    float* chkv   = symf(g_chkv);
    float* chkey  = chkv;
    float* chval  = chkv + (size_t)Bsz * Ss * Dd;
    float* normed = symf(g_normed);
    float* Amat   = symf(g_Amat);
    float* att    = symf(g_att);
    hf*    kp     = symh(g_kp);
    hf*    kp2    = symh(g_kp2);
    hf*    e1     = symh(g_e1);
    hf*    kn     = symh(g_kn);
    hf*    wb     = symh(g_wb);
    hf*    mp16   = symh(g_mp16);
    float* s4     = symf(g_s4);
    float* readv  = symf(g_read);
    float* Wcat   = symf(g_Wcat);
    float* biascat= symf(g_biascat);
    float* Wkv    = symf(g_Wkv);
    float* bkv    = symf(g_bkv);
    float* zerov  = symf(g_zero);
    float* tmp512 = symf(g_tmp512);
    float* zbuf   = symf(g_zbuf);

    static bool init_done = false;
    static cudaStream_t s2 = nullptr;
    static cudaEvent_t evFork = nullptr, evJoin = nullptr;
    if (!init_done) {
        cudaFuncSetAttribute(tgemm_k<2>, cudaFuncAttributeMaxDynamicSharedMemorySize, TG_SMEM);
        cudaFuncSetAttribute(tgemm_k<3>, cudaFuncAttributeMaxDynamicSharedMemorySize, TG_SMEM);
        cudaFuncSetAttribute(tgemm_k<4>, cudaFuncAttributeMaxDynamicSharedMemorySize, TG_SMEM);
        cudaStreamCreateWithFlags(&s2, cudaStreamNonBlocking);
        cudaEventCreateWithFlags(&evFork, cudaEventDisableTiming);
        cudaEventCreateWithFlags(&evJoin, cudaEventDisableTiming);
        init_done = true;
    }

    auto Gs = [](int M, int N, int Z) { return dim3(N / SBN, M / SBM, Z); };
    const dim3 GT(Dd / 128, MKB / 128);
    const float* NPF = nullptr;
    hf* NPH = nullptr;

    // kv weight/bias packing on default stream (needed by the batched kv GEMM)
    copyf_k<<<(Dd*Dd / 4 + 255) / 256, 256>>>(kq_w,  Wkv, Dd*Dd);
    copyf_k<<<(Dd*Dd / 4 + 255) / 256, 256>>>(val_w, Wkv + (size_t)Dd*Dd, Dd*Dd);
    copyf_k<<<(Dd / 4 + 255) / 256, 256>>>(kq_b,  bkv, Dd);
    copyf_k<<<(Dd / 4 + 255) / 256, 256>>>(val_b, bkv + Dd, Dd);

    // ---- fork ----
    cudaEventRecord(evFork, 0);
    cudaStreamWaitEvent(s2, evFork, 0);

    {   // stream s2: conversions + kp + kp2 + write/mproj fusion prep + init state
        size_t nk = (size_t)MKB * Dd;
        cvt16_k<<<(unsigned)((nk / 4 + 255) / 256), 256, 0, s2>>>(knowledge, kn, nk);
        size_t nw = (size_t)Dd * Dd;
        cvt16_k<<<(unsigned)((nw / 4 + 255) / 256), 256, 0, s2>>>(kproj_w,  wb + 0*Dd*Dd, nw);
        cvt16_k<<<(unsigned)((2*nw / 4 + 255) / 256), 256, 0, s2>>>(concat_w, wb + 1*Dd*Dd, 2*nw);
        cvt16_k<<<(unsigned)((nw / 4 + 255) / 256), 256, 0, s2>>>(concat2_w, wb + 3*Dd*Dd, nw);
        // kp / kp2 (fp16 outputs)
        tgemm_k<4><<<GT, 256, TG_SMEM, s2>>>(kn, wb + 0*Dd*Dd,
                                             kproj_b, kp, NPH, NPH, NPF, 0, NPF, nullptr);
        tgemm_k<4><<<GT, 256, TG_SMEM, s2>>>(kp, wb + 2*Dd*Dd,
                                             concat_b, kp2, NPH, NPH, NPF, 0, NPF, nullptr);
        // W2 = write_w @ mproj_w into Wcat[1]; Wcat[0] = write_w
        sgemm_k<0><<<Gs(2*Dd, Dd, 1), 256, 0, s2>>>(write_w, Dd, write_w, Dd, Dd,
                                                    mproj_w, zerov, Wcat + (size_t)2*Dd*Dd,
                                                    2*Dd, Dd, Dd, 0, 0, 0, 0);
        copyf_k<<<(2*Dd*Dd / 4 + 255) / 256, 256, 0, s2>>>(write_w, Wcat, 2*Dd*Dd);
        copyf_k<<<(Dd / 4 + 255) / 256, 256, 0, s2>>>(write_b, biascat, Dd);
        vecmat_k<<<2, 256, 0, s2>>>(write_b, mproj_w, mproj_b, biascat + Dd);   // bias2
        bcast_k<<<(BD + 255) / 256, 256, 0, s2>>>(init_mem, zbuf);              // memory0
        vecmat_k<<<2, 256, 0, s2>>>(init_mem, mproj_w, mproj_b, tmp512);        // mp0 row
        bcast_k<<<(BD + 255) / 256, 256, 0, s2>>>(tmp512, zbuf + BD);           // mp0
    }
    cudaEventRecord(evJoin, s2);

    // default stream: question path
    sgemm_k<1><<<Gs(Bsz, Dd, 1), 256>>>(qemb, Dd, qemb, Dd, Dd, ci_w, ci_b, q0,
                                        Bsz, Dd, Dd, 0, 0, 0, 0);
    sgemm_k<0><<<Gs(Bsz, Dd, Ss), 256>>>(q0, Dd, q0, Dd, Dd, ciu_w, ciu_b, qall,
                                         Bsz, Dd, Dd,
                                         0, (size_t)Dd * Dd, Dd, (size_t)BD);
    word_attn_k<<<dim3(Bsz, Ss), 256>>>(qall, qword, ca_w, ch);
    // chkey + chval in one z=2 batched launch
    sgemm_k<0><<<Gs(Bsz * Ss, Dd, 2), 256>>>(ch, Dd, ch, Dd, Dd, Wkv, bkv, chkv,
                                             Bsz * Ss, Dd, Dd,
                                             0, (size_t)Dd*Dd, Dd, (size_t)Bsz*Ss*Dd);
    norm_k<<<(BD + 255) / 256, 256>>>(chkey, normed);
    gram_k<<<dim3(TBsz, TS), 256>>>(normed, Amat);
    attv_k<<<dim3(TBsz, TS), 256>>>(Amat, chval, att);

    cudaStreamWaitEvent(0, evJoin, 0);

    int p = 0;
    for (int i = 0; i < Ss; i++) {
        float* mcur = zbuf + (size_t)p * 2 * BD;
        float* mpcur = mcur + BD;
        // mp -> fp16 (tiny)
        cvt16_k<<<(BD / 4 + 255) / 256, 256>>>(mpcur, mp16, BD);
        // e1 = elu((kp * mp) @ W1 + kp2), scale fused into A load
        tgemm_k<2><<<GT, 256, TG_SMEM>>>(kp, wb + 1*Dd*Dd,
                                         NPF, e1, kp2, mp16, NPF, 0, NPF, nullptr);
        tgemm_k<3><<<GT, 256, TG_SMEM>>>(e1, wb + 3*Dd*Dd,
                                         concat2_b, NPH, NPH, NPH,
                                         att + (size_t)i * Dd, Ss * Dd, rattn_w, s4);
        read_k<<<Bsz, 256>>>(s4, knowledge, readv);
        sgemm_k<0><<<Gs(Bsz, Dd, 2), 256>>>(mcur, Dd, readv, Dd, Dd,
                                            Wcat, biascat,
                                            zbuf + (size_t)(p ^ 1) * 2 * BD,
                                            Bsz, 2 * Dd, Dd,
                                            0, (size_t)2*Dd*Dd, Dd, (size_t)BD);
        p ^= 1;
    }

    out_k<<<(BD + 255) / 256, 256>>>(zbuf + (size_t)p * 2 * BD, att, out, out_size);
}